// round 1
// baseline (speedup 1.0000x reference)
#include <cuda_runtime.h>
#include <math.h>

#define NN 512
#define CZ 128
#define NROW (NN*NN)          // 262144 rows of shape (CZ,)

// ---------------- scratch (static device globals; no runtime allocation) ----
__device__ float g_left [(size_t)NROW*CZ];   // left_proj  (i,k,c) 128MB
__device__ float g_right[(size_t)NROW*CZ];   // right_proj (j,k,c) 128MB
__device__ float g_glsig[(size_t)NROW*CZ];   // sigmoid(left@gl_w.T+gl_b)  128MB
__device__ float g_projT[128*256];           // [kk][c]
__device__ float g_gateT[128*256];           // [kk][c]
__device__ float g_glT  [128*128];           // [kk][c]
__device__ float g_outpT[128*128];           // [kk][c]

// ---------------- K0: transpose weights so GEMM B-loads are coalesced ------
__global__ void k_transpose(const float* __restrict__ pw, const float* __restrict__ gw,
                            const float* __restrict__ glw, const float* __restrict__ ow)
{
    int idx = blockIdx.x*256 + threadIdx.x;          // 192*256 = 49152 exactly
    if (idx < 256*128) {
        int c = idx >> 7, kk = idx & 127;            // pw/gw are [256][128]
        g_projT[kk*256 + c] = pw[idx];
        g_gateT[kk*256 + c] = gw[idx];
    } else {
        int j = idx - 256*128;                        // glw/ow are [128][128]
        int c = j >> 7, kk = j & 127;
        g_glT  [kk*128 + c] = glw[j];
        g_outpT[kk*128 + c] = ow[j];
    }
}

// ---------------- shared helpers -------------------------------------------
// LayerNorm 64 rows of src into transposed smem sLT[kk][r], stride 65.
__device__ __forceinline__ void ln_to_smem(const float* __restrict__ src,
                                           const float* __restrict__ w,
                                           const float* __restrict__ b,
                                           int r0, int tid, float* sLT)
{
    int wp = tid >> 5, lane = tid & 31;
#pragma unroll
    for (int q = 0; q < 8; q++) {
        int rr = wp*8 + q;
        const float4 x = *(const float4*)(src + (size_t)(r0+rr)*CZ + lane*4);
        float s  = x.x+x.y+x.z+x.w;
        float sq = x.x*x.x + x.y*x.y + x.z*x.z + x.w*x.w;
#pragma unroll
        for (int o = 16; o > 0; o >>= 1) {
            s  += __shfl_xor_sync(0xffffffffu, s,  o);
            sq += __shfl_xor_sync(0xffffffffu, sq, o);
        }
        float m  = s  * (1.f/CZ);
        float v  = sq * (1.f/CZ) - m*m;
        float rs = rsqrtf(v + 1e-5f);
        float4 wv = *(const float4*)(w + lane*4);
        float4 bv = *(const float4*)(b + lane*4);
        sLT[(lane*4+0)*65 + rr] = (x.x-m)*rs*wv.x + bv.x;
        sLT[(lane*4+1)*65 + rr] = (x.y-m)*rs*wv.y + bv.y;
        sLT[(lane*4+2)*65 + rr] = (x.z-m)*rs*wv.z + bv.z;
        sLT[(lane*4+3)*65 + rr] = (x.w-m)*rs*wv.w + bv.w;
    }
}

// load 128x64 weight tile (columns c0..c0+63 of WT[128][ntot]) into sW (stride 68)
__device__ __forceinline__ void load_w(const float* __restrict__ WT, int ntot, int c0,
                                       float* sW, int tid)
{
#pragma unroll 8
    for (int t = tid; t < 128*64; t += 256) {
        int kk = t >> 6, c = t & 63;
        sW[kk*68 + c] = WT[kk*ntot + c0 + c];
    }
}

// 64x64 tile GEMM over K=128: acc[4][4] per thread, thread grid 16x16
__device__ __forceinline__ void gemm64(const float* __restrict__ sLT,
                                       const float* __restrict__ sW,
                                       int tx, int ty, float acc[4][4])
{
#pragma unroll 4
    for (int kk = 0; kk < 128; kk++) {
        float a0 = sLT[kk*65 + ty*4 + 0];
        float a1 = sLT[kk*65 + ty*4 + 1];
        float a2 = sLT[kk*65 + ty*4 + 2];
        float a3 = sLT[kk*65 + ty*4 + 3];
        float4 bb = *(const float4*)(sW + kk*68 + tx*4);
        acc[0][0] += a0*bb.x; acc[0][1] += a0*bb.y; acc[0][2] += a0*bb.z; acc[0][3] += a0*bb.w;
        acc[1][0] += a1*bb.x; acc[1][1] += a1*bb.y; acc[1][2] += a1*bb.z; acc[1][3] += a1*bb.w;
        acc[2][0] += a2*bb.x; acc[2][1] += a2*bb.y; acc[2][2] += a2*bb.z; acc[2][3] += a2*bb.w;
        acc[3][0] += a3*bb.x; acc[3][1] += a3*bb.y; acc[3][2] += a3*bb.z; acc[3][3] += a3*bb.w;
    }
}

__device__ __forceinline__ float sigf(float x) { return 1.f/(1.f + expf(-x)); }

// ---------------- K1: LN + proj*sigmoid(gate)*mask  + gl sigmoid ------------
__global__ __launch_bounds__(256) void k1(const float* __restrict__ act,
                                          const float* __restrict__ mask,
                                          const float* __restrict__ lnw,
                                          const float* __restrict__ lnb,
                                          const float* __restrict__ pb,
                                          const float* __restrict__ gb,
                                          const float* __restrict__ glb)
{
    extern __shared__ float sh[];
    float* sLT = sh;            // [128][65]
    float* sW  = sh + 128*65;   // [128][68]
    int tid = threadIdx.x;
    int r0  = blockIdx.x * 64;

    ln_to_smem(act, lnw, lnb, r0, tid, sLT);
    __syncthreads();

    int tx = tid & 15, ty = tid >> 4;

    // fused proj/gate: for each 64-channel chunk compute gate first (sigmoid in
    // registers — same thread owns the matching proj cell), then proj.
    for (int c0 = 0; c0 < 256; c0 += 64) {
        load_w(g_gateT, 256, c0, sW, tid);
        __syncthreads();
        float acc[4][4] = {};
        gemm64(sLT, sW, tx, ty, acc);
        float4 gbv = *(const float4*)(gb + c0 + tx*4);
        float sigv[4][4];
#pragma unroll
        for (int ii = 0; ii < 4; ii++) {
            sigv[ii][0] = sigf(acc[ii][0] + gbv.x);
            sigv[ii][1] = sigf(acc[ii][1] + gbv.y);
            sigv[ii][2] = sigf(acc[ii][2] + gbv.z);
            sigv[ii][3] = sigf(acc[ii][3] + gbv.w);
        }
        __syncthreads();                        // everyone done reading sW
        load_w(g_projT, 256, c0, sW, tid);
        __syncthreads();
        float acc2[4][4] = {};
        gemm64(sLT, sW, tx, ty, acc2);
        float4 pbv = *(const float4*)(pb + c0 + tx*4);
        float* dstBase = (c0 < 128) ? (g_left + c0) : (g_right + (c0 - 128));
#pragma unroll
        for (int ii = 0; ii < 4; ii++) {
            int r = r0 + ty*4 + ii;
            float mk = mask[r];
            float4 v;
            v.x = mk * (acc2[ii][0] + pbv.x) * sigv[ii][0];
            v.y = mk * (acc2[ii][1] + pbv.y) * sigv[ii][1];
            v.z = mk * (acc2[ii][2] + pbv.z) * sigv[ii][2];
            v.w = mk * (acc2[ii][3] + pbv.w) * sigv[ii][3];
            *(float4*)(dstBase + (size_t)r*128 + tx*4) = v;
        }
        __syncthreads();                        // before next chunk reloads sW
    }

    // gl gate: sigmoid(left @ gl_w.T + gl_b)
    for (int c0 = 0; c0 < 128; c0 += 64) {
        load_w(g_glT, 128, c0, sW, tid);
        __syncthreads();
        float acc[4][4] = {};
        gemm64(sLT, sW, tx, ty, acc);
        float4 bv = *(const float4*)(glb + c0 + tx*4);
#pragma unroll
        for (int ii = 0; ii < 4; ii++) {
            int r = r0 + ty*4 + ii;
            float4 v;
            v.x = sigf(acc[ii][0] + bv.x);
            v.y = sigf(acc[ii][1] + bv.y);
            v.z = sigf(acc[ii][2] + bv.z);
            v.w = sigf(acc[ii][3] + bv.w);
            *(float4*)(g_glsig + (size_t)r*128 + c0 + tx*4) = v;
        }
        __syncthreads();
    }
}

// ---------------- K2: einsum out[i,j,c] = sum_k L[i,k,c]*R[j,k,c] -----------
// Thread = channel c (x), y in [0,4) splits the 16 i-rows. 64 acc/thread.
// All global loads are 128B-coalesced across c. 8x8 tile-group swizzle for L2.
__global__ __launch_bounds__(512) void k2(float* __restrict__ out)
{
    int c = threadIdx.x;        // 0..127
    int y = threadIdx.y;        // 0..3
    int bid = blockIdx.x;       // 0..1023 over 32x32 tiles of 16x16
    int g = bid >> 6, w = bid & 63;
    int ti = (g >> 2)*8 + (w >> 3);
    int tj = (g &  3)*8 + (w &  7);
    int i0 = ti*16 + y*4;
    int j0 = tj*16;

    const float* __restrict__ Lp = g_left  + (size_t)i0*NN*CZ + c;
    const float* __restrict__ Rp = g_right + (size_t)j0*NN*CZ + c;

    float acc[4][16];
#pragma unroll
    for (int ii = 0; ii < 4; ii++)
#pragma unroll
        for (int jj = 0; jj < 16; jj++) acc[ii][jj] = 0.f;

#pragma unroll 2
    for (int k = 0; k < NN; k++) {
        float a[4];
#pragma unroll
        for (int ii = 0; ii < 4; ii++)
            a[ii] = __ldg(Lp + ((size_t)ii*NN + k)*CZ);
        float b[16];
#pragma unroll
        for (int jj = 0; jj < 16; jj++)
            b[jj] = __ldg(Rp + ((size_t)jj*NN + k)*CZ);
#pragma unroll
        for (int ii = 0; ii < 4; ii++)
#pragma unroll
            for (int jj = 0; jj < 16; jj++)
                acc[ii][jj] = fmaf(a[ii], b[jj], acc[ii][jj]);
    }

#pragma unroll
    for (int ii = 0; ii < 4; ii++)
#pragma unroll
        for (int jj = 0; jj < 16; jj++)
            out[((size_t)(i0+ii)*NN + (j0+jj))*CZ + c] = acc[ii][jj];
}

// ---------------- K3: LN(out) -> @outp_w.T + outp_b, * glsig (in place) -----
__global__ __launch_bounds__(256) void k3(float* __restrict__ out,
                                          const float* __restrict__ cnw,
                                          const float* __restrict__ cnb,
                                          const float* __restrict__ ob)
{
    extern __shared__ float sh[];
    float* sLT = sh;            // [128][65]
    float* sW  = sh + 128*65;   // [128][68]
    int tid = threadIdx.x;
    int r0  = blockIdx.x * 64;

    ln_to_smem(out, cnw, cnb, r0, tid, sLT);   // stage all reads before writes
    __syncthreads();

    int tx = tid & 15, ty = tid >> 4;
    for (int c0 = 0; c0 < 128; c0 += 64) {
        load_w(g_outpT, 128, c0, sW, tid);
        __syncthreads();
        float acc[4][4] = {};
        gemm64(sLT, sW, tx, ty, acc);
        float4 obv = *(const float4*)(ob + c0 + tx*4);
#pragma unroll
        for (int ii = 0; ii < 4; ii++) {
            int r = r0 + ty*4 + ii;
            float4 gl = *(const float4*)(g_glsig + (size_t)r*128 + c0 + tx*4);
            float4 v;
            v.x = (acc[ii][0] + obv.x) * gl.x;
            v.y = (acc[ii][1] + obv.y) * gl.y;
            v.z = (acc[ii][2] + obv.z) * gl.z;
            v.w = (acc[ii][3] + obv.w) * gl.w;
            *(float4*)(out + (size_t)r*128 + c0 + tx*4) = v;
        }
        __syncthreads();
    }
}

// ---------------- launch ----------------------------------------------------
extern "C" void kernel_launch(void* const* d_in, const int* in_sizes, int n_in,
                              void* d_out, int out_size)
{
    const float* act = (const float*)d_in[0];
    const float* mask= (const float*)d_in[1];
    const float* lnw = (const float*)d_in[2];
    const float* lnb = (const float*)d_in[3];
    const float* pw  = (const float*)d_in[4];
    const float* pb  = (const float*)d_in[5];
    const float* gw  = (const float*)d_in[6];
    const float* gb  = (const float*)d_in[7];
    const float* cnw = (const float*)d_in[8];
    const float* cnb = (const float*)d_in[9];
    const float* ow  = (const float*)d_in[10];
    const float* ob  = (const float*)d_in[11];
    const float* glw = (const float*)d_in[12];
    const float* glb = (const float*)d_in[13];
    float* out = (float*)d_out;

    const int SMEM = (128*65 + 128*68) * 4;   // 68,096 B dynamic smem
    cudaFuncSetAttribute(k1, cudaFuncAttributeMaxDynamicSharedMemorySize, SMEM);
    cudaFuncSetAttribute(k3, cudaFuncAttributeMaxDynamicSharedMemorySize, SMEM);

    k_transpose<<<192, 256>>>(pw, gw, glw, ow);
    k1<<<NROW/64, 256, SMEM>>>(act, mask, lnw, lnb, pb, gb, glb);
    k2<<<1024, dim3(128, 4)>>>(out);
    k3<<<NROW/64, 256, SMEM>>>(out, cnw, cnb, ob);
}

// round 3
// speedup vs baseline: 2.1775x; 2.1775x over previous
#include <cuda_runtime.h>
#include <cuda_bf16.h>
#include <math.h>
#include <stdint.h>

#define NN 512
#define CZ 128
#define NROW (NN*NN)          // 262144 rows of shape (CZ,)

// ---------------- scratch (static device globals; no runtime allocation) ----
__device__ float g_left  [(size_t)NROW*CZ];   // left_proj  (i,k,c) row-major fp32
__device__ float g_right [(size_t)NROW*CZ];   // right_proj (j,k,c) row-major fp32
__device__ float g_glsig [(size_t)NROW*CZ];   // sigmoid(left@gl_w.T+gl_b)
__device__ __nv_bfloat16 g_LThi[(size_t)CZ*NROW];  // [c][i*512+k] bf16 hi
__device__ __nv_bfloat16 g_LTlo[(size_t)CZ*NROW];  // [c][i*512+k] bf16 lo
__device__ __nv_bfloat16 g_RThi[(size_t)CZ*NROW];  // [c][j*512+k]
__device__ __nv_bfloat16 g_RTlo[(size_t)CZ*NROW];
__device__ float g_einT  [(size_t)CZ*NROW];   // [c][i*512+j] fp32
__device__ float g_projT[128*256];            // [kk][c]
__device__ float g_gateT[128*256];
__device__ float g_glT  [128*128];
__device__ float g_outpT[128*128];

// ======================= PTX helpers (sm_103-safe; NO tcgen05) ==============
__device__ __forceinline__ uint32_t smem_u32(const void* p) {
    uint32_t a;
    asm("{ .reg .u64 t; cvta.to.shared.u64 t, %1; cvt.u32.u64 %0, t; }" : "=r"(a) : "l"(p));
    return a;
}
__device__ __forceinline__ void ldsm4(uint32_t r[4], uint32_t addr) {
    asm volatile("ldmatrix.sync.aligned.m8n8.x4.shared.b16 {%0,%1,%2,%3}, [%4];"
        : "=r"(r[0]), "=r"(r[1]), "=r"(r[2]), "=r"(r[3]) : "r"(addr));
}
__device__ __forceinline__ void mma16816(float c[4], const uint32_t a[4],
                                         uint32_t b0, uint32_t b1) {
    asm volatile("mma.sync.aligned.m16n8k16.row.col.f32.bf16.bf16.f32 "
        "{%0,%1,%2,%3}, {%4,%5,%6,%7}, {%8,%9}, {%0,%1,%2,%3};"
        : "+f"(c[0]), "+f"(c[1]), "+f"(c[2]), "+f"(c[3])
        : "r"(a[0]), "r"(a[1]), "r"(a[2]), "r"(a[3]), "r"(b0), "r"(b1));
}

// ---------------- K0: transpose weights so GEMM B-loads are coalesced ------
__global__ void k_transpose(const float* __restrict__ pw, const float* __restrict__ gw,
                            const float* __restrict__ glw, const float* __restrict__ ow)
{
    int idx = blockIdx.x*256 + threadIdx.x;          // 192*256 = 49152 exactly
    if (idx < 256*128) {
        int c = idx >> 7, kk = idx & 127;            // pw/gw are [256][128]
        g_projT[kk*256 + c] = pw[idx];
        g_gateT[kk*256 + c] = gw[idx];
    } else {
        int j = idx - 256*128;                        // glw/ow are [128][128]
        int c = j >> 7, kk = j & 127;
        g_glT  [kk*128 + c] = glw[j];
        g_outpT[kk*128 + c] = ow[j];
    }
}

// ---------------- shared helpers (k1/k3, unchanged from R1) -----------------
__device__ __forceinline__ void ln_to_smem(const float* __restrict__ src,
                                           const float* __restrict__ w,
                                           const float* __restrict__ b,
                                           int r0, int tid, float* sLT)
{
    int wp = tid >> 5, lane = tid & 31;
#pragma unroll
    for (int q = 0; q < 8; q++) {
        int rr = wp*8 + q;
        const float4 x = *(const float4*)(src + (size_t)(r0+rr)*CZ + lane*4);
        float s  = x.x+x.y+x.z+x.w;
        float sq = x.x*x.x + x.y*x.y + x.z*x.z + x.w*x.w;
#pragma unroll
        for (int o = 16; o > 0; o >>= 1) {
            s  += __shfl_xor_sync(0xffffffffu, s,  o);
            sq += __shfl_xor_sync(0xffffffffu, sq, o);
        }
        float m  = s  * (1.f/CZ);
        float v  = sq * (1.f/CZ) - m*m;
        float rs = rsqrtf(v + 1e-5f);
        float4 wv = *(const float4*)(w + lane*4);
        float4 bv = *(const float4*)(b + lane*4);
        sLT[(lane*4+0)*65 + rr] = (x.x-m)*rs*wv.x + bv.x;
        sLT[(lane*4+1)*65 + rr] = (x.y-m)*rs*wv.y + bv.y;
        sLT[(lane*4+2)*65 + rr] = (x.z-m)*rs*wv.z + bv.z;
        sLT[(lane*4+3)*65 + rr] = (x.w-m)*rs*wv.w + bv.w;
    }
}

__device__ __forceinline__ void load_w(const float* __restrict__ WT, int ntot, int c0,
                                       float* sW, int tid)
{
#pragma unroll 8
    for (int t = tid; t < 128*64; t += 256) {
        int kk = t >> 6, c = t & 63;
        sW[kk*68 + c] = WT[kk*ntot + c0 + c];
    }
}

__device__ __forceinline__ void gemm64(const float* __restrict__ sLT,
                                       const float* __restrict__ sW,
                                       int tx, int ty, float acc[4][4])
{
#pragma unroll 4
    for (int kk = 0; kk < 128; kk++) {
        float a0 = sLT[kk*65 + ty*4 + 0];
        float a1 = sLT[kk*65 + ty*4 + 1];
        float a2 = sLT[kk*65 + ty*4 + 2];
        float a3 = sLT[kk*65 + ty*4 + 3];
        float4 bb = *(const float4*)(sW + kk*68 + tx*4);
        acc[0][0] += a0*bb.x; acc[0][1] += a0*bb.y; acc[0][2] += a0*bb.z; acc[0][3] += a0*bb.w;
        acc[1][0] += a1*bb.x; acc[1][1] += a1*bb.y; acc[1][2] += a1*bb.z; acc[1][3] += a1*bb.w;
        acc[2][0] += a2*bb.x; acc[2][1] += a2*bb.y; acc[2][2] += a2*bb.z; acc[2][3] += a2*bb.w;
        acc[3][0] += a3*bb.x; acc[3][1] += a3*bb.y; acc[3][2] += a3*bb.z; acc[3][3] += a3*bb.w;
    }
}

__device__ __forceinline__ float sigf(float x) { return 1.f/(1.f + expf(-x)); }

// ---------------- K1: LN + proj*sigmoid(gate)*mask  + gl sigmoid ------------
__global__ __launch_bounds__(256) void k1(const float* __restrict__ act,
                                          const float* __restrict__ mask,
                                          const float* __restrict__ lnw,
                                          const float* __restrict__ lnb,
                                          const float* __restrict__ pb,
                                          const float* __restrict__ gb,
                                          const float* __restrict__ glb)
{
    extern __shared__ float sh[];
    float* sLT = sh;            // [128][65]
    float* sW  = sh + 128*65;   // [128][68]
    int tid = threadIdx.x;
    int r0  = blockIdx.x * 64;

    ln_to_smem(act, lnw, lnb, r0, tid, sLT);
    __syncthreads();

    int tx = tid & 15, ty = tid >> 4;

    for (int c0 = 0; c0 < 256; c0 += 64) {
        load_w(g_gateT, 256, c0, sW, tid);
        __syncthreads();
        float acc[4][4] = {};
        gemm64(sLT, sW, tx, ty, acc);
        float4 gbv = *(const float4*)(gb + c0 + tx*4);
        float sigv[4][4];
#pragma unroll
        for (int ii = 0; ii < 4; ii++) {
            sigv[ii][0] = sigf(acc[ii][0] + gbv.x);
            sigv[ii][1] = sigf(acc[ii][1] + gbv.y);
            sigv[ii][2] = sigf(acc[ii][2] + gbv.z);
            sigv[ii][3] = sigf(acc[ii][3] + gbv.w);
        }
        __syncthreads();
        load_w(g_projT, 256, c0, sW, tid);
        __syncthreads();
        float acc2[4][4] = {};
        gemm64(sLT, sW, tx, ty, acc2);
        float4 pbv = *(const float4*)(pb + c0 + tx*4);
        float* dstBase = (c0 < 128) ? (g_left + c0) : (g_right + (c0 - 128));
#pragma unroll
        for (int ii = 0; ii < 4; ii++) {
            int r = r0 + ty*4 + ii;
            float mk = mask[r];
            float4 v;
            v.x = mk * (acc2[ii][0] + pbv.x) * sigv[ii][0];
            v.y = mk * (acc2[ii][1] + pbv.y) * sigv[ii][1];
            v.z = mk * (acc2[ii][2] + pbv.z) * sigv[ii][2];
            v.w = mk * (acc2[ii][3] + pbv.w) * sigv[ii][3];
            *(float4*)(dstBase + (size_t)r*128 + tx*4) = v;
        }
        __syncthreads();
    }

    for (int c0 = 0; c0 < 128; c0 += 64) {
        load_w(g_glT, 128, c0, sW, tid);
        __syncthreads();
        float acc[4][4] = {};
        gemm64(sLT, sW, tx, ty, acc);
        float4 bv = *(const float4*)(glb + c0 + tx*4);
#pragma unroll
        for (int ii = 0; ii < 4; ii++) {
            int r = r0 + ty*4 + ii;
            float4 v;
            v.x = sigf(acc[ii][0] + bv.x);
            v.y = sigf(acc[ii][1] + bv.y);
            v.z = sigf(acc[ii][2] + bv.z);
            v.w = sigf(acc[ii][3] + bv.w);
            *(float4*)(g_glsig + (size_t)r*128 + c0 + tx*4) = v;
        }
        __syncthreads();
    }
}

// ---------------- T1: (r,c) fp32 -> (c,r) bf16 hi/lo split ------------------
__global__ __launch_bounds__(256) void t_fwd()
{
    __shared__ float tile[32][33];
    const float* src = blockIdx.z ? g_right : g_left;
    __nv_bfloat16* dhi = blockIdx.z ? g_RThi : g_LThi;
    __nv_bfloat16* dlo = blockIdx.z ? g_RTlo : g_LTlo;
    int r0 = blockIdx.x*32, c0 = blockIdx.y*32;
    int tx = threadIdx.x & 31, ty = threadIdx.x >> 5;    // (32, 8)
#pragma unroll
    for (int q = 0; q < 4; q++)
        tile[ty + 8*q][tx] = src[(size_t)(r0 + ty + 8*q)*CZ + c0 + tx];
    __syncthreads();
#pragma unroll
    for (int q = 0; q < 4; q++) {
        float x = tile[tx][ty + 8*q];
        __nv_bfloat16 h = __float2bfloat16(x);
        float lo = x - __bfloat162float(h);
        size_t o = (size_t)(c0 + ty + 8*q)*NROW + r0 + tx;
        dhi[o] = h;
        dlo[o] = __float2bfloat16(lo);
    }
}

// ---------------- T2: g_einT (c,r) -> d_out (r,c) ---------------------------
__global__ __launch_bounds__(256) void t_bwd(float* __restrict__ out)
{
    __shared__ float tile[32][33];
    int r0 = blockIdx.x*32, c0 = blockIdx.y*32;
    int tx = threadIdx.x & 31, ty = threadIdx.x >> 5;
#pragma unroll
    for (int q = 0; q < 4; q++)
        tile[ty + 8*q][tx] = g_einT[(size_t)(c0 + ty + 8*q)*NROW + r0 + tx];
    __syncthreads();
#pragma unroll
    for (int q = 0; q < 4; q++)
        out[(size_t)(r0 + ty + 8*q)*CZ + c0 + tx] = tile[tx][ty + 8*q];
}

// ---------------- K2: mma.sync bf16-split batched GEMM ----------------------
// Block: one channel c, one 128x128 tile of C_c = L_c @ R_c^T. 8 warps,
// warp tile 32x64 (m16n8k16). K-chunk 32, double-buffered smem,
// row stride 144B (conflict-free ldmatrix), bf16 hi/lo split = 3 mma passes.
#define RSTRIDE 144
#define COMP_SZ (128*RSTRIDE)       // 18432
#define ST_AHI  0
#define ST_ALO  COMP_SZ
#define ST_BHI  (2*COMP_SZ)
#define ST_BLO  (3*COMP_SZ)
#define STAGE   (4*COMP_SZ)         // 73728
#define SMEM_K2 (2*STAGE)           // 147456

__device__ __forceinline__ void k2_compute(uint32_t sb, const uint32_t aOff[2],
                                           const uint32_t bOff[4], float acc[2][8][4])
{
#pragma unroll
    for (int kk = 0; kk < 2; kk++) {
        uint32_t ah[2][4], al[2][4], bh[4][4], bl[4][4];
#pragma unroll
        for (int fm = 0; fm < 2; fm++) {
            ldsm4(ah[fm], sb + ST_AHI + aOff[fm] + kk*32);
            ldsm4(al[fm], sb + ST_ALO + aOff[fm] + kk*32);
        }
#pragma unroll
        for (int fp = 0; fp < 4; fp++) {
            ldsm4(bh[fp], sb + ST_BHI + bOff[fp] + kk*32);
            ldsm4(bl[fp], sb + ST_BLO + bOff[fp] + kk*32);
        }
#pragma unroll
        for (int fm = 0; fm < 2; fm++)
#pragma unroll
            for (int fn = 0; fn < 8; fn++) {
                int fp = fn >> 1, s = (fn & 1)*2;
                mma16816(acc[fm][fn], ah[fm], bh[fp][s], bh[fp][s+1]);
                mma16816(acc[fm][fn], ah[fm], bl[fp][s], bl[fp][s+1]);
                mma16816(acc[fm][fn], al[fm], bh[fp][s], bh[fp][s+1]);
            }
    }
}

__global__ __launch_bounds__(256) void k2()
{
    extern __shared__ char sb[];
    uint32_t sbase = smem_u32(sb);
    int tid = threadIdx.x, wid = tid >> 5, lane = tid & 31;
    int c  = blockIdx.y;
    int ti = blockIdx.x >> 2, tj = blockIdx.x & 3;

    const __nv_bfloat16* Ah = g_LThi + (size_t)c*NROW + (size_t)ti*128*NN;
    const __nv_bfloat16* Al = g_LTlo + (size_t)c*NROW + (size_t)ti*128*NN;
    const __nv_bfloat16* Bh = g_RThi + (size_t)c*NROW + (size_t)tj*128*NN;
    const __nv_bfloat16* Bl = g_RTlo + (size_t)c*NROW + (size_t)tj*128*NN;
    float* C = g_einT + (size_t)c*NROW + (size_t)(ti*128)*NN + tj*128;

    int wm = wid & 3, wn = wid >> 2;
    int RM = wm*32, RN = wn*64;

    // per-thread ldmatrix byte offsets within a component
    uint32_t aOff[2], bOff[4];
#pragma unroll
    for (int fm = 0; fm < 2; fm++)
        aOff[fm] = (uint32_t)((RM + fm*16 + (lane & 15))*RSTRIDE + (lane >> 4)*16);
#pragma unroll
    for (int fp = 0; fp < 4; fp++)
        bOff[fp] = (uint32_t)((RN + fp*16 + ((lane >> 4) << 3) + (lane & 7))*RSTRIDE
                              + ((lane >> 3) & 1)*16);

    // loader mapping: f = tid + q*256 -> row = f>>2, kg16 = f&3 (16B chunks)
    int lr  = tid >> 2;
    int lkg = tid & 3;

    float acc[2][8][4];
#pragma unroll
    for (int fm = 0; fm < 2; fm++)
#pragma unroll
        for (int fn = 0; fn < 8; fn++)
#pragma unroll
            for (int e = 0; e < 4; e++) acc[fm][fn][e] = 0.f;

    // ---- prologue: chunk 0 -> stage 0
    {
#pragma unroll
        for (int q = 0; q < 2; q++) {
            int r = lr + q*64, kg = lkg;
            size_t go = (size_t)r*NN + kg*8;
            uint32_t so = (uint32_t)(r*RSTRIDE + kg*16);
            *(uint4*)(sb + ST_AHI + so) = *(const uint4*)(Ah + go);
            *(uint4*)(sb + ST_ALO + so) = *(const uint4*)(Al + go);
            *(uint4*)(sb + ST_BHI + so) = *(const uint4*)(Bh + go);
            *(uint4*)(sb + ST_BLO + so) = *(const uint4*)(Bl + go);
        }
    }
    __syncthreads();

    for (int t = 0; t < 16; t++) {
        int cur = t & 1;
        uint4 bufA0[2], bufA1[2], bufB0[2], bufB1[2];
        if (t < 15) {
            int tk = (t+1)*32;
#pragma unroll
            for (int q = 0; q < 2; q++) {
                int r = lr + q*64;
                size_t go = (size_t)r*NN + tk + lkg*8;
                bufA0[q] = *(const uint4*)(Ah + go);
                bufA1[q] = *(const uint4*)(Al + go);
                bufB0[q] = *(const uint4*)(Bh + go);
                bufB1[q] = *(const uint4*)(Bl + go);
            }
        }
        k2_compute(sbase + cur*STAGE, aOff, bOff, acc);
        if (t < 15) {
            char* dst = sb + (cur^1)*STAGE;
#pragma unroll
            for (int q = 0; q < 2; q++) {
                int r = lr + q*64;
                uint32_t so = (uint32_t)(r*RSTRIDE + lkg*16);
                *(uint4*)(dst + ST_AHI + so) = bufA0[q];
                *(uint4*)(dst + ST_ALO + so) = bufA1[q];
                *(uint4*)(dst + ST_BHI + so) = bufB0[q];
                *(uint4*)(dst + ST_BLO + so) = bufB1[q];
            }
        }
        __syncthreads();
    }

    // ---- epilogue: register accumulators -> g_einT
    int rr = lane >> 2, cp = (lane & 3)*2;
#pragma unroll
    for (int fm = 0; fm < 2; fm++)
#pragma unroll
        for (int fn = 0; fn < 8; fn++) {
            int row = RM + fm*16 + rr;
            int col = RN + fn*8 + cp;
            float2 v0 = { acc[fm][fn][0], acc[fm][fn][1] };
            float2 v1 = { acc[fm][fn][2], acc[fm][fn][3] };
            *(float2*)(C + (size_t)row*NN + col)     = v0;
            *(float2*)(C + (size_t)(row+8)*NN + col) = v1;
        }
}

// ---------------- K3: LN(out) -> @outp_w.T + outp_b, * glsig (in place) -----
__global__ __launch_bounds__(256) void k3(float* __restrict__ out,
                                          const float* __restrict__ cnw,
                                          const float* __restrict__ cnb,
                                          const float* __restrict__ ob)
{
    extern __shared__ float sh[];
    float* sLT = sh;            // [128][65]
    float* sW  = sh + 128*65;   // [128][68]
    int tid = threadIdx.x;
    int r0  = blockIdx.x * 64;

    ln_to_smem(out, cnw, cnb, r0, tid, sLT);
    __syncthreads();

    int tx = tid & 15, ty = tid >> 4;
    for (int c0 = 0; c0 < 128; c0 += 64) {
        load_w(g_outpT, 128, c0, sW, tid);
        __syncthreads();
        float acc[4][4] = {};
        gemm64(sLT, sW, tx, ty, acc);
        float4 obv = *(const float4*)(ob + c0 + tx*4);
#pragma unroll
        for (int ii = 0; ii < 4; ii++) {
            int r = r0 + ty*4 + ii;
            float4 gl = *(const float4*)(g_glsig + (size_t)r*128 + c0 + tx*4);
            float4 v;
            v.x = (acc[ii][0] + obv.x) * gl.x;
            v.y = (acc[ii][1] + obv.y) * gl.y;
            v.z = (acc[ii][2] + obv.z) * gl.z;
            v.w = (acc[ii][3] + obv.w) * gl.w;
            *(float4*)(out + (size_t)r*128 + c0 + tx*4) = v;
        }
        __syncthreads();
    }
}

// ---------------- launch ----------------------------------------------------
extern "C" void kernel_launch(void* const* d_in, const int* in_sizes, int n_in,
                              void* d_out, int out_size)
{
    const float* act = (const float*)d_in[0];
    const float* mask= (const float*)d_in[1];
    const float* lnw = (const float*)d_in[2];
    const float* lnb = (const float*)d_in[3];
    const float* pw  = (const float*)d_in[4];
    const float* pb  = (const float*)d_in[5];
    const float* gw  = (const float*)d_in[6];
    const float* gb  = (const float*)d_in[7];
    const float* cnw = (const float*)d_in[8];
    const float* cnb = (const float*)d_in[9];
    const float* ow  = (const float*)d_in[10];
    const float* ob  = (const float*)d_in[11];
    const float* glw = (const float*)d_in[12];
    const float* glb = (const float*)d_in[13];
    float* out = (float*)d_out;

    const int SMEM13 = (128*65 + 128*68) * 4;   // k1/k3 dynamic smem
    cudaFuncSetAttribute(k1, cudaFuncAttributeMaxDynamicSharedMemorySize, SMEM13);
    cudaFuncSetAttribute(k3, cudaFuncAttributeMaxDynamicSharedMemorySize, SMEM13);
    cudaFuncSetAttribute(k2, cudaFuncAttributeMaxDynamicSharedMemorySize, SMEM_K2);

    k_transpose<<<192, 256>>>(pw, gw, glw, ow);
    k1<<<NROW/64, 256, SMEM13>>>(act, mask, lnw, lnb, pb, gb, glb);
    t_fwd<<<dim3(NROW/32, CZ/32, 2), 256>>>();
    k2<<<dim3(16, CZ), 256, SMEM_K2>>>();
    t_bwd<<<dim3(NROW/32, CZ/32), 256>>>(out);
    k3<<<NROW/64, 256, SMEM13>>>(out, cnw, cnb, ob);
}

// round 4
// speedup vs baseline: 3.2114x; 1.4748x over previous
#include <cuda_runtime.h>
#include <cuda_bf16.h>
#include <math.h>
#include <stdint.h>

#define NN 512
#define CZ 128
#define NROW (NN*NN)          // 262144 rows

// ---------------- scratch (static device globals) ---------------------------
__device__ __nv_bfloat16 g_LThi[(size_t)CZ*NROW];  // [c][i*512+k] bf16 hi
__device__ __nv_bfloat16 g_LTlo[(size_t)CZ*NROW];
__device__ __nv_bfloat16 g_RThi[(size_t)CZ*NROW];  // [c][j*512+k]
__device__ __nv_bfloat16 g_RTlo[(size_t)CZ*NROW];
__device__ float g_glsig[(size_t)NROW*CZ];         // row-major (r, c)
__device__ float g_einT [(size_t)CZ*NROW];         // [c][i*512+j]
// weights, bf16 split, [n][k] rows: 0-255 gate, 256-511 proj, 512-639 gl, 640-767 outp
__device__ __nv_bfloat16 g_Whi[768*128];
__device__ __nv_bfloat16 g_Wlo[768*128];

// ======================= PTX helpers (sm_103-safe) ==========================
__device__ __forceinline__ uint32_t smem_u32(const void* p) {
    uint32_t a;
    asm("{ .reg .u64 t; cvta.to.shared.u64 t, %1; cvt.u32.u64 %0, t; }" : "=r"(a) : "l"(p));
    return a;
}
__device__ __forceinline__ void ldsm4(uint32_t r[4], uint32_t addr) {
    asm volatile("ldmatrix.sync.aligned.m8n8.x4.shared.b16 {%0,%1,%2,%3}, [%4];"
        : "=r"(r[0]), "=r"(r[1]), "=r"(r[2]), "=r"(r[3]) : "r"(addr));
}
__device__ __forceinline__ void mma16816(float c[4], const uint32_t a[4],
                                         uint32_t b0, uint32_t b1) {
    asm volatile("mma.sync.aligned.m16n8k16.row.col.f32.bf16.bf16.f32 "
        "{%0,%1,%2,%3}, {%4,%5,%6,%7}, {%8,%9}, {%0,%1,%2,%3};"
        : "+f"(c[0]), "+f"(c[1]), "+f"(c[2]), "+f"(c[3])
        : "r"(a[0]), "r"(a[1]), "r"(a[2]), "r"(a[3]), "r"(b0), "r"(b1));
}
__device__ __forceinline__ float sigf(float x) { return 1.f/(1.f + expf(-x)); }

// ---------------- K0: split all weights into bf16 hi/lo ---------------------
__global__ void wsplit(const float* __restrict__ pw, const float* __restrict__ gw,
                       const float* __restrict__ glw, const float* __restrict__ ow)
{
    int idx = blockIdx.x*256 + threadIdx.x;   // 384*256 = 98304 = 768*128
    int row = idx >> 7;
    float v;
    if      (row < 256) v = gw [idx];
    else if (row < 512) v = pw [idx - 256*128];
    else if (row < 640) v = glw[idx - 512*128];
    else                v = ow [idx - 640*128];
    __nv_bfloat16 h = __float2bfloat16(v);
    g_Whi[idx] = h;
    g_Wlo[idx] = __float2bfloat16(v - __bfloat162float(h));
}

// =================== mma-based LN+GEMM machinery (k1/k3) ====================
// smem layout (bytes):
#define ARS    272                 // A row stride  (128 bf16 + pad)
#define BRS    272                 // B row stride
#define AHI    0                   // 128*272 = 34816
#define ALO    34816
#define BHI    69632               // 64*272 = 17408
#define BLO    87040
#define STHI   104448              // staging 128 x 64 bf16, stride 136
#define STLO   121856
#define SSTR   136
#define SMEM13 139264

// LN 128 rows of src -> bf16 hi/lo A tiles in smem (row-major [row][k])
__device__ __forceinline__ void ln_split(const float* __restrict__ src,
                                         const float* __restrict__ w,
                                         const float* __restrict__ b,
                                         int r0, int tid, char* sb)
{
    int wid = tid >> 5, lane = tid & 31;
    float4 wv = *(const float4*)(w + lane*4);
    float4 bv = *(const float4*)(b + lane*4);
#pragma unroll
    for (int q = 0; q < 16; q++) {
        int row = wid*16 + q;
        float4 x = *(const float4*)(src + (size_t)(r0+row)*CZ + lane*4);
        float s  = x.x+x.y+x.z+x.w;
        float sq = x.x*x.x + x.y*x.y + x.z*x.z + x.w*x.w;
#pragma unroll
        for (int o = 16; o > 0; o >>= 1) {
            s  += __shfl_xor_sync(0xffffffffu, s,  o);
            sq += __shfl_xor_sync(0xffffffffu, sq, o);
        }
        float m  = s * (1.f/CZ);
        float v  = sq * (1.f/CZ) - m*m;
        float rs = rsqrtf(v + 1e-5f);
        float y0 = (x.x-m)*rs*wv.x + bv.x;
        float y1 = (x.y-m)*rs*wv.y + bv.y;
        float y2 = (x.z-m)*rs*wv.z + bv.z;
        float y3 = (x.w-m)*rs*wv.w + bv.w;
        __nv_bfloat162 h01, h23, l01, l23;
        h01.x = __float2bfloat16(y0); h01.y = __float2bfloat16(y1);
        h23.x = __float2bfloat16(y2); h23.y = __float2bfloat16(y3);
        l01.x = __float2bfloat16(y0 - __bfloat162float(h01.x));
        l01.y = __float2bfloat16(y1 - __bfloat162float(h01.y));
        l23.x = __float2bfloat16(y2 - __bfloat162float(h23.x));
        l23.y = __float2bfloat16(y3 - __bfloat162float(h23.y));
        uint32_t off = (uint32_t)(row*ARS + lane*8);
        *(__nv_bfloat162*)(sb + AHI + off)     = h01;
        *(__nv_bfloat162*)(sb + AHI + off + 4) = h23;
        *(__nv_bfloat162*)(sb + ALO + off)     = l01;
        *(__nv_bfloat162*)(sb + ALO + off + 4) = l23;
    }
}

// load 64x128 weight tile (rows nrow0..+63 of g_Whi/g_Wlo) into sB
__device__ __forceinline__ void load_wtile(int nrow0, int tid, char* sb)
{
#pragma unroll
    for (int q = 0; q < 4; q++) {
        int idx = tid + q*256;
        int row = idx >> 4, ch = idx & 15;
        size_t go = (size_t)(nrow0 + row)*128 + ch*8;
        uint32_t so = (uint32_t)(row*BRS + ch*16);
        *(uint4*)(sb + BHI + so) = *(const uint4*)(g_Whi + go);
        *(uint4*)(sb + BLO + so) = *(const uint4*)(g_Wlo + go);
    }
}

// M=128 x N=64 x K=128 bf16-split (3-pass) mma; warp tile 32x32
__device__ __forceinline__ void mma_tile(uint32_t sbase, const uint32_t aOff[2],
                                         const uint32_t bOff[2], float acc[2][4][4])
{
#pragma unroll
    for (int fm = 0; fm < 2; fm++)
#pragma unroll
        for (int fn = 0; fn < 4; fn++)
#pragma unroll
            for (int e = 0; e < 4; e++) acc[fm][fn][e] = 0.f;
#pragma unroll
    for (int kk = 0; kk < 8; kk++) {
        uint32_t ah[2][4], al[2][4], bh[2][4], bl[2][4];
#pragma unroll
        for (int fm = 0; fm < 2; fm++) {
            ldsm4(ah[fm], sbase + AHI + aOff[fm] + kk*32);
            ldsm4(al[fm], sbase + ALO + aOff[fm] + kk*32);
        }
#pragma unroll
        for (int fp = 0; fp < 2; fp++) {
            ldsm4(bh[fp], sbase + BHI + bOff[fp] + kk*32);
            ldsm4(bl[fp], sbase + BLO + bOff[fp] + kk*32);
        }
#pragma unroll
        for (int fm = 0; fm < 2; fm++)
#pragma unroll
            for (int fn = 0; fn < 4; fn++) {
                int fp = fn >> 1, s = (fn & 1)*2;
                mma16816(acc[fm][fn], ah[fm], bh[fp][s], bh[fp][s+1]);
                mma16816(acc[fm][fn], ah[fm], bl[fp][s], bl[fp][s+1]);
                mma16816(acc[fm][fn], al[fm], bh[fp][s], bh[fp][s+1]);
            }
    }
}

// ---------------- K1: LN + gate/proj/gl, writes split-transposed L/R --------
__global__ __launch_bounds__(256) void k1(const float* __restrict__ act,
                                          const float* __restrict__ mask,
                                          const float* __restrict__ lnw,
                                          const float* __restrict__ lnb,
                                          const float* __restrict__ pb,
                                          const float* __restrict__ gb,
                                          const float* __restrict__ glb)
{
    extern __shared__ char sb[];
    uint32_t sbase = smem_u32(sb);
    int tid = threadIdx.x, wid = tid >> 5, lane = tid & 31;
    int r0 = blockIdx.x * 128;
    int wm = wid & 3, wn = wid >> 2;
    int RM = wm*32, RNl = wn*32;
    int rr = lane >> 2, cp = (lane & 3)*2;

    uint32_t aOff[2], bOff[2];
#pragma unroll
    for (int fm = 0; fm < 2; fm++)
        aOff[fm] = (uint32_t)((RM + fm*16 + (lane & 15))*ARS + (lane >> 4)*16);
#pragma unroll
    for (int fp = 0; fp < 2; fp++)
        bOff[fp] = (uint32_t)((RNl + fp*16 + ((lane >> 4) << 3) + (lane & 7))*BRS
                              + ((lane >> 3) & 1)*16);

    ln_split(act, lnw, lnb, r0, tid, sb);
    __syncthreads();

    float acc[2][4][4], sig[2][4][4];

    // ---- 4 tiles of 64 cols: gate (sig) then proj (combine -> L/R split) ----
    for (int nt = 0; nt < 4; nt++) {
        load_wtile(nt*64, tid, sb);               // gate rows 0..255
        __syncthreads();
        mma_tile(sbase, aOff, bOff, acc);
#pragma unroll
        for (int fm = 0; fm < 2; fm++)
#pragma unroll
            for (int fn = 0; fn < 4; fn++) {
                int c0 = nt*64 + RNl + fn*8 + cp;
                float2 gbv = *(const float2*)(gb + c0);
                sig[fm][fn][0] = sigf(acc[fm][fn][0] + gbv.x);
                sig[fm][fn][1] = sigf(acc[fm][fn][1] + gbv.y);
                sig[fm][fn][2] = sigf(acc[fm][fn][2] + gbv.x);
                sig[fm][fn][3] = sigf(acc[fm][fn][3] + gbv.y);
            }
        __syncthreads();                          // done reading sB
        load_wtile(256 + nt*64, tid, sb);         // proj rows 256..511
        __syncthreads();
        mma_tile(sbase, aOff, bOff, acc);
#pragma unroll
        for (int fm = 0; fm < 2; fm++) {
            int rowA = RM + fm*16 + rr;
            float mkA = mask[r0 + rowA];
            float mkB = mask[r0 + rowA + 8];
#pragma unroll
            for (int fn = 0; fn < 4; fn++) {
                int cl = RNl + fn*8 + cp;
                float2 pbv = *(const float2*)(pb + nt*64 + cl);
                float vA0 = mkA*(acc[fm][fn][0] + pbv.x)*sig[fm][fn][0];
                float vA1 = mkA*(acc[fm][fn][1] + pbv.y)*sig[fm][fn][1];
                float vB0 = mkB*(acc[fm][fn][2] + pbv.x)*sig[fm][fn][2];
                float vB1 = mkB*(acc[fm][fn][3] + pbv.y)*sig[fm][fn][3];
                __nv_bfloat162 hA, lA, hB, lB;
                hA.x = __float2bfloat16(vA0); hA.y = __float2bfloat16(vA1);
                lA.x = __float2bfloat16(vA0 - __bfloat162float(hA.x));
                lA.y = __float2bfloat16(vA1 - __bfloat162float(hA.y));
                hB.x = __float2bfloat16(vB0); hB.y = __float2bfloat16(vB1);
                lB.x = __float2bfloat16(vB0 - __bfloat162float(hB.x));
                lB.y = __float2bfloat16(vB1 - __bfloat162float(hB.y));
                uint32_t oA = (uint32_t)(rowA*SSTR + cl*2);
                uint32_t oB = oA + 8*SSTR;
                *(__nv_bfloat162*)(sb + STHI + oA) = hA;
                *(__nv_bfloat162*)(sb + STLO + oA) = lA;
                *(__nv_bfloat162*)(sb + STHI + oB) = hB;
                *(__nv_bfloat162*)(sb + STLO + oB) = lB;
            }
        }
        __syncthreads();                          // staging complete
        {
            __nv_bfloat16* dhi = (nt < 2) ? g_LThi : g_RThi;
            __nv_bfloat16* dlo = (nt < 2) ? g_LTlo : g_RTlo;
            int cbase = (nt & 1)*64;
            int cl = tid >> 2, rs = (tid & 3)*32;
            uint32_t h[16], l[16];
#pragma unroll
            for (int r = 0; r < 16; r++) {
                uint32_t o0 = (uint32_t)((rs + 2*r)*SSTR + cl*2);
                uint32_t o1 = o0 + SSTR;
                h[r] = (uint32_t)*(const unsigned short*)(sb + STHI + o0)
                     | ((uint32_t)*(const unsigned short*)(sb + STHI + o1) << 16);
                l[r] = (uint32_t)*(const unsigned short*)(sb + STLO + o0)
                     | ((uint32_t)*(const unsigned short*)(sb + STLO + o1) << 16);
            }
            size_t go = (size_t)(cbase + cl)*NROW + r0 + rs;
#pragma unroll
            for (int s = 0; s < 4; s++) {
                *(uint4*)(dhi + go + s*8) = make_uint4(h[s*4], h[s*4+1], h[s*4+2], h[s*4+3]);
                *(uint4*)(dlo + go + s*8) = make_uint4(l[s*4], l[s*4+1], l[s*4+2], l[s*4+3]);
            }
        }
        __syncthreads();
    }

    // ---- 2 tiles: gl gate -> g_glsig ----
    for (int nt = 0; nt < 2; nt++) {
        load_wtile(512 + nt*64, tid, sb);
        __syncthreads();
        mma_tile(sbase, aOff, bOff, acc);
#pragma unroll
        for (int fm = 0; fm < 2; fm++) {
            int rowA = RM + fm*16 + rr;
#pragma unroll
            for (int fn = 0; fn < 4; fn++) {
                int c0 = nt*64 + RNl + fn*8 + cp;
                float2 bv = *(const float2*)(glb + c0);
                float2 vA = { sigf(acc[fm][fn][0] + bv.x), sigf(acc[fm][fn][1] + bv.y) };
                float2 vB = { sigf(acc[fm][fn][2] + bv.x), sigf(acc[fm][fn][3] + bv.y) };
                *(float2*)(g_glsig + (size_t)(r0 + rowA)*CZ + c0)     = vA;
                *(float2*)(g_glsig + (size_t)(r0 + rowA + 8)*CZ + c0) = vB;
            }
        }
        __syncthreads();
    }
}

// ---------------- K2: mma.sync bf16-split batched GEMM (unchanged) ----------
#define RSTRIDE 144
#define COMP_SZ (128*RSTRIDE)
#define ST_AHI  0
#define ST_ALO  COMP_SZ
#define ST_BHI  (2*COMP_SZ)
#define ST_BLO  (3*COMP_SZ)
#define STAGE   (4*COMP_SZ)
#define SMEM_K2 (2*STAGE)

__device__ __forceinline__ void k2_compute(uint32_t sbk, const uint32_t aOff[2],
                                           const uint32_t bOff[4], float acc[2][8][4])
{
#pragma unroll
    for (int kk = 0; kk < 2; kk++) {
        uint32_t ah[2][4], al[2][4], bh[4][4], bl[4][4];
#pragma unroll
        for (int fm = 0; fm < 2; fm++) {
            ldsm4(ah[fm], sbk + ST_AHI + aOff[fm] + kk*32);
            ldsm4(al[fm], sbk + ST_ALO + aOff[fm] + kk*32);
        }
#pragma unroll
        for (int fp = 0; fp < 4; fp++) {
            ldsm4(bh[fp], sbk + ST_BHI + bOff[fp] + kk*32);
            ldsm4(bl[fp], sbk + ST_BLO + bOff[fp] + kk*32);
        }
#pragma unroll
        for (int fm = 0; fm < 2; fm++)
#pragma unroll
            for (int fn = 0; fn < 8; fn++) {
                int fp = fn >> 1, s = (fn & 1)*2;
                mma16816(acc[fm][fn], ah[fm], bh[fp][s], bh[fp][s+1]);
                mma16816(acc[fm][fn], ah[fm], bl[fp][s], bl[fp][s+1]);
                mma16816(acc[fm][fn], al[fm], bh[fp][s], bh[fp][s+1]);
            }
    }
}

__global__ __launch_bounds__(256) void k2()
{
    extern __shared__ char sb[];
    uint32_t sbase = smem_u32(sb);
    int tid = threadIdx.x, wid = tid >> 5, lane = tid & 31;
    int c  = blockIdx.y;
    int ti = blockIdx.x >> 2, tj = blockIdx.x & 3;

    const __nv_bfloat16* Ah = g_LThi + (size_t)c*NROW + (size_t)ti*128*NN;
    const __nv_bfloat16* Al = g_LTlo + (size_t)c*NROW + (size_t)ti*128*NN;
    const __nv_bfloat16* Bh = g_RThi + (size_t)c*NROW + (size_t)tj*128*NN;
    const __nv_bfloat16* Bl = g_RTlo + (size_t)c*NROW + (size_t)tj*128*NN;
    float* C = g_einT + (size_t)c*NROW + (size_t)(ti*128)*NN + tj*128;

    int wm = wid & 3, wn = wid >> 2;
    int RM = wm*32, RN = wn*64;

    uint32_t aOff[2], bOff[4];
#pragma unroll
    for (int fm = 0; fm < 2; fm++)
        aOff[fm] = (uint32_t)((RM + fm*16 + (lane & 15))*RSTRIDE + (lane >> 4)*16);
#pragma unroll
    for (int fp = 0; fp < 4; fp++)
        bOff[fp] = (uint32_t)((RN + fp*16 + ((lane >> 4) << 3) + (lane & 7))*RSTRIDE
                              + ((lane >> 3) & 1)*16);

    int lr  = tid >> 2;
    int lkg = tid & 3;

    float acc[2][8][4];
#pragma unroll
    for (int fm = 0; fm < 2; fm++)
#pragma unroll
        for (int fn = 0; fn < 8; fn++)
#pragma unroll
            for (int e = 0; e < 4; e++) acc[fm][fn][e] = 0.f;

#pragma unroll
    for (int q = 0; q < 2; q++) {
        int r = lr + q*64, kg = lkg;
        size_t go = (size_t)r*NN + kg*8;
        uint32_t so = (uint32_t)(r*RSTRIDE + kg*16);
        *(uint4*)(sb + ST_AHI + so) = *(const uint4*)(Ah + go);
        *(uint4*)(sb + ST_ALO + so) = *(const uint4*)(Al + go);
        *(uint4*)(sb + ST_BHI + so) = *(const uint4*)(Bh + go);
        *(uint4*)(sb + ST_BLO + so) = *(const uint4*)(Bl + go);
    }
    __syncthreads();

    for (int t = 0; t < 16; t++) {
        int cur = t & 1;
        uint4 bufA0[2], bufA1[2], bufB0[2], bufB1[2];
        if (t < 15) {
            int tk = (t+1)*32;
#pragma unroll
            for (int q = 0; q < 2; q++) {
                int r = lr + q*64;
                size_t go = (size_t)r*NN + tk + lkg*8;
                bufA0[q] = *(const uint4*)(Ah + go);
                bufA1[q] = *(const uint4*)(Al + go);
                bufB0[q] = *(const uint4*)(Bh + go);
                bufB1[q] = *(const uint4*)(Bl + go);
            }
        }
        k2_compute(sbase + cur*STAGE, aOff, bOff, acc);
        if (t < 15) {
            char* dst = sb + (cur^1)*STAGE;
#pragma unroll
            for (int q = 0; q < 2; q++) {
                int r = lr + q*64;
                uint32_t so = (uint32_t)(r*RSTRIDE + lkg*16);
                *(uint4*)(dst + ST_AHI + so) = bufA0[q];
                *(uint4*)(dst + ST_ALO + so) = bufA1[q];
                *(uint4*)(dst + ST_BHI + so) = bufB0[q];
                *(uint4*)(dst + ST_BLO + so) = bufB1[q];
            }
        }
        __syncthreads();
    }

    int rr = lane >> 2, cp = (lane & 3)*2;
#pragma unroll
    for (int fm = 0; fm < 2; fm++)
#pragma unroll
        for (int fn = 0; fn < 8; fn++) {
            int row = RM + fm*16 + rr;
            int col = RN + fn*8 + cp;
            float2 v0 = { acc[fm][fn][0], acc[fm][fn][1] };
            float2 v1 = { acc[fm][fn][2], acc[fm][fn][3] };
            *(float2*)(C + (size_t)row*NN + col)     = v0;
            *(float2*)(C + (size_t)(row+8)*NN + col) = v1;
        }
}

// ---------------- T2: g_einT (c,r) -> d_out (r,c) ---------------------------
__global__ __launch_bounds__(256) void t_bwd(float* __restrict__ out)
{
    __shared__ float tile[32][33];
    int r0 = blockIdx.x*32, c0 = blockIdx.y*32;
    int tx = threadIdx.x & 31, ty = threadIdx.x >> 5;
#pragma unroll
    for (int q = 0; q < 4; q++)
        tile[ty + 8*q][tx] = g_einT[(size_t)(c0 + ty + 8*q)*NROW + r0 + tx];
    __syncthreads();
#pragma unroll
    for (int q = 0; q < 4; q++)
        out[(size_t)(r0 + ty + 8*q)*CZ + c0 + tx] = tile[tx][ty + 8*q];
}

// ---------------- K3: LN(out) @ outp_w.T + outp_b, * glsig (in place) -------
__global__ __launch_bounds__(256) void k3(float* __restrict__ out,
                                          const float* __restrict__ cnw,
                                          const float* __restrict__ cnb,
                                          const float* __restrict__ ob)
{
    extern __shared__ char sb[];
    uint32_t sbase = smem_u32(sb);
    int tid = threadIdx.x, wid = tid >> 5, lane = tid & 31;
    int r0 = blockIdx.x * 128;
    int wm = wid & 3, wn = wid >> 2;
    int RM = wm*32, RNl = wn*32;
    int rr = lane >> 2, cp = (lane & 3)*2;

    uint32_t aOff[2], bOff[2];
#pragma unroll
    for (int fm = 0; fm < 2; fm++)
        aOff[fm] = (uint32_t)((RM + fm*16 + (lane & 15))*ARS + (lane >> 4)*16);
#pragma unroll
    for (int fp = 0; fp < 2; fp++)
        bOff[fp] = (uint32_t)((RNl + fp*16 + ((lane >> 4) << 3) + (lane & 7))*BRS
                              + ((lane >> 3) & 1)*16);

    ln_split(out, cnw, cnb, r0, tid, sb);
    __syncthreads();

    float acc[2][4][4];
    for (int nt = 0; nt < 2; nt++) {
        load_wtile(640 + nt*64, tid, sb);
        __syncthreads();
        mma_tile(sbase, aOff, bOff, acc);
#pragma unroll
        for (int fm = 0; fm < 2; fm++) {
            int rowA = RM + fm*16 + rr;
#pragma unroll
            for (int fn = 0; fn < 4; fn++) {
                int c0 = nt*64 + RNl + fn*8 + cp;
                float2 obv = *(const float2*)(ob + c0);
                float2 glA = *(const float2*)(g_glsig + (size_t)(r0 + rowA)*CZ + c0);
                float2 glB = *(const float2*)(g_glsig + (size_t)(r0 + rowA + 8)*CZ + c0);
                float2 vA = { (acc[fm][fn][0] + obv.x)*glA.x,
                              (acc[fm][fn][1] + obv.y)*glA.y };
                float2 vB = { (acc[fm][fn][2] + obv.x)*glB.x,
                              (acc[fm][fn][3] + obv.y)*glB.y };
                *(float2*)(out + (size_t)(r0 + rowA)*CZ + c0)     = vA;
                *(float2*)(out + (size_t)(r0 + rowA + 8)*CZ + c0) = vB;
            }
        }
        __syncthreads();
    }
}

// ---------------- launch ----------------------------------------------------
extern "C" void kernel_launch(void* const* d_in, const int* in_sizes, int n_in,
                              void* d_out, int out_size)
{
    const float* act = (const float*)d_in[0];
    const float* mask= (const float*)d_in[1];
    const float* lnw = (const float*)d_in[2];
    const float* lnb = (const float*)d_in[3];
    const float* pw  = (const float*)d_in[4];
    const float* pb  = (const float*)d_in[5];
    const float* gw  = (const float*)d_in[6];
    const float* gb  = (const float*)d_in[7];
    const float* cnw = (const float*)d_in[8];
    const float* cnb = (const float*)d_in[9];
    const float* ow  = (const float*)d_in[10];
    const float* ob  = (const float*)d_in[11];
    const float* glw = (const float*)d_in[12];
    const float* glb = (const float*)d_in[13];
    float* out = (float*)d_out;

    cudaFuncSetAttribute(k1, cudaFuncAttributeMaxDynamicSharedMemorySize, SMEM13);
    cudaFuncSetAttribute(k3, cudaFuncAttributeMaxDynamicSharedMemorySize, SMEM13);
    cudaFuncSetAttribute(k2, cudaFuncAttributeMaxDynamicSharedMemorySize, SMEM_K2);

    wsplit<<<384, 256>>>(pw, gw, glw, ow);
    k1<<<NROW/128, 256, SMEM13>>>(act, mask, lnw, lnb, pb, gb, glb);
    k2<<<dim3(16, CZ), 256, SMEM_K2>>>();
    t_bwd<<<dim3(NROW/32, CZ/32), 256>>>(out);
    k3<<<NROW/128, 256, SMEM13>>>(out, cnw, cnb, ob);
}

// round 5
// speedup vs baseline: 3.3065x; 1.0296x over previous
#include <cuda_runtime.h>
#include <cuda_bf16.h>
#include <math.h>
#include <stdint.h>

#define NN 512
#define CZ 128
#define NROW (NN*NN)          // 262144 rows

// ---------------- scratch (static device globals) ---------------------------
__device__ __nv_bfloat16 g_LThi[(size_t)CZ*NROW];  // [c][i*512+k] bf16 hi
__device__ __nv_bfloat16 g_LTlo[(size_t)CZ*NROW];
__device__ __nv_bfloat16 g_RThi[(size_t)CZ*NROW];  // [c][j*512+k]
__device__ __nv_bfloat16 g_RTlo[(size_t)CZ*NROW];
__device__ float g_glsig[(size_t)NROW*CZ];         // row-major (r, c)
__device__ float g_einT [(size_t)CZ*NROW];         // [c][i*512+j]
// weights, bf16 split, [n][k] rows: 0-255 gate, 256-511 proj, 512-639 gl, 640-767 outp
__device__ __nv_bfloat16 g_Whi[768*128];
__device__ __nv_bfloat16 g_Wlo[768*128];

// ======================= PTX helpers (sm_103-safe) ==========================
__device__ __forceinline__ uint32_t smem_u32(const void* p) {
    uint32_t a;
    asm("{ .reg .u64 t; cvta.to.shared.u64 t, %1; cvt.u32.u64 %0, t; }" : "=r"(a) : "l"(p));
    return a;
}
__device__ __forceinline__ void ldsm4(uint32_t r[4], uint32_t addr) {
    asm volatile("ldmatrix.sync.aligned.m8n8.x4.shared.b16 {%0,%1,%2,%3}, [%4];"
        : "=r"(r[0]), "=r"(r[1]), "=r"(r[2]), "=r"(r[3]) : "r"(addr));
}
__device__ __forceinline__ void mma16816(float c[4], const uint32_t a[4],
                                         uint32_t b0, uint32_t b1) {
    asm volatile("mma.sync.aligned.m16n8k16.row.col.f32.bf16.bf16.f32 "
        "{%0,%1,%2,%3}, {%4,%5,%6,%7}, {%8,%9}, {%0,%1,%2,%3};"
        : "+f"(c[0]), "+f"(c[1]), "+f"(c[2]), "+f"(c[3])
        : "r"(a[0]), "r"(a[1]), "r"(a[2]), "r"(a[3]), "r"(b0), "r"(b1));
}
__device__ __forceinline__ void cp16(uint32_t dst, const void* src) {
    asm volatile("cp.async.cg.shared.global [%0], [%1], 16;" :: "r"(dst), "l"(src));
}
#define CP_COMMIT() asm volatile("cp.async.commit_group;" ::: "memory")
__device__ __forceinline__ float sigf(float x) { return 1.f/(1.f + expf(-x)); }

// ---------------- K0: split all weights into bf16 hi/lo ---------------------
__global__ void wsplit(const float* __restrict__ pw, const float* __restrict__ gw,
                       const float* __restrict__ glw, const float* __restrict__ ow)
{
    int idx = blockIdx.x*256 + threadIdx.x;   // 384*256 = 98304 = 768*128
    int row = idx >> 7;
    float v;
    if      (row < 256) v = gw [idx];
    else if (row < 512) v = pw [idx - 256*128];
    else if (row < 640) v = glw[idx - 512*128];
    else                v = ow [idx - 640*128];
    __nv_bfloat16 h = __float2bfloat16(v);
    g_Whi[idx] = h;
    g_Wlo[idx] = __float2bfloat16(v - __bfloat162float(h));
}

// =================== mma-based LN+GEMM machinery (k1/k3) ====================
#define ARS    272                 // A row stride  (128 bf16 + pad)
#define BRS    272                 // B row stride
#define AHI    0                   // 128*272 = 34816
#define ALO    34816
#define BHI    69632               // 128 rows * 272 = 34816
#define BLO    104448
#define STHI   139264              // staging 128 x 64 bf16, stride 136
#define STLO   156672
#define SSTR   136
#define SMEM13 174080

// LN 128 rows of src -> bf16 hi/lo A tiles in smem (row-major [row][k])
__device__ __forceinline__ void ln_split(const float* __restrict__ src,
                                         const float* __restrict__ w,
                                         const float* __restrict__ b,
                                         int r0, int tid, char* sb)
{
    int wid = tid >> 5, lane = tid & 31;
    float4 wv = *(const float4*)(w + lane*4);
    float4 bv = *(const float4*)(b + lane*4);
#pragma unroll
    for (int q = 0; q < 16; q++) {
        int row = wid*16 + q;
        float4 x = *(const float4*)(src + (size_t)(r0+row)*CZ + lane*4);
        float s  = x.x+x.y+x.z+x.w;
        float sq = x.x*x.x + x.y*x.y + x.z*x.z + x.w*x.w;
#pragma unroll
        for (int o = 16; o > 0; o >>= 1) {
            s  += __shfl_xor_sync(0xffffffffu, s,  o);
            sq += __shfl_xor_sync(0xffffffffu, sq, o);
        }
        float m  = s * (1.f/CZ);
        float v  = sq * (1.f/CZ) - m*m;
        float rs = rsqrtf(v + 1e-5f);
        float y0 = (x.x-m)*rs*wv.x + bv.x;
        float y1 = (x.y-m)*rs*wv.y + bv.y;
        float y2 = (x.z-m)*rs*wv.z + bv.z;
        float y3 = (x.w-m)*rs*wv.w + bv.w;
        __nv_bfloat162 h01, h23, l01, l23;
        h01.x = __float2bfloat16(y0); h01.y = __float2bfloat16(y1);
        h23.x = __float2bfloat16(y2); h23.y = __float2bfloat16(y3);
        l01.x = __float2bfloat16(y0 - __bfloat162float(h01.x));
        l01.y = __float2bfloat16(y1 - __bfloat162float(h01.y));
        l23.x = __float2bfloat16(y2 - __bfloat162float(h23.x));
        l23.y = __float2bfloat16(y3 - __bfloat162float(h23.y));
        uint32_t off = (uint32_t)(row*ARS + lane*8);
        *(__nv_bfloat162*)(sb + AHI + off)     = h01;
        *(__nv_bfloat162*)(sb + AHI + off + 4) = h23;
        *(__nv_bfloat162*)(sb + ALO + off)     = l01;
        *(__nv_bfloat162*)(sb + ALO + off + 4) = l23;
    }
}

// load 128 weight rows into sB: rows 0-63 from rowA0.., rows 64-127 from rowB0..
__device__ __forceinline__ void load_wpair(int rowA0, int rowB0, int tid, char* sb)
{
#pragma unroll
    for (int q = 0; q < 8; q++) {
        int idx = tid + q*256;          // 0..2047
        int row = idx >> 4, ch = idx & 15;
        int gr = (row < 64) ? (rowA0 + row) : (rowB0 + row - 64);
        size_t go = (size_t)gr*128 + ch*8;
        uint32_t so = (uint32_t)(row*BRS + ch*16);
        *(uint4*)(sb + BHI + so) = *(const uint4*)(g_Whi + go);
        *(uint4*)(sb + BLO + so) = *(const uint4*)(g_Wlo + go);
    }
}

// M=128 x N=64 x K=128 bf16-split (3-pass) mma; warp tile 32x32
__device__ __forceinline__ void mma_tile(uint32_t sbase, const uint32_t aOff[2],
                                         const uint32_t bOff[2], float acc[2][4][4])
{
#pragma unroll
    for (int fm = 0; fm < 2; fm++)
#pragma unroll
        for (int fn = 0; fn < 4; fn++)
#pragma unroll
            for (int e = 0; e < 4; e++) acc[fm][fn][e] = 0.f;
#pragma unroll
    for (int kk = 0; kk < 8; kk++) {
        uint32_t ah[2][4], al[2][4], bh[2][4], bl[2][4];
#pragma unroll
        for (int fm = 0; fm < 2; fm++) {
            ldsm4(ah[fm], sbase + AHI + aOff[fm] + kk*32);
            ldsm4(al[fm], sbase + ALO + aOff[fm] + kk*32);
        }
#pragma unroll
        for (int fp = 0; fp < 2; fp++) {
            ldsm4(bh[fp], sbase + BHI + bOff[fp] + kk*32);
            ldsm4(bl[fp], sbase + BLO + bOff[fp] + kk*32);
        }
#pragma unroll
        for (int fm = 0; fm < 2; fm++)
#pragma unroll
            for (int fn = 0; fn < 4; fn++) {
                int fp = fn >> 1, s = (fn & 1)*2;
                mma16816(acc[fm][fn], ah[fm], bh[fp][s], bh[fp][s+1]);
                mma16816(acc[fm][fn], ah[fm], bl[fp][s], bl[fp][s+1]);
                mma16816(acc[fm][fn], al[fm], bh[fp][s], bh[fp][s+1]);
            }
    }
}

// ---------------- K1: LN + gate/proj/gl, writes split-transposed L/R --------
__global__ __launch_bounds__(256) void k1(const float* __restrict__ act,
                                          const float* __restrict__ mask,
                                          const float* __restrict__ lnw,
                                          const float* __restrict__ lnb,
                                          const float* __restrict__ pb,
                                          const float* __restrict__ gb,
                                          const float* __restrict__ glb)
{
    extern __shared__ char sb[];
    uint32_t sbase = smem_u32(sb);
    int tid = threadIdx.x, wid = tid >> 5, lane = tid & 31;
    int r0 = blockIdx.x * 128;
    int wm = wid & 3, wn = wid >> 2;
    int RM = wm*32, RNl = wn*32;
    int rr = lane >> 2, cp = (lane & 3)*2;

    uint32_t aOff[2], bOff[2], bOffP[2];
#pragma unroll
    for (int fm = 0; fm < 2; fm++)
        aOff[fm] = (uint32_t)((RM + fm*16 + (lane & 15))*ARS + (lane >> 4)*16);
#pragma unroll
    for (int fp = 0; fp < 2; fp++) {
        bOff[fp]  = (uint32_t)((RNl + fp*16 + ((lane >> 4) << 3) + (lane & 7))*BRS
                               + ((lane >> 3) & 1)*16);
        bOffP[fp] = bOff[fp] + 64*BRS;
    }

    ln_split(act, lnw, lnb, r0, tid, sb);
    // (no standalone sync needed: first loop iteration syncs after load_wpair,
    //  but A must be visible before mma — the same barrier covers both.)

    float acc[2][4][4], sig[2][4][4];

    // ---- 4 tiles of 64 cols: gate+proj loaded together ----
    for (int nt = 0; nt < 4; nt++) {
        load_wpair(nt*64, 256 + nt*64, tid, sb);   // gate rows | proj rows
        __syncthreads();
        mma_tile(sbase, aOff, bOff, acc);          // gate
#pragma unroll
        for (int fm = 0; fm < 2; fm++)
#pragma unroll
            for (int fn = 0; fn < 4; fn++) {
                int c0 = nt*64 + RNl + fn*8 + cp;
                float2 gbv = *(const float2*)(gb + c0);
                sig[fm][fn][0] = sigf(acc[fm][fn][0] + gbv.x);
                sig[fm][fn][1] = sigf(acc[fm][fn][1] + gbv.y);
                sig[fm][fn][2] = sigf(acc[fm][fn][2] + gbv.x);
                sig[fm][fn][3] = sigf(acc[fm][fn][3] + gbv.y);
            }
        mma_tile(sbase, aOff, bOffP, acc);         // proj
#pragma unroll
        for (int fm = 0; fm < 2; fm++) {
            int rowA = RM + fm*16 + rr;
            float mkA = mask[r0 + rowA];
            float mkB = mask[r0 + rowA + 8];
#pragma unroll
            for (int fn = 0; fn < 4; fn++) {
                int cl = RNl + fn*8 + cp;
                float2 pbv = *(const float2*)(pb + nt*64 + cl);
                float vA0 = mkA*(acc[fm][fn][0] + pbv.x)*sig[fm][fn][0];
                float vA1 = mkA*(acc[fm][fn][1] + pbv.y)*sig[fm][fn][1];
                float vB0 = mkB*(acc[fm][fn][2] + pbv.x)*sig[fm][fn][2];
                float vB1 = mkB*(acc[fm][fn][3] + pbv.y)*sig[fm][fn][3];
                __nv_bfloat162 hA, lA, hB, lB;
                hA.x = __float2bfloat16(vA0); hA.y = __float2bfloat16(vA1);
                lA.x = __float2bfloat16(vA0 - __bfloat162float(hA.x));
                lA.y = __float2bfloat16(vA1 - __bfloat162float(hA.y));
                hB.x = __float2bfloat16(vB0); hB.y = __float2bfloat16(vB1);
                lB.x = __float2bfloat16(vB0 - __bfloat162float(hB.x));
                lB.y = __float2bfloat16(vB1 - __bfloat162float(hB.y));
                uint32_t oA = (uint32_t)(rowA*SSTR + cl*2);
                uint32_t oB = oA + 8*SSTR;
                *(__nv_bfloat162*)(sb + STHI + oA) = hA;
                *(__nv_bfloat162*)(sb + STLO + oA) = lA;
                *(__nv_bfloat162*)(sb + STHI + oB) = hB;
                *(__nv_bfloat162*)(sb + STLO + oB) = lB;
            }
        }
        __syncthreads();                           // staging complete
        {
            __nv_bfloat16* dhi = (nt < 2) ? g_LThi : g_RThi;
            __nv_bfloat16* dlo = (nt < 2) ? g_LTlo : g_RTlo;
            int cbase = (nt & 1)*64;
            int cl = tid >> 2, rs = (tid & 3)*32;
            uint32_t h[16], l[16];
#pragma unroll
            for (int r = 0; r < 16; r++) {
                uint32_t o0 = (uint32_t)((rs + 2*r)*SSTR + cl*2);
                uint32_t o1 = o0 + SSTR;
                h[r] = (uint32_t)*(const unsigned short*)(sb + STHI + o0)
                     | ((uint32_t)*(const unsigned short*)(sb + STHI + o1) << 16);
                l[r] = (uint32_t)*(const unsigned short*)(sb + STLO + o0)
                     | ((uint32_t)*(const unsigned short*)(sb + STLO + o1) << 16);
            }
            size_t go = (size_t)(cbase + cl)*NROW + r0 + rs;
#pragma unroll
            for (int s = 0; s < 4; s++) {
                *(uint4*)(dhi + go + s*8) = make_uint4(h[s*4], h[s*4+1], h[s*4+2], h[s*4+3]);
                *(uint4*)(dlo + go + s*8) = make_uint4(l[s*4], l[s*4+1], l[s*4+2], l[s*4+3]);
            }
        }
        // next iteration's load_wpair writes B only; staging reads above are
        // ordered before next staging writes by the post-load __syncthreads.
    }

    __syncthreads();                               // staging reads done everywhere

    // ---- gl gate: both 64-col halves in one 128-row load ----
    load_wpair(512, 576, tid, sb);
    __syncthreads();
    for (int nt = 0; nt < 2; nt++) {
        mma_tile(sbase, aOff, nt ? bOffP : bOff, acc);
#pragma unroll
        for (int fm = 0; fm < 2; fm++) {
            int rowA = RM + fm*16 + rr;
#pragma unroll
            for (int fn = 0; fn < 4; fn++) {
                int c0 = nt*64 + RNl + fn*8 + cp;
                float2 bv = *(const float2*)(glb + c0);
                float2 vA = { sigf(acc[fm][fn][0] + bv.x), sigf(acc[fm][fn][1] + bv.y) };
                float2 vB = { sigf(acc[fm][fn][2] + bv.x), sigf(acc[fm][fn][3] + bv.y) };
                *(float2*)(g_glsig + (size_t)(r0 + rowA)*CZ + c0)     = vA;
                *(float2*)(g_glsig + (size_t)(r0 + rowA + 8)*CZ + c0) = vB;
            }
        }
    }
}

// ---------------- K2: mma.sync bf16-split GEMM, cp.async 3-stage ------------
#define RSTRIDE 144
#define COMP_SZ (128*RSTRIDE)
#define ST_AHI  0
#define ST_ALO  COMP_SZ
#define ST_BHI  (2*COMP_SZ)
#define ST_BLO  (3*COMP_SZ)
#define STAGE   (4*COMP_SZ)         // 73728
#define SMEM_K2 (3*STAGE)           // 221184

__device__ __forceinline__ void k2_compute(uint32_t sbk, const uint32_t aOff[2],
                                           const uint32_t bOff[4], float acc[2][8][4])
{
#pragma unroll
    for (int kk = 0; kk < 2; kk++) {
        uint32_t ah[2][4], al[2][4], bh[4][4], bl[4][4];
#pragma unroll
        for (int fm = 0; fm < 2; fm++) {
            ldsm4(ah[fm], sbk + ST_AHI + aOff[fm] + kk*32);
            ldsm4(al[fm], sbk + ST_ALO + aOff[fm] + kk*32);
        }
#pragma unroll
        for (int fp = 0; fp < 4; fp++) {
            ldsm4(bh[fp], sbk + ST_BHI + bOff[fp] + kk*32);
            ldsm4(bl[fp], sbk + ST_BLO + bOff[fp] + kk*32);
        }
#pragma unroll
        for (int fm = 0; fm < 2; fm++)
#pragma unroll
            for (int fn = 0; fn < 8; fn++) {
                int fp = fn >> 1, s = (fn & 1)*2;
                mma16816(acc[fm][fn], ah[fm], bh[fp][s], bh[fp][s+1]);
                mma16816(acc[fm][fn], ah[fm], bl[fp][s], bl[fp][s+1]);
                mma16816(acc[fm][fn], al[fm], bh[fp][s], bh[fp][s+1]);
            }
    }
}

__device__ __forceinline__ void k2_copy(uint32_t st,
                                        const __nv_bfloat16* Ah, const __nv_bfloat16* Al,
                                        const __nv_bfloat16* Bh, const __nv_bfloat16* Bl,
                                        int k0, int lr, int lkg)
{
#pragma unroll
    for (int q = 0; q < 2; q++) {
        int r = lr + q*64;
        size_t go = (size_t)r*NN + k0 + lkg*8;
        uint32_t so = (uint32_t)(r*RSTRIDE + lkg*16);
        cp16(st + ST_AHI + so, Ah + go);
        cp16(st + ST_ALO + so, Al + go);
        cp16(st + ST_BHI + so, Bh + go);
        cp16(st + ST_BLO + so, Bl + go);
    }
}

__global__ __launch_bounds__(256) void k2()
{
    extern __shared__ char sb[];
    uint32_t sbase = smem_u32(sb);
    int tid = threadIdx.x, wid = tid >> 5, lane = tid & 31;
    int c  = blockIdx.y;
    int ti = blockIdx.x >> 2, tj = blockIdx.x & 3;

    const __nv_bfloat16* Ah = g_LThi + (size_t)c*NROW + (size_t)ti*128*NN;
    const __nv_bfloat16* Al = g_LTlo + (size_t)c*NROW + (size_t)ti*128*NN;
    const __nv_bfloat16* Bh = g_RThi + (size_t)c*NROW + (size_t)tj*128*NN;
    const __nv_bfloat16* Bl = g_RTlo + (size_t)c*NROW + (size_t)tj*128*NN;
    float* C = g_einT + (size_t)c*NROW + (size_t)(ti*128)*NN + tj*128;

    int wm = wid & 3, wn = wid >> 2;
    int RM = wm*32, RN = wn*64;

    uint32_t aOff[2], bOff[4];
#pragma unroll
    for (int fm = 0; fm < 2; fm++)
        aOff[fm] = (uint32_t)((RM + fm*16 + (lane & 15))*RSTRIDE + (lane >> 4)*16);
#pragma unroll
    for (int fp = 0; fp < 4; fp++)
        bOff[fp] = (uint32_t)((RN + fp*16 + ((lane >> 4) << 3) + (lane & 7))*RSTRIDE
                              + ((lane >> 3) & 1)*16);

    int lr  = tid >> 2;
    int lkg = tid & 3;

    float acc[2][8][4];
#pragma unroll
    for (int fm = 0; fm < 2; fm++)
#pragma unroll
        for (int fn = 0; fn < 8; fn++)
#pragma unroll
            for (int e = 0; e < 4; e++) acc[fm][fn][e] = 0.f;

    // prologue: tiles 0,1 in flight
    k2_copy(sbase + 0*STAGE, Ah, Al, Bh, Bl, 0,  lr, lkg); CP_COMMIT();
    k2_copy(sbase + 1*STAGE, Ah, Al, Bh, Bl, 32, lr, lkg); CP_COMMIT();

    for (int t = 0; t < 16; t++) {
        if (t < 15) asm volatile("cp.async.wait_group 1;" ::: "memory");
        else        asm volatile("cp.async.wait_group 0;" ::: "memory");
        __syncthreads();
        if (t + 2 < 16) {
            k2_copy(sbase + ((t+2)%3)*STAGE, Ah, Al, Bh, Bl, (t+2)*32, lr, lkg);
            CP_COMMIT();
        }
        k2_compute(sbase + (t%3)*STAGE, aOff, bOff, acc);
    }

    int rr = lane >> 2, cp = (lane & 3)*2;
#pragma unroll
    for (int fm = 0; fm < 2; fm++)
#pragma unroll
        for (int fn = 0; fn < 8; fn++) {
            int row = RM + fm*16 + rr;
            int col = RN + fn*8 + cp;
            float2 v0 = { acc[fm][fn][0], acc[fm][fn][1] };
            float2 v1 = { acc[fm][fn][2], acc[fm][fn][3] };
            *(float2*)(C + (size_t)row*NN + col)     = v0;
            *(float2*)(C + (size_t)(row+8)*NN + col) = v1;
        }
}

// ---------------- T2: g_einT (c,r) -> d_out (r,c) ---------------------------
__global__ __launch_bounds__(256) void t_bwd(float* __restrict__ out)
{
    __shared__ float tile[32][33];
    int r0 = blockIdx.x*32, c0 = blockIdx.y*32;
    int tx = threadIdx.x & 31, ty = threadIdx.x >> 5;
#pragma unroll
    for (int q = 0; q < 4; q++)
        tile[ty + 8*q][tx] = g_einT[(size_t)(c0 + ty + 8*q)*NROW + r0 + tx];
    __syncthreads();
#pragma unroll
    for (int q = 0; q < 4; q++)
        out[(size_t)(r0 + ty + 8*q)*CZ + c0 + tx] = tile[tx][ty + 8*q];
}

// ---------------- K3: LN(out) @ outp_w.T + outp_b, * glsig (in place) -------
__global__ __launch_bounds__(256) void k3(float* __restrict__ out,
                                          const float* __restrict__ cnw,
                                          const float* __restrict__ cnb,
                                          const float* __restrict__ ob)
{
    extern __shared__ char sb[];
    uint32_t sbase = smem_u32(sb);
    int tid = threadIdx.x, wid = tid >> 5, lane = tid & 31;
    int r0 = blockIdx.x * 128;
    int wm = wid & 3, wn = wid >> 2;
    int RM = wm*32, RNl = wn*32;
    int rr = lane >> 2, cp = (lane & 3)*2;

    uint32_t aOff[2], bOff[2], bOffP[2];
#pragma unroll
    for (int fm = 0; fm < 2; fm++)
        aOff[fm] = (uint32_t)((RM + fm*16 + (lane & 15))*ARS + (lane >> 4)*16);
#pragma unroll
    for (int fp = 0; fp < 2; fp++) {
        bOff[fp]  = (uint32_t)((RNl + fp*16 + ((lane >> 4) << 3) + (lane & 7))*BRS
                               + ((lane >> 3) & 1)*16);
        bOffP[fp] = bOff[fp] + 64*BRS;
    }

    ln_split(out, cnw, cnb, r0, tid, sb);
    load_wpair(640, 704, tid, sb);
    __syncthreads();

    float acc[2][4][4];
    for (int nt = 0; nt < 2; nt++) {
        mma_tile(sbase, aOff, nt ? bOffP : bOff, acc);
#pragma unroll
        for (int fm = 0; fm < 2; fm++) {
            int rowA = RM + fm*16 + rr;
#pragma unroll
            for (int fn = 0; fn < 4; fn++) {
                int c0 = nt*64 + RNl + fn*8 + cp;
                float2 obv = *(const float2*)(ob + c0);
                float2 glA = *(const float2*)(g_glsig + (size_t)(r0 + rowA)*CZ + c0);
                float2 glB = *(const float2*)(g_glsig + (size_t)(r0 + rowA + 8)*CZ + c0);
                float2 vA = { (acc[fm][fn][0] + obv.x)*glA.x,
                              (acc[fm][fn][1] + obv.y)*glA.y };
                float2 vB = { (acc[fm][fn][2] + obv.x)*glB.x,
                              (acc[fm][fn][3] + obv.y)*glB.y };
                *(float2*)(out + (size_t)(r0 + rowA)*CZ + c0)     = vA;
                *(float2*)(out + (size_t)(r0 + rowA + 8)*CZ + c0) = vB;
            }
        }
    }
}

// ---------------- launch ----------------------------------------------------
extern "C" void kernel_launch(void* const* d_in, const int* in_sizes, int n_in,
                              void* d_out, int out_size)
{
    const float* act = (const float*)d_in[0];
    const float* mask= (const float*)d_in[1];
    const float* lnw = (const float*)d_in[2];
    const float* lnb = (const float*)d_in[3];
    const float* pw  = (const float*)d_in[4];
    const float* pb  = (const float*)d_in[5];
    const float* gw  = (const float*)d_in[6];
    const float* gb  = (const float*)d_in[7];
    const float* cnw = (const float*)d_in[8];
    const float* cnb = (const float*)d_in[9];
    const float* ow  = (const float*)d_in[10];
    const float* ob  = (const float*)d_in[11];
    const float* glw = (const float*)d_in[12];
    const float* glb = (const float*)d_in[13];
    float* out = (float*)d_out;

    cudaFuncSetAttribute(k1, cudaFuncAttributeMaxDynamicSharedMemorySize, SMEM13);
    cudaFuncSetAttribute(k3, cudaFuncAttributeMaxDynamicSharedMemorySize, SMEM13);
    cudaFuncSetAttribute(k2, cudaFuncAttributeMaxDynamicSharedMemorySize, SMEM_K2);

    wsplit<<<384, 256>>>(pw, gw, glw, ow);
    k1<<<NROW/128, 256, SMEM13>>>(act, mask, lnw, lnb, pb, gb, glb);
    k2<<<dim3(16, CZ), 256, SMEM_K2>>>();
    t_bwd<<<dim3(NROW/32, CZ/32), 256>>>(out);
    k3<<<NROW/128, 256, SMEM13>>>(out, cnw, cnb, ob);
}

// round 6
// speedup vs baseline: 4.2386x; 1.2819x over previous
#include <cuda_runtime.h>
#include <cuda_fp16.h>
#include <math.h>
#include <stdint.h>

#define NN 512
#define CZ 128
#define NROW (NN*NN)          // 262144 rows

// ---------------- scratch (static device globals) ---------------------------
__device__ __half g_LThi[(size_t)CZ*NROW];  // [c][i*512+k] fp16 (quantized side)
__device__ __half g_RThi[(size_t)CZ*NROW];  // [c][j*512+k] fp16 hi
__device__ __half g_RTlo[(size_t)CZ*NROW];  // [c][j*512+k] fp16 lo
__device__ float  g_glsig[(size_t)NROW*CZ]; // row-major (r, c)
__device__ float  g_einT [(size_t)CZ*NROW]; // [c][i*512+j]
// weights fp16 hi/lo, [n][k]: rows 0-255 gate, 256-511 proj, 512-639 gl, 640-767 outp
__device__ __half g_Whi[768*128];
__device__ __half g_Wlo[768*128];

// ======================= PTX helpers (sm_103-safe) ==========================
__device__ __forceinline__ uint32_t smem_u32(const void* p) {
    uint32_t a;
    asm("{ .reg .u64 t; cvta.to.shared.u64 t, %1; cvt.u32.u64 %0, t; }" : "=r"(a) : "l"(p));
    return a;
}
__device__ __forceinline__ void ldsm4(uint32_t r[4], uint32_t addr) {
    asm volatile("ldmatrix.sync.aligned.m8n8.x4.shared.b16 {%0,%1,%2,%3}, [%4];"
        : "=r"(r[0]), "=r"(r[1]), "=r"(r[2]), "=r"(r[3]) : "r"(addr));
}
__device__ __forceinline__ void mma16816(float c[4], const uint32_t a[4],
                                         uint32_t b0, uint32_t b1) {
    asm volatile("mma.sync.aligned.m16n8k16.row.col.f32.f16.f16.f32 "
        "{%0,%1,%2,%3}, {%4,%5,%6,%7}, {%8,%9}, {%0,%1,%2,%3};"
        : "+f"(c[0]), "+f"(c[1]), "+f"(c[2]), "+f"(c[3])
        : "r"(a[0]), "r"(a[1]), "r"(a[2]), "r"(a[3]), "r"(b0), "r"(b1));
}
__device__ __forceinline__ void cp16(uint32_t dst, const void* src) {
    asm volatile("cp.async.cg.shared.global [%0], [%1], 16;" :: "r"(dst), "l"(src));
}
#define CP_COMMIT() asm volatile("cp.async.commit_group;" ::: "memory")
__device__ __forceinline__ float sigf(float x) { return 1.f/(1.f + expf(-x)); }

// ---------------- K0: split weights into fp16 hi/lo -------------------------
__global__ void wsplit(const float* __restrict__ pw, const float* __restrict__ gw,
                       const float* __restrict__ glw, const float* __restrict__ ow)
{
    int idx = blockIdx.x*256 + threadIdx.x;   // 384*256 = 98304 = 768*128
    int row = idx >> 7;
    float v;
    if      (row < 256) v = gw [idx];
    else if (row < 512) v = pw [idx - 256*128];
    else if (row < 640) v = glw[idx - 512*128];
    else                v = ow [idx - 640*128];
    __half h = __float2half_rn(v);
    g_Whi[idx] = h;
    g_Wlo[idx] = __float2half_rn(v - __half2float(h));
}

// =================== mma-based LN+GEMM machinery (k1/k3) ====================
#define ARS    272                 // A row stride  (128 fp16 = 256B + pad)
#define BRS    272
#define AHI    0                   // 128*272 = 34816
#define BHI    34816               // 128 rows
#define BLO    69632
#define STHI   104448              // staging 128 x 64 fp16, stride 136
#define STLO   121856
#define SSTR   136
#define SMEM13 139264

// LN 128 rows of src -> fp16 A tile in smem (row-major [row][k]), single comp
__device__ __forceinline__ void ln_quant(const float* __restrict__ src,
                                         const float* __restrict__ w,
                                         const float* __restrict__ b,
                                         int r0, int tid, char* sb)
{
    int wid = tid >> 5, lane = tid & 31;
    float4 wv = *(const float4*)(w + lane*4);
    float4 bv = *(const float4*)(b + lane*4);
#pragma unroll
    for (int q = 0; q < 16; q++) {
        int row = wid*16 + q;
        float4 x = *(const float4*)(src + (size_t)(r0+row)*CZ + lane*4);
        float s  = x.x+x.y+x.z+x.w;
        float sq = x.x*x.x + x.y*x.y + x.z*x.z + x.w*x.w;
#pragma unroll
        for (int o = 16; o > 0; o >>= 1) {
            s  += __shfl_xor_sync(0xffffffffu, s,  o);
            sq += __shfl_xor_sync(0xffffffffu, sq, o);
        }
        float m  = s * (1.f/CZ);
        float v  = sq * (1.f/CZ) - m*m;
        float rs = rsqrtf(v + 1e-5f);
        float y0 = (x.x-m)*rs*wv.x + bv.x;
        float y1 = (x.y-m)*rs*wv.y + bv.y;
        float y2 = (x.z-m)*rs*wv.z + bv.z;
        float y3 = (x.w-m)*rs*wv.w + bv.w;
        uint32_t off = (uint32_t)(row*ARS + lane*8);
        *(__half2*)(sb + AHI + off)     = __floats2half2_rn(y0, y1);
        *(__half2*)(sb + AHI + off + 4) = __floats2half2_rn(y2, y3);
    }
}

// load 128 weight rows into sB: rows 0-63 from rowA0.., rows 64-127 from rowB0..
__device__ __forceinline__ void load_wpair(int rowA0, int rowB0, int tid, char* sb)
{
#pragma unroll
    for (int q = 0; q < 8; q++) {
        int idx = tid + q*256;          // 0..2047
        int row = idx >> 4, ch = idx & 15;
        int gr = (row < 64) ? (rowA0 + row) : (rowB0 + row - 64);
        size_t go = (size_t)gr*128 + ch*8;
        uint32_t so = (uint32_t)(row*BRS + ch*16);
        *(uint4*)(sb + BHI + so) = *(const uint4*)(g_Whi + go);
        *(uint4*)(sb + BLO + so) = *(const uint4*)(g_Wlo + go);
    }
}

// M=128 x N=64 x K=128, fp16 asym 2-pass (ah*bh + ah*bl); warp tile 32x32
__device__ __forceinline__ void mma_tile2(uint32_t sbase, const uint32_t aOff[2],
                                          const uint32_t bOff[2], float acc[2][4][4])
{
#pragma unroll
    for (int fm = 0; fm < 2; fm++)
#pragma unroll
        for (int fn = 0; fn < 4; fn++)
#pragma unroll
            for (int e = 0; e < 4; e++) acc[fm][fn][e] = 0.f;
#pragma unroll
    for (int kk = 0; kk < 8; kk++) {
        uint32_t ah[2][4], bh[2][4], bl[2][4];
#pragma unroll
        for (int fm = 0; fm < 2; fm++)
            ldsm4(ah[fm], sbase + AHI + aOff[fm] + kk*32);
#pragma unroll
        for (int fp = 0; fp < 2; fp++) {
            ldsm4(bh[fp], sbase + BHI + bOff[fp] + kk*32);
            ldsm4(bl[fp], sbase + BLO + bOff[fp] + kk*32);
        }
#pragma unroll
        for (int fm = 0; fm < 2; fm++)
#pragma unroll
            for (int fn = 0; fn < 4; fn++) {
                int fp = fn >> 1, s = (fn & 1)*2;
                mma16816(acc[fm][fn], ah[fm], bh[fp][s], bh[fp][s+1]);
                mma16816(acc[fm][fn], ah[fm], bl[fp][s], bl[fp][s+1]);
            }
    }
}

// ---------------- K1: LN + gate/proj/gl, writes split-transposed L/R --------
__global__ __launch_bounds__(256) void k1(const float* __restrict__ act,
                                          const float* __restrict__ mask,
                                          const float* __restrict__ lnw,
                                          const float* __restrict__ lnb,
                                          const float* __restrict__ pb,
                                          const float* __restrict__ gb,
                                          const float* __restrict__ glb)
{
    extern __shared__ char sb[];
    uint32_t sbase = smem_u32(sb);
    int tid = threadIdx.x, wid = tid >> 5, lane = tid & 31;
    int r0 = blockIdx.x * 128;
    int wm = wid & 3, wn = wid >> 2;
    int RM = wm*32, RNl = wn*32;
    int rr = lane >> 2, cp = (lane & 3)*2;

    uint32_t aOff[2], bOff[2], bOffP[2];
#pragma unroll
    for (int fm = 0; fm < 2; fm++)
        aOff[fm] = (uint32_t)((RM + fm*16 + (lane & 15))*ARS + (lane >> 4)*16);
#pragma unroll
    for (int fp = 0; fp < 2; fp++) {
        bOff[fp]  = (uint32_t)((RNl + fp*16 + ((lane >> 4) << 3) + (lane & 7))*BRS
                               + ((lane >> 3) & 1)*16);
        bOffP[fp] = bOff[fp] + 64*BRS;
    }

    ln_quant(act, lnw, lnb, r0, tid, sb);

    float acc[2][4][4], sig[2][4][4];

    // ---- 4 tiles of 64 cols: gate+proj loaded together ----
    for (int nt = 0; nt < 4; nt++) {
        load_wpair(nt*64, 256 + nt*64, tid, sb);   // gate rows | proj rows
        __syncthreads();
        mma_tile2(sbase, aOff, bOff, acc);         // gate
#pragma unroll
        for (int fm = 0; fm < 2; fm++)
#pragma unroll
            for (int fn = 0; fn < 4; fn++) {
                int c0 = nt*64 + RNl + fn*8 + cp;
                float2 gbv = *(const float2*)(gb + c0);
                sig[fm][fn][0] = sigf(acc[fm][fn][0] + gbv.x);
                sig[fm][fn][1] = sigf(acc[fm][fn][1] + gbv.y);
                sig[fm][fn][2] = sigf(acc[fm][fn][2] + gbv.x);
                sig[fm][fn][3] = sigf(acc[fm][fn][3] + gbv.y);
            }
        mma_tile2(sbase, aOff, bOffP, acc);        // proj
#pragma unroll
        for (int fm = 0; fm < 2; fm++) {
            int rowA = RM + fm*16 + rr;
            float mkA = mask[r0 + rowA];
            float mkB = mask[r0 + rowA + 8];
#pragma unroll
            for (int fn = 0; fn < 4; fn++) {
                int cl = RNl + fn*8 + cp;
                float2 pbv = *(const float2*)(pb + nt*64 + cl);
                float vA0 = mkA*(acc[fm][fn][0] + pbv.x)*sig[fm][fn][0];
                float vA1 = mkA*(acc[fm][fn][1] + pbv.y)*sig[fm][fn][1];
                float vB0 = mkB*(acc[fm][fn][2] + pbv.x)*sig[fm][fn][2];
                float vB1 = mkB*(acc[fm][fn][3] + pbv.y)*sig[fm][fn][3];
                __half2 hA = __floats2half2_rn(vA0, vA1);
                __half2 hB = __floats2half2_rn(vB0, vB1);
                __half2 lA = __floats2half2_rn(vA0 - __half2float(__low2half(hA)),
                                               vA1 - __half2float(__high2half(hA)));
                __half2 lB = __floats2half2_rn(vB0 - __half2float(__low2half(hB)),
                                               vB1 - __half2float(__high2half(hB)));
                uint32_t oA = (uint32_t)(rowA*SSTR + cl*2);
                uint32_t oB = oA + 8*SSTR;
                *(__half2*)(sb + STHI + oA) = hA;
                *(__half2*)(sb + STHI + oB) = hB;
                *(__half2*)(sb + STLO + oA) = lA;
                *(__half2*)(sb + STLO + oB) = lB;
            }
        }
        __syncthreads();                           // staging complete
        {
            int cl = tid >> 2, rs = (tid & 3)*32;
            size_t go;
            uint32_t h[16];
#pragma unroll
            for (int r = 0; r < 16; r++) {
                uint32_t o0 = (uint32_t)((rs + 2*r)*SSTR + cl*2);
                uint32_t o1 = o0 + SSTR;
                h[r] = (uint32_t)*(const unsigned short*)(sb + STHI + o0)
                     | ((uint32_t)*(const unsigned short*)(sb + STHI + o1) << 16);
            }
            if (nt < 2) {                          // left: quantized side, hi only
                go = (size_t)((nt & 1)*64 + cl)*NROW + r0 + rs;
#pragma unroll
                for (int s = 0; s < 4; s++)
                    *(uint4*)(g_LThi + go + s*8) = make_uint4(h[s*4], h[s*4+1], h[s*4+2], h[s*4+3]);
            } else {                               // right: hi + lo
                uint32_t l[16];
#pragma unroll
                for (int r = 0; r < 16; r++) {
                    uint32_t o0 = (uint32_t)((rs + 2*r)*SSTR + cl*2);
                    uint32_t o1 = o0 + SSTR;
                    l[r] = (uint32_t)*(const unsigned short*)(sb + STLO + o0)
                         | ((uint32_t)*(const unsigned short*)(sb + STLO + o1) << 16);
                }
                go = (size_t)((nt & 1)*64 + cl)*NROW + r0 + rs;
#pragma unroll
                for (int s = 0; s < 4; s++) {
                    *(uint4*)(g_RThi + go + s*8) = make_uint4(h[s*4], h[s*4+1], h[s*4+2], h[s*4+3]);
                    *(uint4*)(g_RTlo + go + s*8) = make_uint4(l[s*4], l[s*4+1], l[s*4+2], l[s*4+3]);
                }
            }
        }
    }

    __syncthreads();

    // ---- gl gate: both 64-col halves in one 128-row load ----
    load_wpair(512, 576, tid, sb);
    __syncthreads();
    for (int nt = 0; nt < 2; nt++) {
        mma_tile2(sbase, aOff, nt ? bOffP : bOff, acc);
#pragma unroll
        for (int fm = 0; fm < 2; fm++) {
            int rowA = RM + fm*16 + rr;
#pragma unroll
            for (int fn = 0; fn < 4; fn++) {
                int c0 = nt*64 + RNl + fn*8 + cp;
                float2 bv = *(const float2*)(glb + c0);
                float2 vA = { sigf(acc[fm][fn][0] + bv.x), sigf(acc[fm][fn][1] + bv.y) };
                float2 vB = { sigf(acc[fm][fn][2] + bv.x), sigf(acc[fm][fn][3] + bv.y) };
                *(float2*)(g_glsig + (size_t)(r0 + rowA)*CZ + c0)     = vA;
                *(float2*)(g_glsig + (size_t)(r0 + rowA + 8)*CZ + c0) = vB;
            }
        }
    }
}

// ---------------- K2: fp16 asym 2-pass GEMM, cp.async 2-stage, 2 blocks/SM --
#define RSTRIDE 80
#define KCOMP   (128*RSTRIDE)       // 10240
#define ST_A    0
#define ST_BH   KCOMP
#define ST_BL   (2*KCOMP)
#define STAGE   (3*KCOMP)           // 30720
#define SMEM_K2 (2*STAGE)           // 61440

__device__ __forceinline__ void k2_compute(uint32_t sbk, const uint32_t aOff[2],
                                           const uint32_t bOff[4], float acc[2][8][4])
{
#pragma unroll
    for (int kk = 0; kk < 2; kk++) {
        uint32_t ah[2][4], bh[4][4], bl[4][4];
#pragma unroll
        for (int fm = 0; fm < 2; fm++)
            ldsm4(ah[fm], sbk + ST_A + aOff[fm] + kk*32);
#pragma unroll
        for (int fp = 0; fp < 4; fp++) {
            ldsm4(bh[fp], sbk + ST_BH + bOff[fp] + kk*32);
            ldsm4(bl[fp], sbk + ST_BL + bOff[fp] + kk*32);
        }
#pragma unroll
        for (int fm = 0; fm < 2; fm++)
#pragma unroll
            for (int fn = 0; fn < 8; fn++) {
                int fp = fn >> 1, s = (fn & 1)*2;
                mma16816(acc[fm][fn], ah[fm], bh[fp][s], bh[fp][s+1]);
                mma16816(acc[fm][fn], ah[fm], bl[fp][s], bl[fp][s+1]);
            }
    }
}

__device__ __forceinline__ void k2_copy(uint32_t st,
                                        const __half* Ah, const __half* Bh,
                                        const __half* Bl, int k0, int lr, int lkg)
{
#pragma unroll
    for (int q = 0; q < 2; q++) {
        int r = lr + q*64;
        size_t go = (size_t)r*NN + k0 + lkg*8;
        uint32_t so = (uint32_t)(r*RSTRIDE + lkg*16);
        cp16(st + ST_A  + so, Ah + go);
        cp16(st + ST_BH + so, Bh + go);
        cp16(st + ST_BL + so, Bl + go);
    }
}

__global__ __launch_bounds__(256, 2) void k2()
{
    extern __shared__ char sb[];
    uint32_t sbase = smem_u32(sb);
    int tid = threadIdx.x, wid = tid >> 5, lane = tid & 31;
    int c  = blockIdx.y;
    int ti = blockIdx.x >> 2, tj = blockIdx.x & 3;

    const __half* Ah = g_LThi + (size_t)c*NROW + (size_t)ti*128*NN;
    const __half* Bh = g_RThi + (size_t)c*NROW + (size_t)tj*128*NN;
    const __half* Bl = g_RTlo + (size_t)c*NROW + (size_t)tj*128*NN;
    float* C = g_einT + (size_t)c*NROW + (size_t)(ti*128)*NN + tj*128;

    int wm = wid & 3, wn = wid >> 2;
    int RM = wm*32, RN = wn*64;

    uint32_t aOff[2], bOff[4];
#pragma unroll
    for (int fm = 0; fm < 2; fm++)
        aOff[fm] = (uint32_t)((RM + fm*16 + (lane & 15))*RSTRIDE + (lane >> 4)*16);
#pragma unroll
    for (int fp = 0; fp < 4; fp++)
        bOff[fp] = (uint32_t)((RN + fp*16 + ((lane >> 4) << 3) + (lane & 7))*RSTRIDE
                              + ((lane >> 3) & 1)*16);

    int lr  = tid >> 2;
    int lkg = tid & 3;

    float acc[2][8][4];
#pragma unroll
    for (int fm = 0; fm < 2; fm++)
#pragma unroll
        for (int fn = 0; fn < 8; fn++)
#pragma unroll
            for (int e = 0; e < 4; e++) acc[fm][fn][e] = 0.f;

    k2_copy(sbase, Ah, Bh, Bl, 0, lr, lkg); CP_COMMIT();

    for (int t = 0; t < 16; t++) {
        if (t < 15) {
            k2_copy(sbase + ((t+1) & 1)*STAGE, Ah, Bh, Bl, (t+1)*32, lr, lkg);
            CP_COMMIT();
            asm volatile("cp.async.wait_group 1;" ::: "memory");
        } else {
            asm volatile("cp.async.wait_group 0;" ::: "memory");
        }
        __syncthreads();
        k2_compute(sbase + (t & 1)*STAGE, aOff, bOff, acc);
        __syncthreads();
    }

    int rr = lane >> 2, cp = (lane & 3)*2;
#pragma unroll
    for (int fm = 0; fm < 2; fm++)
#pragma unroll
        for (int fn = 0; fn < 8; fn++) {
            int row = RM + fm*16 + rr;
            int col = RN + fn*8 + cp;
            float2 v0 = { acc[fm][fn][0], acc[fm][fn][1] };
            float2 v1 = { acc[fm][fn][2], acc[fm][fn][3] };
            *(float2*)(C + (size_t)row*NN + col)     = v0;
            *(float2*)(C + (size_t)(row+8)*NN + col) = v1;
        }
}

// ---------------- T2: g_einT (c,r) -> d_out (r,c) ---------------------------
__global__ __launch_bounds__(256) void t_bwd(float* __restrict__ out)
{
    __shared__ float tile[32][33];
    int r0 = blockIdx.x*32, c0 = blockIdx.y*32;
    int tx = threadIdx.x & 31, ty = threadIdx.x >> 5;
#pragma unroll
    for (int q = 0; q < 4; q++)
        tile[ty + 8*q][tx] = g_einT[(size_t)(c0 + ty + 8*q)*NROW + r0 + tx];
    __syncthreads();
#pragma unroll
    for (int q = 0; q < 4; q++)
        out[(size_t)(r0 + ty + 8*q)*CZ + c0 + tx] = tile[tx][ty + 8*q];
}

// ---------------- K3: LN(out) @ outp_w.T + outp_b, * glsig (in place) -------
__global__ __launch_bounds__(256) void k3(float* __restrict__ out,
                                          const float* __restrict__ cnw,
                                          const float* __restrict__ cnb,
                                          const float* __restrict__ ob)
{
    extern __shared__ char sb[];
    uint32_t sbase = smem_u32(sb);
    int tid = threadIdx.x, wid = tid >> 5, lane = tid & 31;
    int r0 = blockIdx.x * 128;
    int wm = wid & 3, wn = wid >> 2;
    int RM = wm*32, RNl = wn*32;
    int rr = lane >> 2, cp = (lane & 3)*2;

    uint32_t aOff[2], bOff[2], bOffP[2];
#pragma unroll
    for (int fm = 0; fm < 2; fm++)
        aOff[fm] = (uint32_t)((RM + fm*16 + (lane & 15))*ARS + (lane >> 4)*16);
#pragma unroll
    for (int fp = 0; fp < 2; fp++) {
        bOff[fp]  = (uint32_t)((RNl + fp*16 + ((lane >> 4) << 3) + (lane & 7))*BRS
                               + ((lane >> 3) & 1)*16);
        bOffP[fp] = bOff[fp] + 64*BRS;
    }

    ln_quant(out, cnw, cnb, r0, tid, sb);
    load_wpair(640, 704, tid, sb);
    __syncthreads();

    float acc[2][4][4];
    for (int nt = 0; nt < 2; nt++) {
        mma_tile2(sbase, aOff, nt ? bOffP : bOff, acc);
#pragma unroll
        for (int fm = 0; fm < 2; fm++) {
            int rowA = RM + fm*16 + rr;
#pragma unroll
            for (int fn = 0; fn < 4; fn++) {
                int c0 = nt*64 + RNl + fn*8 + cp;
                float2 obv = *(const float2*)(ob + c0);
                float2 glA = *(const float2*)(g_glsig + (size_t)(r0 + rowA)*CZ + c0);
                float2 glB = *(const float2*)(g_glsig + (size_t)(r0 + rowA + 8)*CZ + c0);
                float2 vA = { (acc[fm][fn][0] + obv.x)*glA.x,
                              (acc[fm][fn][1] + obv.y)*glA.y };
                float2 vB = { (acc[fm][fn][2] + obv.x)*glB.x,
                              (acc[fm][fn][3] + obv.y)*glB.y };
                *(float2*)(out + (size_t)(r0 + rowA)*CZ + c0)     = vA;
                *(float2*)(out + (size_t)(r0 + rowA + 8)*CZ + c0) = vB;
            }
        }
    }
}

// ---------------- launch ----------------------------------------------------
extern "C" void kernel_launch(void* const* d_in, const int* in_sizes, int n_in,
                              void* d_out, int out_size)
{
    const float* act = (const float*)d_in[0];
    const float* mask= (const float*)d_in[1];
    const float* lnw = (const float*)d_in[2];
    const float* lnb = (const float*)d_in[3];
    const float* pw  = (const float*)d_in[4];
    const float* pb  = (const float*)d_in[5];
    const float* gw  = (const float*)d_in[6];
    const float* gb  = (const float*)d_in[7];
    const float* cnw = (const float*)d_in[8];
    const float* cnb = (const float*)d_in[9];
    const float* ow  = (const float*)d_in[10];
    const float* ob  = (const float*)d_in[11];
    const float* glw = (const float*)d_in[12];
    const float* glb = (const float*)d_in[13];
    float* out = (float*)d_out;

    cudaFuncSetAttribute(k1, cudaFuncAttributeMaxDynamicSharedMemorySize, SMEM13);
    cudaFuncSetAttribute(k3, cudaFuncAttributeMaxDynamicSharedMemorySize, SMEM13);
    cudaFuncSetAttribute(k2, cudaFuncAttributeMaxDynamicSharedMemorySize, SMEM_K2);

    wsplit<<<384, 256>>>(pw, gw, glw, ow);
    k1<<<NROW/128, 256, SMEM13>>>(act, mask, lnw, lnb, pb, gb, glb);
    k2<<<dim3(16, CZ), 256, SMEM_K2>>>();
    t_bwd<<<dim3(NROW/32, CZ/32), 256>>>(out);
    k3<<<NROW/128, 256, SMEM13>>>(out, cnw, cnb, ob);
}

// round 7
// speedup vs baseline: 5.4327x; 1.2817x over previous
#include <cuda_runtime.h>
#include <cuda_fp16.h>
#include <math.h>
#include <stdint.h>

#define NN 512
#define CZ 128
#define NROW (NN*NN)          // 262144 rows

// ---------------- scratch (static device globals) ---------------------------
__device__ __half g_LThi[(size_t)CZ*NROW];  // [c][i*512+k] fp16 (quantized side)
__device__ __half g_RThi[(size_t)CZ*NROW];  // [c][j*512+k] fp16 hi
__device__ __half g_RTlo[(size_t)CZ*NROW];  // [c][j*512+k] fp16 lo
__device__ float  g_glsig[(size_t)NROW*CZ]; // row-major (r, c)
__device__ float  g_einT [(size_t)CZ*NROW]; // [c][i*512+j]
// weights fp16 hi/lo, [n][k]: rows 0-255 gate, 256-511 proj, 512-639 gl, 640-767 outp
__device__ __half g_Whi[768*128];
__device__ __half g_Wlo[768*128];

// ======================= PTX helpers (sm_103-safe) ==========================
__device__ __forceinline__ uint32_t smem_u32(const void* p) {
    uint32_t a;
    asm("{ .reg .u64 t; cvta.to.shared.u64 t, %1; cvt.u32.u64 %0, t; }" : "=r"(a) : "l"(p));
    return a;
}
__device__ __forceinline__ void ldsm4(uint32_t r[4], uint32_t addr) {
    asm volatile("ldmatrix.sync.aligned.m8n8.x4.shared.b16 {%0,%1,%2,%3}, [%4];"
        : "=r"(r[0]), "=r"(r[1]), "=r"(r[2]), "=r"(r[3]) : "r"(addr));
}
__device__ __forceinline__ void mma16816(float c[4], const uint32_t a[4],
                                         uint32_t b0, uint32_t b1) {
    asm volatile("mma.sync.aligned.m16n8k16.row.col.f32.f16.f16.f32 "
        "{%0,%1,%2,%3}, {%4,%5,%6,%7}, {%8,%9}, {%0,%1,%2,%3};"
        : "+f"(c[0]), "+f"(c[1]), "+f"(c[2]), "+f"(c[3])
        : "r"(a[0]), "r"(a[1]), "r"(a[2]), "r"(a[3]), "r"(b0), "r"(b1));
}
__device__ __forceinline__ void cp16(uint32_t dst, const void* src) {
    asm volatile("cp.async.cg.shared.global [%0], [%1], 16;" :: "r"(dst), "l"(src));
}
#define CP_COMMIT() asm volatile("cp.async.commit_group;" ::: "memory")
__device__ __forceinline__ float sigf(float x) { return 1.f/(1.f + expf(-x)); }

// ---------------- K0: split weights into fp16 hi/lo -------------------------
__global__ void wsplit(const float* __restrict__ pw, const float* __restrict__ gw,
                       const float* __restrict__ glw, const float* __restrict__ ow)
{
    int idx = blockIdx.x*256 + threadIdx.x;   // 384*256 = 98304 = 768*128
    int row = idx >> 7;
    float v;
    if      (row < 256) v = gw [idx];
    else if (row < 512) v = pw [idx - 256*128];
    else if (row < 640) v = glw[idx - 512*128];
    else                v = ow [idx - 640*128];
    __half h = __float2half_rn(v);
    g_Whi[idx] = h;
    g_Wlo[idx] = __float2half_rn(v - __half2float(h));
}

// =================== mma-based LN+GEMM machinery (k1/k3) ====================
#define ARS    272                 // A row stride  (128 fp16 = 256B + pad)
#define BRS    272
#define AHI    0                   // A: 128*272 = 34816
#define BHI    34816               // B hi: 128 rows
#define BLO    69632               // B lo
// staging (k1) REUSES the BHI region after proj mma has consumed the weights
#define STHI   34816               // 128 x 64 fp16, stride 136 -> 17408
#define STLO   52224
#define SSTR   136
#define SMEM13 104448              // <= 116224 -> 2 blocks/SM
// k3f extra: fp32 einT tile + LN partials
#define TILEF  34816               // 128 x 132 fp32 = 67584, inside B region
#define TFS    132
#define PSUM   104448              // 256 floats
#define PSQ    105472              // 256 floats
#define SMEM_K3 106496

// LN 128 rows of src -> fp16 A tile in smem (row-major [row][k]), single comp
__device__ __forceinline__ void ln_quant(const float* __restrict__ src,
                                         const float* __restrict__ w,
                                         const float* __restrict__ b,
                                         int r0, int tid, char* sb)
{
    int wid = tid >> 5, lane = tid & 31;
    float4 wv = *(const float4*)(w + lane*4);
    float4 bv = *(const float4*)(b + lane*4);
#pragma unroll
    for (int q = 0; q < 16; q++) {
        int row = wid*16 + q;
        float4 x = *(const float4*)(src + (size_t)(r0+row)*CZ + lane*4);
        float s  = x.x+x.y+x.z+x.w;
        float sq = x.x*x.x + x.y*x.y + x.z*x.z + x.w*x.w;
#pragma unroll
        for (int o = 16; o > 0; o >>= 1) {
            s  += __shfl_xor_sync(0xffffffffu, s,  o);
            sq += __shfl_xor_sync(0xffffffffu, sq, o);
        }
        float m  = s * (1.f/CZ);
        float v  = sq * (1.f/CZ) - m*m;
        float rs = rsqrtf(v + 1e-5f);
        float y0 = (x.x-m)*rs*wv.x + bv.x;
        float y1 = (x.y-m)*rs*wv.y + bv.y;
        float y2 = (x.z-m)*rs*wv.z + bv.z;
        float y3 = (x.w-m)*rs*wv.w + bv.w;
        uint32_t off = (uint32_t)(row*ARS + lane*8);
        *(__half2*)(sb + AHI + off)     = __floats2half2_rn(y0, y1);
        *(__half2*)(sb + AHI + off + 4) = __floats2half2_rn(y2, y3);
    }
}

// load 128 weight rows into sB: rows 0-63 from rowA0.., rows 64-127 from rowB0..
__device__ __forceinline__ void load_wpair(int rowA0, int rowB0, int tid, char* sb)
{
#pragma unroll
    for (int q = 0; q < 8; q++) {
        int idx = tid + q*256;          // 0..2047
        int row = idx >> 4, ch = idx & 15;
        int gr = (row < 64) ? (rowA0 + row) : (rowB0 + row - 64);
        size_t go = (size_t)gr*128 + ch*8;
        uint32_t so = (uint32_t)(row*BRS + ch*16);
        *(uint4*)(sb + BHI + so) = *(const uint4*)(g_Whi + go);
        *(uint4*)(sb + BLO + so) = *(const uint4*)(g_Wlo + go);
    }
}

// M=128 x N=64 x K=128, fp16 asym 2-pass (ah*bh + ah*bl); warp tile 32x32
__device__ __forceinline__ void mma_tile2(uint32_t sbase, const uint32_t aOff[2],
                                          const uint32_t bOff[2], float acc[2][4][4])
{
#pragma unroll
    for (int fm = 0; fm < 2; fm++)
#pragma unroll
        for (int fn = 0; fn < 4; fn++)
#pragma unroll
            for (int e = 0; e < 4; e++) acc[fm][fn][e] = 0.f;
#pragma unroll
    for (int kk = 0; kk < 8; kk++) {
        uint32_t ah[2][4], bh[2][4], bl[2][4];
#pragma unroll
        for (int fm = 0; fm < 2; fm++)
            ldsm4(ah[fm], sbase + AHI + aOff[fm] + kk*32);
#pragma unroll
        for (int fp = 0; fp < 2; fp++) {
            ldsm4(bh[fp], sbase + BHI + bOff[fp] + kk*32);
            ldsm4(bl[fp], sbase + BLO + bOff[fp] + kk*32);
        }
#pragma unroll
        for (int fm = 0; fm < 2; fm++)
#pragma unroll
            for (int fn = 0; fn < 4; fn++) {
                int fp = fn >> 1, s = (fn & 1)*2;
                mma16816(acc[fm][fn], ah[fm], bh[fp][s], bh[fp][s+1]);
                mma16816(acc[fm][fn], ah[fm], bl[fp][s], bl[fp][s+1]);
            }
    }
}

// ---------------- K1: LN + gate/proj/gl, writes split-transposed L/R --------
__global__ __launch_bounds__(256, 2) void k1(const float* __restrict__ act,
                                             const float* __restrict__ mask,
                                             const float* __restrict__ lnw,
                                             const float* __restrict__ lnb,
                                             const float* __restrict__ pb,
                                             const float* __restrict__ gb,
                                             const float* __restrict__ glb)
{
    extern __shared__ char sb[];
    uint32_t sbase = smem_u32(sb);
    int tid = threadIdx.x, wid = tid >> 5, lane = tid & 31;
    int r0 = blockIdx.x * 128;
    int wm = wid & 3, wn = wid >> 2;
    int RM = wm*32, RNl = wn*32;
    int rr = lane >> 2, cp = (lane & 3)*2;

    uint32_t aOff[2], bOff[2], bOffP[2];
#pragma unroll
    for (int fm = 0; fm < 2; fm++)
        aOff[fm] = (uint32_t)((RM + fm*16 + (lane & 15))*ARS + (lane >> 4)*16);
#pragma unroll
    for (int fp = 0; fp < 2; fp++) {
        bOff[fp]  = (uint32_t)((RNl + fp*16 + ((lane >> 4) << 3) + (lane & 7))*BRS
                               + ((lane >> 3) & 1)*16);
        bOffP[fp] = bOff[fp] + 64*BRS;
    }

    ln_quant(act, lnw, lnb, r0, tid, sb);

    float acc[2][4][4], sig[2][4][4];

    // ---- 4 tiles of 64 cols: gate+proj loaded together; staging reuses B ----
    for (int nt = 0; nt < 4; nt++) {
        load_wpair(nt*64, 256 + nt*64, tid, sb);   // gate rows | proj rows
        __syncthreads();                           // B (and A on nt=0) visible
        mma_tile2(sbase, aOff, bOff, acc);         // gate
#pragma unroll
        for (int fm = 0; fm < 2; fm++)
#pragma unroll
            for (int fn = 0; fn < 4; fn++) {
                int c0 = nt*64 + RNl + fn*8 + cp;
                float2 gbv = *(const float2*)(gb + c0);
                sig[fm][fn][0] = sigf(acc[fm][fn][0] + gbv.x);
                sig[fm][fn][1] = sigf(acc[fm][fn][1] + gbv.y);
                sig[fm][fn][2] = sigf(acc[fm][fn][2] + gbv.x);
                sig[fm][fn][3] = sigf(acc[fm][fn][3] + gbv.y);
            }
        mma_tile2(sbase, aOff, bOffP, acc);        // proj
        __syncthreads();                           // everyone done reading B
#pragma unroll
        for (int fm = 0; fm < 2; fm++) {
            int rowA = RM + fm*16 + rr;
            float mkA = mask[r0 + rowA];
            float mkB = mask[r0 + rowA + 8];
#pragma unroll
            for (int fn = 0; fn < 4; fn++) {
                int cl = RNl + fn*8 + cp;
                float2 pbv = *(const float2*)(pb + nt*64 + cl);
                float vA0 = mkA*(acc[fm][fn][0] + pbv.x)*sig[fm][fn][0];
                float vA1 = mkA*(acc[fm][fn][1] + pbv.y)*sig[fm][fn][1];
                float vB0 = mkB*(acc[fm][fn][2] + pbv.x)*sig[fm][fn][2];
                float vB1 = mkB*(acc[fm][fn][3] + pbv.y)*sig[fm][fn][3];
                __half2 hA = __floats2half2_rn(vA0, vA1);
                __half2 hB = __floats2half2_rn(vB0, vB1);
                __half2 lA = __floats2half2_rn(vA0 - __half2float(__low2half(hA)),
                                               vA1 - __half2float(__high2half(hA)));
                __half2 lB = __floats2half2_rn(vB0 - __half2float(__low2half(hB)),
                                               vB1 - __half2float(__high2half(hB)));
                uint32_t oA = (uint32_t)(rowA*SSTR + cl*2);
                uint32_t oB = oA + 8*SSTR;
                *(__half2*)(sb + STHI + oA) = hA;
                *(__half2*)(sb + STHI + oB) = hB;
                *(__half2*)(sb + STLO + oA) = lA;
                *(__half2*)(sb + STLO + oB) = lB;
            }
        }
        __syncthreads();                           // staging writes complete
        {
            int cl = tid >> 2, rs = (tid & 3)*32;
            size_t go;
            uint32_t h[16];
#pragma unroll
            for (int r = 0; r < 16; r++) {
                uint32_t o0 = (uint32_t)((rs + 2*r)*SSTR + cl*2);
                uint32_t o1 = o0 + SSTR;
                h[r] = (uint32_t)*(const unsigned short*)(sb + STHI + o0)
                     | ((uint32_t)*(const unsigned short*)(sb + STHI + o1) << 16);
            }
            if (nt < 2) {                          // left: quantized side, hi only
                go = (size_t)((nt & 1)*64 + cl)*NROW + r0 + rs;
#pragma unroll
                for (int s = 0; s < 4; s++)
                    *(uint4*)(g_LThi + go + s*8) = make_uint4(h[s*4], h[s*4+1], h[s*4+2], h[s*4+3]);
            } else {                               // right: hi + lo
                uint32_t l[16];
#pragma unroll
                for (int r = 0; r < 16; r++) {
                    uint32_t o0 = (uint32_t)((rs + 2*r)*SSTR + cl*2);
                    uint32_t o1 = o0 + SSTR;
                    l[r] = (uint32_t)*(const unsigned short*)(sb + STLO + o0)
                         | ((uint32_t)*(const unsigned short*)(sb + STLO + o1) << 16);
                }
                go = (size_t)((nt & 1)*64 + cl)*NROW + r0 + rs;
#pragma unroll
                for (int s = 0; s < 4; s++) {
                    *(uint4*)(g_RThi + go + s*8) = make_uint4(h[s*4], h[s*4+1], h[s*4+2], h[s*4+3]);
                    *(uint4*)(g_RTlo + go + s*8) = make_uint4(l[s*4], l[s*4+1], l[s*4+2], l[s*4+3]);
                }
            }
        }
        __syncthreads();                           // staging reads done before next load
    }

    // ---- gl gate: both 64-col halves in one 128-row load ----
    load_wpair(512, 576, tid, sb);
    __syncthreads();
    for (int nt = 0; nt < 2; nt++) {
        mma_tile2(sbase, aOff, nt ? bOffP : bOff, acc);
#pragma unroll
        for (int fm = 0; fm < 2; fm++) {
            int rowA = RM + fm*16 + rr;
#pragma unroll
            for (int fn = 0; fn < 4; fn++) {
                int c0 = nt*64 + RNl + fn*8 + cp;
                float2 bv = *(const float2*)(glb + c0);
                float2 vA = { sigf(acc[fm][fn][0] + bv.x), sigf(acc[fm][fn][1] + bv.y) };
                float2 vB = { sigf(acc[fm][fn][2] + bv.x), sigf(acc[fm][fn][3] + bv.y) };
                *(float2*)(g_glsig + (size_t)(r0 + rowA)*CZ + c0)     = vA;
                *(float2*)(g_glsig + (size_t)(r0 + rowA + 8)*CZ + c0) = vB;
            }
        }
    }
}

// ---------------- K2: fp16 asym 2-pass GEMM, cp.async 2-stage, 2 blocks/SM --
#define RSTRIDE 80
#define KCOMP   (128*RSTRIDE)       // 10240
#define ST_A    0
#define ST_BH   KCOMP
#define ST_BL   (2*KCOMP)
#define STAGE   (3*KCOMP)           // 30720
#define SMEM_K2 (2*STAGE)           // 61440

__device__ __forceinline__ void k2_compute(uint32_t sbk, const uint32_t aOff[2],
                                           const uint32_t bOff[4], float acc[2][8][4])
{
#pragma unroll
    for (int kk = 0; kk < 2; kk++) {
        uint32_t ah[2][4], bh[4][4], bl[4][4];
#pragma unroll
        for (int fm = 0; fm < 2; fm++)
            ldsm4(ah[fm], sbk + ST_A + aOff[fm] + kk*32);
#pragma unroll
        for (int fp = 0; fp < 4; fp++) {
            ldsm4(bh[fp], sbk + ST_BH + bOff[fp] + kk*32);
            ldsm4(bl[fp], sbk + ST_BL + bOff[fp] + kk*32);
        }
#pragma unroll
        for (int fm = 0; fm < 2; fm++)
#pragma unroll
            for (int fn = 0; fn < 8; fn++) {
                int fp = fn >> 1, s = (fn & 1)*2;
                mma16816(acc[fm][fn], ah[fm], bh[fp][s], bh[fp][s+1]);
                mma16816(acc[fm][fn], ah[fm], bl[fp][s], bl[fp][s+1]);
            }
    }
}

__device__ __forceinline__ void k2_copy(uint32_t st,
                                        const __half* Ah, const __half* Bh,
                                        const __half* Bl, int k0, int lr, int lkg)
{
#pragma unroll
    for (int q = 0; q < 2; q++) {
        int r = lr + q*64;
        size_t go = (size_t)r*NN + k0 + lkg*8;
        uint32_t so = (uint32_t)(r*RSTRIDE + lkg*16);
        cp16(st + ST_A  + so, Ah + go);
        cp16(st + ST_BH + so, Bh + go);
        cp16(st + ST_BL + so, Bl + go);
    }
}

__global__ __launch_bounds__(256, 2) void k2()
{
    extern __shared__ char sb[];
    uint32_t sbase = smem_u32(sb);
    int tid = threadIdx.x, wid = tid >> 5, lane = tid & 31;
    int c  = blockIdx.y;
    int ti = blockIdx.x >> 2, tj = blockIdx.x & 3;

    const __half* Ah = g_LThi + (size_t)c*NROW + (size_t)ti*128*NN;
    const __half* Bh = g_RThi + (size_t)c*NROW + (size_t)tj*128*NN;
    const __half* Bl = g_RTlo + (size_t)c*NROW + (size_t)tj*128*NN;
    float* C = g_einT + (size_t)c*NROW + (size_t)(ti*128)*NN + tj*128;

    int wm = wid & 3, wn = wid >> 2;
    int RM = wm*32, RN = wn*64;

    uint32_t aOff[2], bOff[4];
#pragma unroll
    for (int fm = 0; fm < 2; fm++)
        aOff[fm] = (uint32_t)((RM + fm*16 + (lane & 15))*RSTRIDE + (lane >> 4)*16);
#pragma unroll
    for (int fp = 0; fp < 4; fp++)
        bOff[fp] = (uint32_t)((RN + fp*16 + ((lane >> 4) << 3) + (lane & 7))*RSTRIDE
                              + ((lane >> 3) & 1)*16);

    int lr  = tid >> 2;
    int lkg = tid & 3;

    float acc[2][8][4];
#pragma unroll
    for (int fm = 0; fm < 2; fm++)
#pragma unroll
        for (int fn = 0; fn < 8; fn++)
#pragma unroll
            for (int e = 0; e < 4; e++) acc[fm][fn][e] = 0.f;

    k2_copy(sbase, Ah, Bh, Bl, 0, lr, lkg); CP_COMMIT();

    for (int t = 0; t < 16; t++) {
        if (t < 15) {
            k2_copy(sbase + ((t+1) & 1)*STAGE, Ah, Bh, Bl, (t+1)*32, lr, lkg);
            CP_COMMIT();
            asm volatile("cp.async.wait_group 1;" ::: "memory");
        } else {
            asm volatile("cp.async.wait_group 0;" ::: "memory");
        }
        __syncthreads();
        k2_compute(sbase + (t & 1)*STAGE, aOff, bOff, acc);
        __syncthreads();
    }

    int rr = lane >> 2, cp = (lane & 3)*2;
#pragma unroll
    for (int fm = 0; fm < 2; fm++)
#pragma unroll
        for (int fn = 0; fn < 8; fn++) {
            int row = RM + fm*16 + rr;
            int col = RN + fn*8 + cp;
            float2 v0 = { acc[fm][fn][0], acc[fm][fn][1] };
            float2 v1 = { acc[fm][fn][2], acc[fm][fn][3] };
            *(float2*)(C + (size_t)row*NN + col)     = v0;
            *(float2*)(C + (size_t)(row+8)*NN + col) = v1;
        }
}

// ---------------- K3f: einT tile load + transpose-LN + outp GEMM + gl -------
// Block = 128 rows of out = (fixed i, 128 consecutive j). Reads g_einT
// coalesced (512B rows), LN over c along smem columns, writes fp16 A tile,
// then reuses the tile region for the outp weights. Replaces t_bwd + k3.
__global__ __launch_bounds__(256, 2) void k3f(float* __restrict__ out,
                                              const float* __restrict__ cnw,
                                              const float* __restrict__ cnb,
                                              const float* __restrict__ ob)
{
    extern __shared__ char sb[];
    uint32_t sbase = smem_u32(sb);
    float* tileF = (float*)(sb + TILEF);
    float* psum  = (float*)(sb + PSUM);
    float* psq   = (float*)(sb + PSQ);
    int tid = threadIdx.x, wid = tid >> 5, lane = tid & 31;
    int r0 = blockIdx.x * 128;         // = i*512 + jbase

    // ---- load 128(c) x 128(j) fp32 tile of g_einT, coalesced ----
#pragma unroll
    for (int q = 0; q < 16; q++) {
        int idx = tid + q*256;             // float4 index, 4096 total
        int c = idx >> 5, col4 = idx & 31;
        float4 v = *(const float4*)(g_einT + (size_t)c*NROW + r0 + col4*4);
        *(float4*)(tileF + c*TFS + col4*4) = v;
    }
    __syncthreads();

    // ---- LN over c for each j (column reads, conflict-free) ----
    {
        int half = tid >> 7, j = tid & 127;
        float s = 0.f, sq = 0.f;
#pragma unroll 8
        for (int c2 = 0; c2 < 64; c2++) {
            float v = tileF[(half*64 + c2)*TFS + j];
            s += v; sq += v*v;
        }
        psum[half*128 + j] = s;
        psq [half*128 + j] = sq;
        __syncthreads();
        float st  = psum[j] + psum[128 + j];
        float sqt = psq [j] + psq [128 + j];
        float m  = st * (1.f/CZ);
        float vv = sqt * (1.f/CZ) - m*m;
        float rs = rsqrtf(vv + 1e-5f);
        // write normalized fp16 into A row j (cols half*64..half*64+63)
#pragma unroll 8
        for (int c2 = 0; c2 < 32; c2++) {
            int c = half*64 + c2*2;
            float v0 = tileF[c*TFS + j];
            float v1 = tileF[(c+1)*TFS + j];
            float y0 = (v0 - m)*rs*__ldg(cnw + c)     + __ldg(cnb + c);
            float y1 = (v1 - m)*rs*__ldg(cnw + c + 1) + __ldg(cnb + c + 1);
            *(__half2*)(sb + AHI + j*ARS + c*2) = __floats2half2_rn(y0, y1);
        }
    }
    __syncthreads();                       // A complete; tileF now dead

    load_wpair(640, 704, tid, sb);         // overwrites tileF region
    __syncthreads();

    int wm = wid & 3, wn = wid >> 2;
    int RM = wm*32, RNl = wn*32;
    int rr = lane >> 2, cp = (lane & 3)*2;

    uint32_t aOff[2], bOff[2], bOffP[2];
#pragma unroll
    for (int fm = 0; fm < 2; fm++)
        aOff[fm] = (uint32_t)((RM + fm*16 + (lane & 15))*ARS + (lane >> 4)*16);
#pragma unroll
    for (int fp = 0; fp < 2; fp++) {
        bOff[fp]  = (uint32_t)((RNl + fp*16 + ((lane >> 4) << 3) + (lane & 7))*BRS
                               + ((lane >> 3) & 1)*16);
        bOffP[fp] = bOff[fp] + 64*BRS;
    }

    float acc[2][4][4];
    for (int nt = 0; nt < 2; nt++) {
        mma_tile2(sbase, aOff, nt ? bOffP : bOff, acc);
#pragma unroll
        for (int fm = 0; fm < 2; fm++) {
            int rowA = RM + fm*16 + rr;
#pragma unroll
            for (int fn = 0; fn < 4; fn++) {
                int c0 = nt*64 + RNl + fn*8 + cp;
                float2 obv = *(const float2*)(ob + c0);
                float2 glA = *(const float2*)(g_glsig + (size_t)(r0 + rowA)*CZ + c0);
                float2 glB = *(const float2*)(g_glsig + (size_t)(r0 + rowA + 8)*CZ + c0);
                float2 vA = { (acc[fm][fn][0] + obv.x)*glA.x,
                              (acc[fm][fn][1] + obv.y)*glA.y };
                float2 vB = { (acc[fm][fn][2] + obv.x)*glB.x,
                              (acc[fm][fn][3] + obv.y)*glB.y };
                *(float2*)(out + (size_t)(r0 + rowA)*CZ + c0)     = vA;
                *(float2*)(out + (size_t)(r0 + rowA + 8)*CZ + c0) = vB;
            }
        }
    }
}

// ---------------- launch ----------------------------------------------------
extern "C" void kernel_launch(void* const* d_in, const int* in_sizes, int n_in,
                              void* d_out, int out_size)
{
    const float* act = (const float*)d_in[0];
    const float* mask= (const float*)d_in[1];
    const float* lnw = (const float*)d_in[2];
    const float* lnb = (const float*)d_in[3];
    const float* pw  = (const float*)d_in[4];
    const float* pb  = (const float*)d_in[5];
    const float* gw  = (const float*)d_in[6];
    const float* gb  = (const float*)d_in[7];
    const float* cnw = (const float*)d_in[8];
    const float* cnb = (const float*)d_in[9];
    const float* ow  = (const float*)d_in[10];
    const float* ob  = (const float*)d_in[11];
    const float* glw = (const float*)d_in[12];
    const float* glb = (const float*)d_in[13];
    float* out = (float*)d_out;

    cudaFuncSetAttribute(k1,  cudaFuncAttributeMaxDynamicSharedMemorySize, SMEM13);
    cudaFuncSetAttribute(k3f, cudaFuncAttributeMaxDynamicSharedMemorySize, SMEM_K3);
    cudaFuncSetAttribute(k2,  cudaFuncAttributeMaxDynamicSharedMemorySize, SMEM_K2);

    wsplit<<<384, 256>>>(pw, gw, glw, ow);
    k1<<<NROW/128, 256, SMEM13>>>(act, mask, lnw, lnb, pb, gb, glb);
    k2<<<dim3(16, CZ), 256, SMEM_K2>>>();
    k3f<<<NROW/128, 256, SMEM_K3>>>(out, cnw, cnb, ob);
}

// round 8
// speedup vs baseline: 5.8943x; 1.0850x over previous
#include <cuda_runtime.h>
#include <cuda_fp16.h>
#include <math.h>
#include <stdint.h>

#define NN 512
#define CZ 128
#define NROW (NN*NN)          // 262144 rows

// ---------------- scratch (static device globals) ---------------------------
__device__ __half g_LThi[(size_t)CZ*NROW];  // [c][i*512+k] fp16 (quantized side)
__device__ __half g_RThi[(size_t)CZ*NROW];  // [c][j*512+k] fp16 hi
__device__ __half g_RTlo[(size_t)CZ*NROW];  // [c][j*512+k] fp16 lo
__device__ __half g_glsig[(size_t)NROW*CZ]; // fp16, row-major (r, c)
__device__ float  g_einT [(size_t)CZ*NROW]; // [c][i*512+j]
// weights fp16 hi/lo, [n][k]: rows 0-255 gate, 256-511 proj, 512-639 gl, 640-767 outp
__device__ __half g_Whi[768*128];
__device__ __half g_Wlo[768*128];

// ======================= PTX helpers (sm_103-safe) ==========================
__device__ __forceinline__ uint32_t smem_u32(const void* p) {
    uint32_t a;
    asm("{ .reg .u64 t; cvta.to.shared.u64 t, %1; cvt.u32.u64 %0, t; }" : "=r"(a) : "l"(p));
    return a;
}
__device__ __forceinline__ void ldsm4(uint32_t r[4], uint32_t addr) {
    asm volatile("ldmatrix.sync.aligned.m8n8.x4.shared.b16 {%0,%1,%2,%3}, [%4];"
        : "=r"(r[0]), "=r"(r[1]), "=r"(r[2]), "=r"(r[3]) : "r"(addr));
}
__device__ __forceinline__ void mma16816(float c[4], const uint32_t a[4],
                                         uint32_t b0, uint32_t b1) {
    asm volatile("mma.sync.aligned.m16n8k16.row.col.f32.f16.f16.f32 "
        "{%0,%1,%2,%3}, {%4,%5,%6,%7}, {%8,%9}, {%0,%1,%2,%3};"
        : "+f"(c[0]), "+f"(c[1]), "+f"(c[2]), "+f"(c[3])
        : "r"(a[0]), "r"(a[1]), "r"(a[2]), "r"(a[3]), "r"(b0), "r"(b1));
}
__device__ __forceinline__ void cp16(uint32_t dst, const void* src) {
    asm volatile("cp.async.cg.shared.global [%0], [%1], 16;" :: "r"(dst), "l"(src));
}
#define CP_COMMIT() asm volatile("cp.async.commit_group;" ::: "memory")
__device__ __forceinline__ float sigf(float x) { return 1.f/(1.f + expf(-x)); }

// ---------------- K0: split weights into fp16 hi/lo -------------------------
__global__ void wsplit(const float* __restrict__ pw, const float* __restrict__ gw,
                       const float* __restrict__ glw, const float* __restrict__ ow)
{
    int idx = blockIdx.x*256 + threadIdx.x;   // 384*256 = 98304 = 768*128
    int row = idx >> 7;
    float v;
    if      (row < 256) v = gw [idx];
    else if (row < 512) v = pw [idx - 256*128];
    else if (row < 640) v = glw[idx - 512*128];
    else                v = ow [idx - 640*128];
    __half h = __float2half_rn(v);
    g_Whi[idx] = h;
    g_Wlo[idx] = __float2half_rn(v - __half2float(h));
}

// =================== mma-based LN+GEMM machinery (k1/k3) ====================
#define ARS    272                 // A row stride  (128 fp16 = 256B + pad)
#define BRS    272
#define AHI    0                   // A: 128*272 = 34816
#define BHI    34816               // B hi: 128 rows
#define BLO    69632               // B lo
// staging (k1) REUSES the BHI region after proj mma has consumed the weights
#define STHI   34816               // 128 x 64 fp16, stride 136 -> 17408
#define STLO   52224
#define SSTR   136
#define SMEM13 104448              // <= 116224 -> 2 blocks/SM
// k3f extra: fp32 einT tile + LN partials
#define TILEF  34816               // 128 x 132 fp32 = 67584, inside B region
#define TFS    132
#define PSUM   104448              // 256 floats
#define PSQ    105472              // 256 floats
#define SMEM_K3 106496

// LN 128 rows of src -> fp16 A tile in smem (row-major [row][k]), single comp
__device__ __forceinline__ void ln_quant(const float* __restrict__ src,
                                         const float* __restrict__ w,
                                         const float* __restrict__ b,
                                         int r0, int tid, char* sb)
{
    int wid = tid >> 5, lane = tid & 31;
    float4 wv = *(const float4*)(w + lane*4);
    float4 bv = *(const float4*)(b + lane*4);
#pragma unroll
    for (int q = 0; q < 16; q++) {
        int row = wid*16 + q;
        float4 x = *(const float4*)(src + (size_t)(r0+row)*CZ + lane*4);
        float s  = x.x+x.y+x.z+x.w;
        float sq = x.x*x.x + x.y*x.y + x.z*x.z + x.w*x.w;
#pragma unroll
        for (int o = 16; o > 0; o >>= 1) {
            s  += __shfl_xor_sync(0xffffffffu, s,  o);
            sq += __shfl_xor_sync(0xffffffffu, sq, o);
        }
        float m  = s * (1.f/CZ);
        float v  = sq * (1.f/CZ) - m*m;
        float rs = rsqrtf(v + 1e-5f);
        float y0 = (x.x-m)*rs*wv.x + bv.x;
        float y1 = (x.y-m)*rs*wv.y + bv.y;
        float y2 = (x.z-m)*rs*wv.z + bv.z;
        float y3 = (x.w-m)*rs*wv.w + bv.w;
        uint32_t off = (uint32_t)(row*ARS + lane*8);
        *(__half2*)(sb + AHI + off)     = __floats2half2_rn(y0, y1);
        *(__half2*)(sb + AHI + off + 4) = __floats2half2_rn(y2, y3);
    }
}

// gate hi -> BHI rows 0-63, proj hi -> BHI rows 64-127, proj lo -> BLO rows 64-127
__device__ __forceinline__ void load_w_gateproj(int nt, int tid, char* sb)
{
#pragma unroll
    for (int q = 0; q < 8; q++) {
        int idx = tid + q*256;          // 0..2047
        int row = idx >> 4, ch = idx & 15;
        int gr = (row < 64) ? (nt*64 + row) : (256 + nt*64 + row - 64);
        *(uint4*)(sb + BHI + row*BRS + ch*16) = *(const uint4*)(g_Whi + (size_t)gr*128 + ch*8);
    }
#pragma unroll
    for (int q = 0; q < 4; q++) {
        int idx = tid + q*256;          // 0..1023
        int row = 64 + (idx >> 4), ch = idx & 15;
        int gr = 256 + nt*64 + (row - 64);
        *(uint4*)(sb + BLO + row*BRS + ch*16) = *(const uint4*)(g_Wlo + (size_t)gr*128 + ch*8);
    }
}

// gl weights: 128 rows hi only -> BHI
__device__ __forceinline__ void load_w_gl(int tid, char* sb)
{
#pragma unroll
    for (int q = 0; q < 8; q++) {
        int idx = tid + q*256;
        int row = idx >> 4, ch = idx & 15;
        *(uint4*)(sb + BHI + row*BRS + ch*16) = *(const uint4*)(g_Whi + (size_t)(512 + row)*128 + ch*8);
    }
}

// outp weights: full hi/lo pair (2-pass)
__device__ __forceinline__ void load_wpair(int rowA0, int rowB0, int tid, char* sb)
{
#pragma unroll
    for (int q = 0; q < 8; q++) {
        int idx = tid + q*256;
        int row = idx >> 4, ch = idx & 15;
        int gr = (row < 64) ? (rowA0 + row) : (rowB0 + row - 64);
        size_t go = (size_t)gr*128 + ch*8;
        uint32_t so = (uint32_t)(row*BRS + ch*16);
        *(uint4*)(sb + BHI + so) = *(const uint4*)(g_Whi + go);
        *(uint4*)(sb + BLO + so) = *(const uint4*)(g_Wlo + go);
    }
}

// M=128 x N=64 x K=128, 2-pass (ah*bh + ah*bl); warp tile 32x32
__device__ __forceinline__ void mma_tile2(uint32_t sbase, const uint32_t aOff[2],
                                          const uint32_t bOff[2], float acc[2][4][4])
{
#pragma unroll
    for (int fm = 0; fm < 2; fm++)
#pragma unroll
        for (int fn = 0; fn < 4; fn++)
#pragma unroll
            for (int e = 0; e < 4; e++) acc[fm][fn][e] = 0.f;
#pragma unroll
    for (int kk = 0; kk < 8; kk++) {
        uint32_t ah[2][4], bh[2][4], bl[2][4];
#pragma unroll
        for (int fm = 0; fm < 2; fm++)
            ldsm4(ah[fm], sbase + AHI + aOff[fm] + kk*32);
#pragma unroll
        for (int fp = 0; fp < 2; fp++) {
            ldsm4(bh[fp], sbase + BHI + bOff[fp] + kk*32);
            ldsm4(bl[fp], sbase + BLO + bOff[fp] + kk*32);
        }
#pragma unroll
        for (int fm = 0; fm < 2; fm++)
#pragma unroll
            for (int fn = 0; fn < 4; fn++) {
                int fp = fn >> 1, s = (fn & 1)*2;
                mma16816(acc[fm][fn], ah[fm], bh[fp][s], bh[fp][s+1]);
                mma16816(acc[fm][fn], ah[fm], bl[fp][s], bl[fp][s+1]);
            }
    }
}

// M=128 x N=64 x K=128, single-pass (hi only) for sigmoid-damped GEMMs
__device__ __forceinline__ void mma_tile1(uint32_t sbase, const uint32_t aOff[2],
                                          const uint32_t bOff[2], float acc[2][4][4])
{
#pragma unroll
    for (int fm = 0; fm < 2; fm++)
#pragma unroll
        for (int fn = 0; fn < 4; fn++)
#pragma unroll
            for (int e = 0; e < 4; e++) acc[fm][fn][e] = 0.f;
#pragma unroll
    for (int kk = 0; kk < 8; kk++) {
        uint32_t ah[2][4], bh[2][4];
#pragma unroll
        for (int fm = 0; fm < 2; fm++)
            ldsm4(ah[fm], sbase + AHI + aOff[fm] + kk*32);
#pragma unroll
        for (int fp = 0; fp < 2; fp++)
            ldsm4(bh[fp], sbase + BHI + bOff[fp] + kk*32);
#pragma unroll
        for (int fm = 0; fm < 2; fm++)
#pragma unroll
            for (int fn = 0; fn < 4; fn++) {
                int fp = fn >> 1, s = (fn & 1)*2;
                mma16816(acc[fm][fn], ah[fm], bh[fp][s], bh[fp][s+1]);
            }
    }
}

// ---------------- K1: LN + gate/proj/gl, writes split-transposed L/R --------
__global__ __launch_bounds__(256, 2) void k1(const float* __restrict__ act,
                                             const float* __restrict__ mask,
                                             const float* __restrict__ lnw,
                                             const float* __restrict__ lnb,
                                             const float* __restrict__ pb,
                                             const float* __restrict__ gb,
                                             const float* __restrict__ glb)
{
    extern __shared__ char sb[];
    uint32_t sbase = smem_u32(sb);
    int tid = threadIdx.x, wid = tid >> 5, lane = tid & 31;
    int r0 = blockIdx.x * 128;
    int wm = wid & 3, wn = wid >> 2;
    int RM = wm*32, RNl = wn*32;
    int rr = lane >> 2, cp = (lane & 3)*2;

    uint32_t aOff[2], bOff[2], bOffP[2];
#pragma unroll
    for (int fm = 0; fm < 2; fm++)
        aOff[fm] = (uint32_t)((RM + fm*16 + (lane & 15))*ARS + (lane >> 4)*16);
#pragma unroll
    for (int fp = 0; fp < 2; fp++) {
        bOff[fp]  = (uint32_t)((RNl + fp*16 + ((lane >> 4) << 3) + (lane & 7))*BRS
                               + ((lane >> 3) & 1)*16);
        bOffP[fp] = bOff[fp] + 64*BRS;
    }

    ln_quant(act, lnw, lnb, r0, tid, sb);

    float acc[2][4][4], sig[2][4][4];

    // ---- 4 tiles of 64 cols: gate (1-pass) + proj (2-pass); staging reuses B
    for (int nt = 0; nt < 4; nt++) {
        load_w_gateproj(nt, tid, sb);              // gate hi | proj hi+lo
        __syncthreads();                           // B (and A on nt=0) visible
        mma_tile1(sbase, aOff, bOff, acc);         // gate, single-pass
#pragma unroll
        for (int fm = 0; fm < 2; fm++)
#pragma unroll
            for (int fn = 0; fn < 4; fn++) {
                int c0 = nt*64 + RNl + fn*8 + cp;
                float2 gbv = *(const float2*)(gb + c0);
                sig[fm][fn][0] = sigf(acc[fm][fn][0] + gbv.x);
                sig[fm][fn][1] = sigf(acc[fm][fn][1] + gbv.y);
                sig[fm][fn][2] = sigf(acc[fm][fn][2] + gbv.x);
                sig[fm][fn][3] = sigf(acc[fm][fn][3] + gbv.y);
            }
        mma_tile2(sbase, aOff, bOffP, acc);        // proj, 2-pass
        __syncthreads();                           // everyone done reading B
#pragma unroll
        for (int fm = 0; fm < 2; fm++) {
            int rowA = RM + fm*16 + rr;
            float mkA = mask[r0 + rowA];
            float mkB = mask[r0 + rowA + 8];
#pragma unroll
            for (int fn = 0; fn < 4; fn++) {
                int cl = RNl + fn*8 + cp;
                float2 pbv = *(const float2*)(pb + nt*64 + cl);
                float vA0 = mkA*(acc[fm][fn][0] + pbv.x)*sig[fm][fn][0];
                float vA1 = mkA*(acc[fm][fn][1] + pbv.y)*sig[fm][fn][1];
                float vB0 = mkB*(acc[fm][fn][2] + pbv.x)*sig[fm][fn][2];
                float vB1 = mkB*(acc[fm][fn][3] + pbv.y)*sig[fm][fn][3];
                __half2 hA = __floats2half2_rn(vA0, vA1);
                __half2 hB = __floats2half2_rn(vB0, vB1);
                __half2 lA = __floats2half2_rn(vA0 - __half2float(__low2half(hA)),
                                               vA1 - __half2float(__high2half(hA)));
                __half2 lB = __floats2half2_rn(vB0 - __half2float(__low2half(hB)),
                                               vB1 - __half2float(__high2half(hB)));
                uint32_t oA = (uint32_t)(rowA*SSTR + cl*2);
                uint32_t oB = oA + 8*SSTR;
                *(__half2*)(sb + STHI + oA) = hA;
                *(__half2*)(sb + STHI + oB) = hB;
                *(__half2*)(sb + STLO + oA) = lA;
                *(__half2*)(sb + STLO + oB) = lB;
            }
        }
        __syncthreads();                           // staging writes complete
        {
            int cl = tid >> 2, rs = (tid & 3)*32;
            size_t go;
            uint32_t h[16];
#pragma unroll
            for (int r = 0; r < 16; r++) {
                uint32_t o0 = (uint32_t)((rs + 2*r)*SSTR + cl*2);
                uint32_t o1 = o0 + SSTR;
                h[r] = (uint32_t)*(const unsigned short*)(sb + STHI + o0)
                     | ((uint32_t)*(const unsigned short*)(sb + STHI + o1) << 16);
            }
            if (nt < 2) {                          // left: quantized side, hi only
                go = (size_t)((nt & 1)*64 + cl)*NROW + r0 + rs;
#pragma unroll
                for (int s = 0; s < 4; s++)
                    *(uint4*)(g_LThi + go + s*8) = make_uint4(h[s*4], h[s*4+1], h[s*4+2], h[s*4+3]);
            } else {                               // right: hi + lo
                uint32_t l[16];
#pragma unroll
                for (int r = 0; r < 16; r++) {
                    uint32_t o0 = (uint32_t)((rs + 2*r)*SSTR + cl*2);
                    uint32_t o1 = o0 + SSTR;
                    l[r] = (uint32_t)*(const unsigned short*)(sb + STLO + o0)
                         | ((uint32_t)*(const unsigned short*)(sb + STLO + o1) << 16);
                }
                go = (size_t)((nt & 1)*64 + cl)*NROW + r0 + rs;
#pragma unroll
                for (int s = 0; s < 4; s++) {
                    *(uint4*)(g_RThi + go + s*8) = make_uint4(h[s*4], h[s*4+1], h[s*4+2], h[s*4+3]);
                    *(uint4*)(g_RTlo + go + s*8) = make_uint4(l[s*4], l[s*4+1], l[s*4+2], l[s*4+3]);
                }
            }
        }
        __syncthreads();                           // staging reads done before next load
    }

    // ---- gl gate: single-pass, hi-only weights ----
    load_w_gl(tid, sb);
    __syncthreads();
    for (int nt = 0; nt < 2; nt++) {
        mma_tile1(sbase, aOff, nt ? bOffP : bOff, acc);
#pragma unroll
        for (int fm = 0; fm < 2; fm++) {
            int rowA = RM + fm*16 + rr;
#pragma unroll
            for (int fn = 0; fn < 4; fn++) {
                int c0 = nt*64 + RNl + fn*8 + cp;
                float2 bv = *(const float2*)(glb + c0);
                *(__half2*)(g_glsig + (size_t)(r0 + rowA)*CZ + c0) =
                    __floats2half2_rn(sigf(acc[fm][fn][0] + bv.x), sigf(acc[fm][fn][1] + bv.y));
                *(__half2*)(g_glsig + (size_t)(r0 + rowA + 8)*CZ + c0) =
                    __floats2half2_rn(sigf(acc[fm][fn][2] + bv.x), sigf(acc[fm][fn][3] + bv.y));
            }
        }
    }
}

// ---------------- K2: fp16 asym 2-pass GEMM, cp.async 3-stage, 2 blocks/SM --
#define RSTRIDE 80
#define KCOMP   (128*RSTRIDE)       // 10240
#define ST_A    0
#define ST_BH   KCOMP
#define ST_BL   (2*KCOMP)
#define STAGE   (3*KCOMP)           // 30720
#define SMEM_K2 (3*STAGE)           // 92160 <= 116224 -> 2 blocks/SM

__device__ __forceinline__ void k2_compute(uint32_t sbk, const uint32_t aOff[2],
                                           const uint32_t bOff[4], float acc[2][8][4])
{
#pragma unroll
    for (int kk = 0; kk < 2; kk++) {
        uint32_t ah[2][4], bh[4][4], bl[4][4];
#pragma unroll
        for (int fm = 0; fm < 2; fm++)
            ldsm4(ah[fm], sbk + ST_A + aOff[fm] + kk*32);
#pragma unroll
        for (int fp = 0; fp < 4; fp++) {
            ldsm4(bh[fp], sbk + ST_BH + bOff[fp] + kk*32);
            ldsm4(bl[fp], sbk + ST_BL + bOff[fp] + kk*32);
        }
#pragma unroll
        for (int fm = 0; fm < 2; fm++)
#pragma unroll
            for (int fn = 0; fn < 8; fn++) {
                int fp = fn >> 1, s = (fn & 1)*2;
                mma16816(acc[fm][fn], ah[fm], bh[fp][s], bh[fp][s+1]);
                mma16816(acc[fm][fn], ah[fm], bl[fp][s], bl[fp][s+1]);
            }
    }
}

__device__ __forceinline__ void k2_copy(uint32_t st,
                                        const __half* Ah, const __half* Bh,
                                        const __half* Bl, int k0, int lr, int lkg)
{
#pragma unroll
    for (int q = 0; q < 2; q++) {
        int r = lr + q*64;
        size_t go = (size_t)r*NN + k0 + lkg*8;
        uint32_t so = (uint32_t)(r*RSTRIDE + lkg*16);
        cp16(st + ST_A  + so, Ah + go);
        cp16(st + ST_BH + so, Bh + go);
        cp16(st + ST_BL + so, Bl + go);
    }
}

__global__ __launch_bounds__(256, 2) void k2()
{
    extern __shared__ char sb[];
    uint32_t sbase = smem_u32(sb);
    int tid = threadIdx.x, wid = tid >> 5, lane = tid & 31;
    int c  = blockIdx.y;
    int ti = blockIdx.x >> 2, tj = blockIdx.x & 3;

    const __half* Ah = g_LThi + (size_t)c*NROW + (size_t)ti*128*NN;
    const __half* Bh = g_RThi + (size_t)c*NROW + (size_t)tj*128*NN;
    const __half* Bl = g_RTlo + (size_t)c*NROW + (size_t)tj*128*NN;
    float* C = g_einT + (size_t)c*NROW + (size_t)(ti*128)*NN + tj*128;

    int wm = wid & 3, wn = wid >> 2;
    int RM = wm*32, RN = wn*64;

    uint32_t aOff[2], bOff[4];
#pragma unroll
    for (int fm = 0; fm < 2; fm++)
        aOff[fm] = (uint32_t)((RM + fm*16 + (lane & 15))*RSTRIDE + (lane >> 4)*16);
#pragma unroll
    for (int fp = 0; fp < 4; fp++)
        bOff[fp] = (uint32_t)((RN + fp*16 + ((lane >> 4) << 3) + (lane & 7))*RSTRIDE
                              + ((lane >> 3) & 1)*16);

    int lr  = tid >> 2;
    int lkg = tid & 3;

    float acc[2][8][4];
#pragma unroll
    for (int fm = 0; fm < 2; fm++)
#pragma unroll
        for (int fn = 0; fn < 8; fn++)
#pragma unroll
            for (int e = 0; e < 4; e++) acc[fm][fn][e] = 0.f;

    // prologue: tiles 0,1 in flight
    k2_copy(sbase + 0*STAGE, Ah, Bh, Bl, 0,  lr, lkg); CP_COMMIT();
    k2_copy(sbase + 1*STAGE, Ah, Bh, Bl, 32, lr, lkg); CP_COMMIT();

    for (int t = 0; t < 16; t++) {
        if (t < 15) asm volatile("cp.async.wait_group 1;" ::: "memory");
        else        asm volatile("cp.async.wait_group 0;" ::: "memory");
        __syncthreads();                 // tile t visible; all warps past compute(t-1)
        if (t + 2 < 16) {
            k2_copy(sbase + ((t+2)%3)*STAGE, Ah, Bh, Bl, (t+2)*32, lr, lkg);
            CP_COMMIT();
        }
        k2_compute(sbase + (t%3)*STAGE, aOff, bOff, acc);
    }

    int rr = lane >> 2, cp = (lane & 3)*2;
#pragma unroll
    for (int fm = 0; fm < 2; fm++)
#pragma unroll
        for (int fn = 0; fn < 8; fn++) {
            int row = RM + fm*16 + rr;
            int col = RN + fn*8 + cp;
            float2 v0 = { acc[fm][fn][0], acc[fm][fn][1] };
            float2 v1 = { acc[fm][fn][2], acc[fm][fn][3] };
            *(float2*)(C + (size_t)row*NN + col)     = v0;
            *(float2*)(C + (size_t)(row+8)*NN + col) = v1;
        }
}

// ---------------- K3f: einT tile load + transpose-LN + outp GEMM + gl -------
__global__ __launch_bounds__(256, 2) void k3f(float* __restrict__ out,
                                              const float* __restrict__ cnw,
                                              const float* __restrict__ cnb,
                                              const float* __restrict__ ob)
{
    extern __shared__ char sb[];
    uint32_t sbase = smem_u32(sb);
    float* tileF = (float*)(sb + TILEF);
    float* psum  = (float*)(sb + PSUM);
    float* psq   = (float*)(sb + PSQ);
    int tid = threadIdx.x, wid = tid >> 5, lane = tid & 31;
    int r0 = blockIdx.x * 128;         // = i*512 + jbase

    // ---- load 128(c) x 128(j) fp32 tile of g_einT, coalesced ----
#pragma unroll
    for (int q = 0; q < 16; q++) {
        int idx = tid + q*256;             // float4 index, 4096 total
        int c = idx >> 5, col4 = idx & 31;
        float4 v = *(const float4*)(g_einT + (size_t)c*NROW + r0 + col4*4);
        *(float4*)(tileF + c*TFS + col4*4) = v;
    }
    __syncthreads();

    // ---- LN over c for each j (column reads, conflict-free) ----
    {
        int half = tid >> 7, j = tid & 127;
        float s = 0.f, sq = 0.f;
#pragma unroll 8
        for (int c2 = 0; c2 < 64; c2++) {
            float v = tileF[(half*64 + c2)*TFS + j];
            s += v; sq += v*v;
        }
        psum[half*128 + j] = s;
        psq [half*128 + j] = sq;
        __syncthreads();
        float st  = psum[j] + psum[128 + j];
        float sqt = psq [j] + psq [128 + j];
        float m  = st * (1.f/CZ);
        float vv = sqt * (1.f/CZ) - m*m;
        float rs = rsqrtf(vv + 1e-5f);
#pragma unroll 8
        for (int c2 = 0; c2 < 32; c2++) {
            int c = half*64 + c2*2;
            float v0 = tileF[c*TFS + j];
            float v1 = tileF[(c+1)*TFS + j];
            float y0 = (v0 - m)*rs*__ldg(cnw + c)     + __ldg(cnb + c);
            float y1 = (v1 - m)*rs*__ldg(cnw + c + 1) + __ldg(cnb + c + 1);
            *(__half2*)(sb + AHI + j*ARS + c*2) = __floats2half2_rn(y0, y1);
        }
    }
    __syncthreads();                       // A complete; tileF now dead

    load_wpair(640, 704, tid, sb);         // outp hi/lo, overwrites tileF region
    __syncthreads();

    int wm = wid & 3, wn = wid >> 2;
    int RM = wm*32, RNl = wn*32;
    int rr = lane >> 2, cp = (lane & 3)*2;

    uint32_t aOff[2], bOff[2], bOffP[2];
#pragma unroll
    for (int fm = 0; fm < 2; fm++)
        aOff[fm] = (uint32_t)((RM + fm*16 + (lane & 15))*ARS + (lane >> 4)*16);
#pragma unroll
    for (int fp = 0; fp < 2; fp++) {
        bOff[fp]  = (uint32_t)((RNl + fp*16 + ((lane >> 4) << 3) + (lane & 7))*BRS
                               + ((lane >> 3) & 1)*16);
        bOffP[fp] = bOff[fp] + 64*BRS;
    }

    float acc[2][4][4];
    for (int nt = 0; nt < 2; nt++) {
        mma_tile2(sbase, aOff, nt ? bOffP : bOff, acc);
#pragma unroll
        for (int fm = 0; fm < 2; fm++) {
            int rowA = RM + fm*16 + rr;
#pragma unroll
            for (int fn = 0; fn < 4; fn++) {
                int c0 = nt*64 + RNl + fn*8 + cp;
                float2 obv = *(const float2*)(ob + c0);
                float2 glA = __half22float2(*(const __half2*)(g_glsig + (size_t)(r0 + rowA)*CZ + c0));
                float2 glB = __half22float2(*(const __half2*)(g_glsig + (size_t)(r0 + rowA + 8)*CZ + c0));
                float2 vA = { (acc[fm][fn][0] + obv.x)*glA.x,
                              (acc[fm][fn][1] + obv.y)*glA.y };
                float2 vB = { (acc[fm][fn][2] + obv.x)*glB.x,
                              (acc[fm][fn][3] + obv.y)*glB.y };
                *(float2*)(out + (size_t)(r0 + rowA)*CZ + c0)     = vA;
                *(float2*)(out + (size_t)(r0 + rowA + 8)*CZ + c0) = vB;
            }
        }
    }
}

// ---------------- launch ----------------------------------------------------
extern "C" void kernel_launch(void* const* d_in, const int* in_sizes, int n_in,
                              void* d_out, int out_size)
{
    const float* act = (const float*)d_in[0];
    const float* mask= (const float*)d_in[1];
    const float* lnw = (const float*)d_in[2];
    const float* lnb = (const float*)d_in[3];
    const float* pw  = (const float*)d_in[4];
    const float* pb  = (const float*)d_in[5];
    const float* gw  = (const float*)d_in[6];
    const float* gb  = (const float*)d_in[7];
    const float* cnw = (const float*)d_in[8];
    const float* cnb = (const float*)d_in[9];
    const float* ow  = (const float*)d_in[10];
    const float* ob  = (const float*)d_in[11];
    const float* glw = (const float*)d_in[12];
    const float* glb = (const float*)d_in[13];
    float* out = (float*)d_out;

    cudaFuncSetAttribute(k1,  cudaFuncAttributeMaxDynamicSharedMemorySize, SMEM13);
    cudaFuncSetAttribute(k3f, cudaFuncAttributeMaxDynamicSharedMemorySize, SMEM_K3);
    cudaFuncSetAttribute(k2,  cudaFuncAttributeMaxDynamicSharedMemorySize, SMEM_K2);

    wsplit<<<384, 256>>>(pw, gw, glw, ow);
    k1<<<NROW/128, 256, SMEM13>>>(act, mask, lnw, lnb, pb, gb, glb);
    k2<<<dim3(16, CZ), 256, SMEM_K2>>>();
    k3f<<<NROW/128, 256, SMEM_K3>>>(out, cnw, cnb, ob);
}

// round 9
// speedup vs baseline: 8.1725x; 1.3865x over previous
#include <cuda_runtime.h>
#include <cuda_fp16.h>
#include <math.h>
#include <stdint.h>

#define NN 512
#define CZ 128
#define NROW (NN*NN)          // 262144 rows

// ---------------- scratch (static device globals) ---------------------------
__device__ __half g_LThi[(size_t)CZ*NROW];  // [c][i*512+k] fp16
__device__ __half g_RThi[(size_t)CZ*NROW];  // [c][j*512+k] fp16
__device__ __half g_glsig[(size_t)NROW*CZ]; // fp16, row-major (r, c)
__device__ __half g_einH [(size_t)CZ*NROW]; // [c][i*512+j] fp16
// weights fp16 hi/lo, [n][k]: rows 0-255 gate, 256-511 proj, 512-639 gl, 640-767 outp
__device__ __half g_Whi[768*128];
__device__ __half g_Wlo[768*128];

// ======================= PTX helpers (sm_103-safe) ==========================
__device__ __forceinline__ uint32_t smem_u32(const void* p) {
    uint32_t a;
    asm("{ .reg .u64 t; cvta.to.shared.u64 t, %1; cvt.u32.u64 %0, t; }" : "=r"(a) : "l"(p));
    return a;
}
__device__ __forceinline__ void ldsm4(uint32_t r[4], uint32_t addr) {
    asm volatile("ldmatrix.sync.aligned.m8n8.x4.shared.b16 {%0,%1,%2,%3}, [%4];"
        : "=r"(r[0]), "=r"(r[1]), "=r"(r[2]), "=r"(r[3]) : "r"(addr));
}
__device__ __forceinline__ void mma16816(float c[4], const uint32_t a[4],
                                         uint32_t b0, uint32_t b1) {
    asm volatile("mma.sync.aligned.m16n8k16.row.col.f32.f16.f16.f32 "
        "{%0,%1,%2,%3}, {%4,%5,%6,%7}, {%8,%9}, {%0,%1,%2,%3};"
        : "+f"(c[0]), "+f"(c[1]), "+f"(c[2]), "+f"(c[3])
        : "r"(a[0]), "r"(a[1]), "r"(a[2]), "r"(a[3]), "r"(b0), "r"(b1));
}
__device__ __forceinline__ void cp16(uint32_t dst, const void* src) {
    asm volatile("cp.async.cg.shared.global [%0], [%1], 16;" :: "r"(dst), "l"(src));
}
#define CP_COMMIT() asm volatile("cp.async.commit_group;" ::: "memory")
__device__ __forceinline__ float sigf(float x) { return 1.f/(1.f + expf(-x)); }

// ---------------- K0: split weights into fp16 hi/lo -------------------------
__global__ void wsplit(const float* __restrict__ pw, const float* __restrict__ gw,
                       const float* __restrict__ glw, const float* __restrict__ ow)
{
    int idx = blockIdx.x*256 + threadIdx.x;   // 384*256 = 98304 = 768*128
    int row = idx >> 7;
    float v;
    if      (row < 256) v = gw [idx];
    else if (row < 512) v = pw [idx - 256*128];
    else if (row < 640) v = glw[idx - 512*128];
    else                v = ow [idx - 640*128];
    __half h = __float2half_rn(v);
    g_Whi[idx] = h;
    g_Wlo[idx] = __float2half_rn(v - __half2float(h));
}

// =================== mma-based LN+GEMM machinery (k1/k3) ====================
#define ARS    272                 // A row stride  (128 fp16 = 256B + pad)
#define BRS    272
#define AHI    0                   // A: 128*272 = 34816
#define BHI    34816               // B hi: 128 rows
#define STK1   69632               // k1 staging 128 x 64 fp16, stride 136
#define SSTR   136
#define SMEM13 87040               // k1: A + Bhi + staging; 2 blocks/SM
// k3f layout: A + tileH(=BHI region) + BLO + partials
#define BLO    69632
#define TFSH   136                 // half stride of einH tile (272 B rows)
#define PSUM   104448              // 256 floats
#define PSQ    105472
#define SMEM_K3 106496

// LN 128 rows of src -> fp16 A tile in smem (row-major [row][k])
__device__ __forceinline__ void ln_quant(const float* __restrict__ src,
                                         const float* __restrict__ w,
                                         const float* __restrict__ b,
                                         int r0, int tid, char* sb)
{
    int wid = tid >> 5, lane = tid & 31;
    float4 wv = *(const float4*)(w + lane*4);
    float4 bv = *(const float4*)(b + lane*4);
#pragma unroll
    for (int q = 0; q < 16; q++) {
        int row = wid*16 + q;
        float4 x = *(const float4*)(src + (size_t)(r0+row)*CZ + lane*4);
        float s  = x.x+x.y+x.z+x.w;
        float sq = x.x*x.x + x.y*x.y + x.z*x.z + x.w*x.w;
#pragma unroll
        for (int o = 16; o > 0; o >>= 1) {
            s  += __shfl_xor_sync(0xffffffffu, s,  o);
            sq += __shfl_xor_sync(0xffffffffu, sq, o);
        }
        float m  = s * (1.f/CZ);
        float v  = sq * (1.f/CZ) - m*m;
        float rs = rsqrtf(v + 1e-5f);
        float y0 = (x.x-m)*rs*wv.x + bv.x;
        float y1 = (x.y-m)*rs*wv.y + bv.y;
        float y2 = (x.z-m)*rs*wv.z + bv.z;
        float y3 = (x.w-m)*rs*wv.w + bv.w;
        uint32_t off = (uint32_t)(row*ARS + lane*8);
        *(__half2*)(sb + AHI + off)     = __floats2half2_rn(y0, y1);
        *(__half2*)(sb + AHI + off + 4) = __floats2half2_rn(y2, y3);
    }
}

// gate hi rows 0-63 | proj hi rows 64-127 -> BHI (hi only, single-pass)
__device__ __forceinline__ void load_w_gp(int nt, int tid, char* sb)
{
#pragma unroll
    for (int q = 0; q < 8; q++) {
        int idx = tid + q*256;
        int row = idx >> 4, ch = idx & 15;
        int gr = (row < 64) ? (nt*64 + row) : (256 + nt*64 + row - 64);
        *(uint4*)(sb + BHI + row*BRS + ch*16) = *(const uint4*)(g_Whi + (size_t)gr*128 + ch*8);
    }
}

// gl weights: 128 rows hi only -> BHI
__device__ __forceinline__ void load_w_gl(int tid, char* sb)
{
#pragma unroll
    for (int q = 0; q < 8; q++) {
        int idx = tid + q*256;
        int row = idx >> 4, ch = idx & 15;
        *(uint4*)(sb + BHI + row*BRS + ch*16) = *(const uint4*)(g_Whi + (size_t)(512 + row)*128 + ch*8);
    }
}

// outp weights: full hi/lo pair (2-pass, k3f only)
__device__ __forceinline__ void load_wpair(int rowA0, int rowB0, int tid, char* sb)
{
#pragma unroll
    for (int q = 0; q < 8; q++) {
        int idx = tid + q*256;
        int row = idx >> 4, ch = idx & 15;
        int gr = (row < 64) ? (rowA0 + row) : (rowB0 + row - 64);
        size_t go = (size_t)gr*128 + ch*8;
        uint32_t so = (uint32_t)(row*BRS + ch*16);
        *(uint4*)(sb + BHI + so) = *(const uint4*)(g_Whi + go);
        *(uint4*)(sb + BLO + so) = *(const uint4*)(g_Wlo + go);
    }
}

// M=128 x N=64 x K=128, 2-pass (ah*bh + ah*bl); warp tile 32x32 (k3f outp)
__device__ __forceinline__ void mma_tile2(uint32_t sbase, const uint32_t aOff[2],
                                          const uint32_t bOff[2], float acc[2][4][4])
{
#pragma unroll
    for (int fm = 0; fm < 2; fm++)
#pragma unroll
        for (int fn = 0; fn < 4; fn++)
#pragma unroll
            for (int e = 0; e < 4; e++) acc[fm][fn][e] = 0.f;
#pragma unroll
    for (int kk = 0; kk < 8; kk++) {
        uint32_t ah[2][4], bh[2][4], bl[2][4];
#pragma unroll
        for (int fm = 0; fm < 2; fm++)
            ldsm4(ah[fm], sbase + AHI + aOff[fm] + kk*32);
#pragma unroll
        for (int fp = 0; fp < 2; fp++) {
            ldsm4(bh[fp], sbase + BHI + bOff[fp] + kk*32);
            ldsm4(bl[fp], sbase + BLO + bOff[fp] + kk*32);
        }
#pragma unroll
        for (int fm = 0; fm < 2; fm++)
#pragma unroll
            for (int fn = 0; fn < 4; fn++) {
                int fp = fn >> 1, s = (fn & 1)*2;
                mma16816(acc[fm][fn], ah[fm], bh[fp][s], bh[fp][s+1]);
                mma16816(acc[fm][fn], ah[fm], bl[fp][s], bl[fp][s+1]);
            }
    }
}

// M=128 x N=64 x K=128, single-pass (hi only)
__device__ __forceinline__ void mma_tile1(uint32_t sbase, const uint32_t aOff[2],
                                          const uint32_t bOff[2], float acc[2][4][4])
{
#pragma unroll
    for (int fm = 0; fm < 2; fm++)
#pragma unroll
        for (int fn = 0; fn < 4; fn++)
#pragma unroll
            for (int e = 0; e < 4; e++) acc[fm][fn][e] = 0.f;
#pragma unroll
    for (int kk = 0; kk < 8; kk++) {
        uint32_t ah[2][4], bh[2][4];
#pragma unroll
        for (int fm = 0; fm < 2; fm++)
            ldsm4(ah[fm], sbase + AHI + aOff[fm] + kk*32);
#pragma unroll
        for (int fp = 0; fp < 2; fp++)
            ldsm4(bh[fp], sbase + BHI + bOff[fp] + kk*32);
#pragma unroll
        for (int fm = 0; fm < 2; fm++)
#pragma unroll
            for (int fn = 0; fn < 4; fn++) {
                int fp = fn >> 1, s = (fn & 1)*2;
                mma16816(acc[fm][fn], ah[fm], bh[fp][s], bh[fp][s+1]);
            }
    }
}

// ---------------- K1: LN + gate/proj/gl, single-pass, writes L/R fp16 -------
__global__ __launch_bounds__(256, 2) void k1(const float* __restrict__ act,
                                             const float* __restrict__ mask,
                                             const float* __restrict__ lnw,
                                             const float* __restrict__ lnb,
                                             const float* __restrict__ pb,
                                             const float* __restrict__ gb,
                                             const float* __restrict__ glb)
{
    extern __shared__ char sb[];
    uint32_t sbase = smem_u32(sb);
    int tid = threadIdx.x, wid = tid >> 5, lane = tid & 31;
    int r0 = blockIdx.x * 128;
    int wm = wid & 3, wn = wid >> 2;
    int RM = wm*32, RNl = wn*32;
    int rr = lane >> 2, cp = (lane & 3)*2;

    uint32_t aOff[2], bOff[2], bOffP[2];
#pragma unroll
    for (int fm = 0; fm < 2; fm++)
        aOff[fm] = (uint32_t)((RM + fm*16 + (lane & 15))*ARS + (lane >> 4)*16);
#pragma unroll
    for (int fp = 0; fp < 2; fp++) {
        bOff[fp]  = (uint32_t)((RNl + fp*16 + ((lane >> 4) << 3) + (lane & 7))*BRS
                               + ((lane >> 3) & 1)*16);
        bOffP[fp] = bOff[fp] + 64*BRS;
    }

    ln_quant(act, lnw, lnb, r0, tid, sb);

    float acc[2][4][4], sig[2][4][4];

    // ---- 4 tiles of 64 cols: gate (1-pass) + proj (1-pass) ----
    for (int nt = 0; nt < 4; nt++) {
        load_w_gp(nt, tid, sb);                    // gate hi | proj hi
        __syncthreads();                           // B (and A/staging reads) settled
        mma_tile1(sbase, aOff, bOff, acc);         // gate
#pragma unroll
        for (int fm = 0; fm < 2; fm++)
#pragma unroll
            for (int fn = 0; fn < 4; fn++) {
                int c0 = nt*64 + RNl + fn*8 + cp;
                float2 gbv = *(const float2*)(gb + c0);
                sig[fm][fn][0] = sigf(acc[fm][fn][0] + gbv.x);
                sig[fm][fn][1] = sigf(acc[fm][fn][1] + gbv.y);
                sig[fm][fn][2] = sigf(acc[fm][fn][2] + gbv.x);
                sig[fm][fn][3] = sigf(acc[fm][fn][3] + gbv.y);
            }
        mma_tile1(sbase, aOff, bOffP, acc);        // proj
#pragma unroll
        for (int fm = 0; fm < 2; fm++) {
            int rowA = RM + fm*16 + rr;
            float mkA = mask[r0 + rowA];
            float mkB = mask[r0 + rowA + 8];
#pragma unroll
            for (int fn = 0; fn < 4; fn++) {
                int cl = RNl + fn*8 + cp;
                float2 pbv = *(const float2*)(pb + nt*64 + cl);
                float vA0 = mkA*(acc[fm][fn][0] + pbv.x)*sig[fm][fn][0];
                float vA1 = mkA*(acc[fm][fn][1] + pbv.y)*sig[fm][fn][1];
                float vB0 = mkB*(acc[fm][fn][2] + pbv.x)*sig[fm][fn][2];
                float vB1 = mkB*(acc[fm][fn][3] + pbv.y)*sig[fm][fn][3];
                uint32_t oA = (uint32_t)(rowA*SSTR + cl*2);
                *(__half2*)(sb + STK1 + oA)          = __floats2half2_rn(vA0, vA1);
                *(__half2*)(sb + STK1 + oA + 8*SSTR) = __floats2half2_rn(vB0, vB1);
            }
        }
        __syncthreads();                           // staging visible (mma all done)
        {
            __half* dst = (nt < 2) ? g_LThi : g_RThi;
            int cl = tid >> 2, rs = (tid & 3)*32;
            uint32_t h[16];
#pragma unroll
            for (int r = 0; r < 16; r++) {
                uint32_t o0 = (uint32_t)((rs + 2*r)*SSTR + cl*2);
                h[r] = (uint32_t)*(const unsigned short*)(sb + STK1 + o0)
                     | ((uint32_t)*(const unsigned short*)(sb + STK1 + o0 + SSTR) << 16);
            }
            size_t go = (size_t)((nt & 1)*64 + cl)*NROW + r0 + rs;
#pragma unroll
            for (int s = 0; s < 4; s++)
                *(uint4*)(dst + go + s*8) = make_uint4(h[s*4], h[s*4+1], h[s*4+2], h[s*4+3]);
        }
        // next load_w_gp only touches B; next staging writes gated by its sync
    }

    __syncthreads();                               // staging reads finished

    // ---- gl gate: single-pass ----
    load_w_gl(tid, sb);
    __syncthreads();
    for (int nt = 0; nt < 2; nt++) {
        mma_tile1(sbase, aOff, nt ? bOffP : bOff, acc);
#pragma unroll
        for (int fm = 0; fm < 2; fm++) {
            int rowA = RM + fm*16 + rr;
#pragma unroll
            for (int fn = 0; fn < 4; fn++) {
                int c0 = nt*64 + RNl + fn*8 + cp;
                float2 bv = *(const float2*)(glb + c0);
                *(__half2*)(g_glsig + (size_t)(r0 + rowA)*CZ + c0) =
                    __floats2half2_rn(sigf(acc[fm][fn][0] + bv.x), sigf(acc[fm][fn][1] + bv.y));
                *(__half2*)(g_glsig + (size_t)(r0 + rowA + 8)*CZ + c0) =
                    __floats2half2_rn(sigf(acc[fm][fn][2] + bv.x), sigf(acc[fm][fn][3] + bv.y));
            }
        }
    }
}

// ---------------- K2: fp16 single-pass GEMM, cp.async 3-stage ---------------
#define RSTRIDE 80
#define KCOMP   (128*RSTRIDE)       // 10240
#define ST_A    0
#define ST_BH   KCOMP
#define STAGE   (2*KCOMP)           // 20480
#define SMEM_K2 (3*STAGE)           // 61440 -> 2 blocks/SM

__device__ __forceinline__ void k2_compute(uint32_t sbk, const uint32_t aOff[2],
                                           const uint32_t bOff[4], float acc[2][8][4])
{
#pragma unroll
    for (int kk = 0; kk < 2; kk++) {
        uint32_t ah[2][4], bh[4][4];
#pragma unroll
        for (int fm = 0; fm < 2; fm++)
            ldsm4(ah[fm], sbk + ST_A + aOff[fm] + kk*32);
#pragma unroll
        for (int fp = 0; fp < 4; fp++)
            ldsm4(bh[fp], sbk + ST_BH + bOff[fp] + kk*32);
#pragma unroll
        for (int fm = 0; fm < 2; fm++)
#pragma unroll
            for (int fn = 0; fn < 8; fn++) {
                int fp = fn >> 1, s = (fn & 1)*2;
                mma16816(acc[fm][fn], ah[fm], bh[fp][s], bh[fp][s+1]);
            }
    }
}

__device__ __forceinline__ void k2_copy(uint32_t st, const __half* Ah,
                                        const __half* Bh, int k0, int lr, int lkg)
{
#pragma unroll
    for (int q = 0; q < 2; q++) {
        int r = lr + q*64;
        size_t go = (size_t)r*NN + k0 + lkg*8;
        uint32_t so = (uint32_t)(r*RSTRIDE + lkg*16);
        cp16(st + ST_A  + so, Ah + go);
        cp16(st + ST_BH + so, Bh + go);
    }
}

__global__ __launch_bounds__(256, 2) void k2()
{
    extern __shared__ char sb[];
    uint32_t sbase = smem_u32(sb);
    int tid = threadIdx.x, wid = tid >> 5, lane = tid & 31;
    int c  = blockIdx.y;
    int ti = blockIdx.x >> 2, tj = blockIdx.x & 3;

    const __half* Ah = g_LThi + (size_t)c*NROW + (size_t)ti*128*NN;
    const __half* Bh = g_RThi + (size_t)c*NROW + (size_t)tj*128*NN;
    __half* C = g_einH + (size_t)c*NROW + (size_t)(ti*128)*NN + tj*128;

    int wm = wid & 3, wn = wid >> 2;
    int RM = wm*32, RN = wn*64;

    uint32_t aOff[2], bOff[4];
#pragma unroll
    for (int fm = 0; fm < 2; fm++)
        aOff[fm] = (uint32_t)((RM + fm*16 + (lane & 15))*RSTRIDE + (lane >> 4)*16);
#pragma unroll
    for (int fp = 0; fp < 4; fp++)
        bOff[fp] = (uint32_t)((RN + fp*16 + ((lane >> 4) << 3) + (lane & 7))*RSTRIDE
                              + ((lane >> 3) & 1)*16);

    int lr  = tid >> 2;
    int lkg = tid & 3;

    float acc[2][8][4];
#pragma unroll
    for (int fm = 0; fm < 2; fm++)
#pragma unroll
        for (int fn = 0; fn < 8; fn++)
#pragma unroll
            for (int e = 0; e < 4; e++) acc[fm][fn][e] = 0.f;

    k2_copy(sbase + 0*STAGE, Ah, Bh, 0,  lr, lkg); CP_COMMIT();
    k2_copy(sbase + 1*STAGE, Ah, Bh, 32, lr, lkg); CP_COMMIT();

    for (int t = 0; t < 16; t++) {
        if (t < 15) asm volatile("cp.async.wait_group 1;" ::: "memory");
        else        asm volatile("cp.async.wait_group 0;" ::: "memory");
        __syncthreads();
        if (t + 2 < 16) {
            k2_copy(sbase + ((t+2)%3)*STAGE, Ah, Bh, (t+2)*32, lr, lkg);
            CP_COMMIT();
        }
        k2_compute(sbase + (t%3)*STAGE, aOff, bOff, acc);
    }

    int rr = lane >> 2, cp = (lane & 3)*2;
#pragma unroll
    for (int fm = 0; fm < 2; fm++)
#pragma unroll
        for (int fn = 0; fn < 8; fn++) {
            int row = RM + fm*16 + rr;
            int col = RN + fn*8 + cp;
            *(__half2*)(C + (size_t)row*NN + col) =
                __floats2half2_rn(acc[fm][fn][0], acc[fm][fn][1]);
            *(__half2*)(C + (size_t)(row+8)*NN + col) =
                __floats2half2_rn(acc[fm][fn][2], acc[fm][fn][3]);
        }
}

// ---------------- K3f: einH tile + transpose-LN + outp 2-pass + gl ----------
__global__ __launch_bounds__(256, 2) void k3f(float* __restrict__ out,
                                              const float* __restrict__ cnw,
                                              const float* __restrict__ cnb,
                                              const float* __restrict__ ob)
{
    extern __shared__ char sb[];
    uint32_t sbase = smem_u32(sb);
    __half* tileH = (__half*)(sb + BHI);   // 128 x 136 halves = 34816 B
    float* psum  = (float*)(sb + PSUM);
    float* psq   = (float*)(sb + PSQ);
    int tid = threadIdx.x, wid = tid >> 5, lane = tid & 31;
    int r0 = blockIdx.x * 128;             // = i*512 + jbase

    // ---- load 128(c) x 128(j) fp16 tile of g_einH, coalesced ----
#pragma unroll
    for (int q = 0; q < 8; q++) {
        int idx = tid + q*256;             // uint4 index, 2048 total
        int c = idx >> 4, col8 = idx & 15;
        uint4 v = *(const uint4*)(g_einH + (size_t)c*NROW + r0 + col8*8);
        *(uint4*)((char*)tileH + c*272 + col8*16) = v;
    }
    __syncthreads();

    // ---- LN over c for each j ----
    {
        int half = tid >> 7, j = tid & 127;
        float s = 0.f, sq = 0.f;
#pragma unroll 8
        for (int c2 = 0; c2 < 64; c2++) {
            float v = __half2float(tileH[(half*64 + c2)*TFSH + j]);
            s += v; sq += v*v;
        }
        psum[half*128 + j] = s;
        psq [half*128 + j] = sq;
        __syncthreads();
        float st  = psum[j] + psum[128 + j];
        float sqt = psq [j] + psq [128 + j];
        float m  = st * (1.f/CZ);
        float vv = sqt * (1.f/CZ) - m*m;
        float rs = rsqrtf(vv + 1e-5f);
#pragma unroll 8
        for (int c2 = 0; c2 < 32; c2++) {
            int c = half*64 + c2*2;
            float v0 = __half2float(tileH[c*TFSH + j]);
            float v1 = __half2float(tileH[(c+1)*TFSH + j]);
            float y0 = (v0 - m)*rs*__ldg(cnw + c)     + __ldg(cnb + c);
            float y1 = (v1 - m)*rs*__ldg(cnw + c + 1) + __ldg(cnb + c + 1);
            *(__half2*)(sb + AHI + j*ARS + c*2) = __floats2half2_rn(y0, y1);
        }
    }
    __syncthreads();                       // A complete; tileH dead

    load_wpair(640, 704, tid, sb);         // outp hi/lo (overwrites tileH + BLO)
    __syncthreads();

    int wm = wid & 3, wn = wid >> 2;
    int RM = wm*32, RNl = wn*32;
    int rr = lane >> 2, cp = (lane & 3)*2;

    uint32_t aOff[2], bOff[2], bOffP[2];
#pragma unroll
    for (int fm = 0; fm < 2; fm++)
        aOff[fm] = (uint32_t)((RM + fm*16 + (lane & 15))*ARS + (lane >> 4)*16);
#pragma unroll
    for (int fp = 0; fp < 2; fp++) {
        bOff[fp]  = (uint32_t)((RNl + fp*16 + ((lane >> 4) << 3) + (lane & 7))*BRS
                               + ((lane >> 3) & 1)*16);
        bOffP[fp] = bOff[fp] + 64*BRS;
    }

    float acc[2][4][4];
    for (int nt = 0; nt < 2; nt++) {
        mma_tile2(sbase, aOff, nt ? bOffP : bOff, acc);
#pragma unroll
        for (int fm = 0; fm < 2; fm++) {
            int rowA = RM + fm*16 + rr;
#pragma unroll
            for (int fn = 0; fn < 4; fn++) {
                int c0 = nt*64 + RNl + fn*8 + cp;
                float2 obv = *(const float2*)(ob + c0);
                float2 glA = __half22float2(*(const __half2*)(g_glsig + (size_t)(r0 + rowA)*CZ + c0));
                float2 glB = __half22float2(*(const __half2*)(g_glsig + (size_t)(r0 + rowA + 8)*CZ + c0));
                float2 vA = { (acc[fm][fn][0] + obv.x)*glA.x,
                              (acc[fm][fn][1] + obv.y)*glA.y };
                float2 vB = { (acc[fm][fn][2] + obv.x)*glB.x,
                              (acc[fm][fn][3] + obv.y)*glB.y };
                *(float2*)(out + (size_t)(r0 + rowA)*CZ + c0)     = vA;
                *(float2*)(out + (size_t)(r0 + rowA + 8)*CZ + c0) = vB;
            }
        }
    }
}

// ---------------- launch ----------------------------------------------------
extern "C" void kernel_launch(void* const* d_in, const int* in_sizes, int n_in,
                              void* d_out, int out_size)
{
    const float* act = (const float*)d_in[0];
    const float* mask= (const float*)d_in[1];
    const float* lnw = (const float*)d_in[2];
    const float* lnb = (const float*)d_in[3];
    const float* pw  = (const float*)d_in[4];
    const float* pb  = (const float*)d_in[5];
    const float* gw  = (const float*)d_in[6];
    const float* gb  = (const float*)d_in[7];
    const float* cnw = (const float*)d_in[8];
    const float* cnb = (const float*)d_in[9];
    const float* ow  = (const float*)d_in[10];
    const float* ob  = (const float*)d_in[11];
    const float* glw = (const float*)d_in[12];
    const float* glb = (const float*)d_in[13];
    float* out = (float*)d_out;

    cudaFuncSetAttribute(k1,  cudaFuncAttributeMaxDynamicSharedMemorySize, SMEM13);
    cudaFuncSetAttribute(k3f, cudaFuncAttributeMaxDynamicSharedMemorySize, SMEM_K3);
    cudaFuncSetAttribute(k2,  cudaFuncAttributeMaxDynamicSharedMemorySize, SMEM_K2);

    wsplit<<<384, 256>>>(pw, gw, glw, ow);
    k1<<<NROW/128, 256, SMEM13>>>(act, mask, lnw, lnb, pb, gb, glb);
    k2<<<dim3(16, CZ), 256, SMEM_K2>>>();
    k3f<<<NROW/128, 256, SMEM_K3>>>(out, cnw, cnb, ob);
}

// round 10
// speedup vs baseline: 8.6729x; 1.0612x over previous
#include <cuda_runtime.h>
#include <cuda_fp16.h>
#include <math.h>
#include <stdint.h>

#define NN 512
#define CZ 128
#define NROW (NN*NN)          // 262144 rows

// ---------------- scratch (static device globals) ---------------------------
__device__ __half g_LThi[(size_t)CZ*NROW];  // [c][i*512+k] fp16
__device__ __half g_RThi[(size_t)CZ*NROW];  // [c][j*512+k] fp16
__device__ __half g_glsig[(size_t)NROW*CZ]; // fp16, row-major (r, c)
__device__ __half g_einH [(size_t)CZ*NROW]; // [c][i*512+j] fp16
// weights fp16 (hi only), [n][k]: rows 0-255 gate, 256-511 proj, 512-639 gl, 640-767 outp
__device__ __half g_Whi[768*128];

// ======================= PTX helpers (sm_103-safe) ==========================
__device__ __forceinline__ uint32_t smem_u32(const void* p) {
    uint32_t a;
    asm("{ .reg .u64 t; cvta.to.shared.u64 t, %1; cvt.u32.u64 %0, t; }" : "=r"(a) : "l"(p));
    return a;
}
__device__ __forceinline__ void ldsm4(uint32_t r[4], uint32_t addr) {
    asm volatile("ldmatrix.sync.aligned.m8n8.x4.shared.b16 {%0,%1,%2,%3}, [%4];"
        : "=r"(r[0]), "=r"(r[1]), "=r"(r[2]), "=r"(r[3]) : "r"(addr));
}
__device__ __forceinline__ void mma16816(float c[4], const uint32_t a[4],
                                         uint32_t b0, uint32_t b1) {
    asm volatile("mma.sync.aligned.m16n8k16.row.col.f32.f16.f16.f32 "
        "{%0,%1,%2,%3}, {%4,%5,%6,%7}, {%8,%9}, {%0,%1,%2,%3};"
        : "+f"(c[0]), "+f"(c[1]), "+f"(c[2]), "+f"(c[3])
        : "r"(a[0]), "r"(a[1]), "r"(a[2]), "r"(a[3]), "r"(b0), "r"(b1));
}
__device__ __forceinline__ void cp16(uint32_t dst, const void* src) {
    asm volatile("cp.async.cg.shared.global [%0], [%1], 16;" :: "r"(dst), "l"(src));
}
#define CP_COMMIT() asm volatile("cp.async.commit_group;" ::: "memory")
__device__ __forceinline__ float sigf(float x) { return 1.f/(1.f + expf(-x)); }

// ---------------- K0: weights -> fp16 ---------------------------------------
__global__ void wsplit(const float* __restrict__ pw, const float* __restrict__ gw,
                       const float* __restrict__ glw, const float* __restrict__ ow)
{
    int idx = blockIdx.x*256 + threadIdx.x;   // 384*256 = 98304 = 768*128
    int row = idx >> 7;
    float v;
    if      (row < 256) v = gw [idx];
    else if (row < 512) v = pw [idx - 256*128];
    else if (row < 640) v = glw[idx - 512*128];
    else                v = ow [idx - 640*128];
    g_Whi[idx] = __float2half_rn(v);
}

// =================== mma-based LN+GEMM machinery (k1/k3) ====================
#define ARS    272                 // A row stride  (128 fp16 = 256B + pad)
#define BRS    272
#define AHI    0                   // A: 128*272 = 34816
#define BHI    34816               // B hi: 128 rows -> 34816
#define STK1   69632               // k1 staging 128 x 64 fp16, stride 136
#define SSTR   136
#define SMEM13 87040               // k1: A + Bhi + staging; 2 blocks/SM
// k3f: A + tileH(=BHI region, also weights after) + partials
#define TFSH   136                 // half stride of einH tile (272 B rows)
#define PSUM   69632               // 256 floats
#define PSQ    70656
#define SMEM_K3 71680              // 3 blocks/SM (215 KB)

// LN 128 rows of src -> fp16 A tile in smem (row-major [row][k])
__device__ __forceinline__ void ln_quant(const float* __restrict__ src,
                                         const float* __restrict__ w,
                                         const float* __restrict__ b,
                                         int r0, int tid, char* sb)
{
    int wid = tid >> 5, lane = tid & 31;
    float4 wv = *(const float4*)(w + lane*4);
    float4 bv = *(const float4*)(b + lane*4);
#pragma unroll
    for (int q = 0; q < 16; q++) {
        int row = wid*16 + q;
        float4 x = *(const float4*)(src + (size_t)(r0+row)*CZ + lane*4);
        float s  = x.x+x.y+x.z+x.w;
        float sq = x.x*x.x + x.y*x.y + x.z*x.z + x.w*x.w;
#pragma unroll
        for (int o = 16; o > 0; o >>= 1) {
            s  += __shfl_xor_sync(0xffffffffu, s,  o);
            sq += __shfl_xor_sync(0xffffffffu, sq, o);
        }
        float m  = s * (1.f/CZ);
        float v  = sq * (1.f/CZ) - m*m;
        float rs = rsqrtf(v + 1e-5f);
        float y0 = (x.x-m)*rs*wv.x + bv.x;
        float y1 = (x.y-m)*rs*wv.y + bv.y;
        float y2 = (x.z-m)*rs*wv.z + bv.z;
        float y3 = (x.w-m)*rs*wv.w + bv.w;
        uint32_t off = (uint32_t)(row*ARS + lane*8);
        *(__half2*)(sb + AHI + off)     = __floats2half2_rn(y0, y1);
        *(__half2*)(sb + AHI + off + 4) = __floats2half2_rn(y2, y3);
    }
}

// gate rows 0-63 | proj rows 64-127 -> BHI
__device__ __forceinline__ void load_w_gp(int nt, int tid, char* sb)
{
#pragma unroll
    for (int q = 0; q < 8; q++) {
        int idx = tid + q*256;
        int row = idx >> 4, ch = idx & 15;
        int gr = (row < 64) ? (nt*64 + row) : (256 + nt*64 + row - 64);
        *(uint4*)(sb + BHI + row*BRS + ch*16) = *(const uint4*)(g_Whi + (size_t)gr*128 + ch*8);
    }
}

// 128 contiguous weight rows (base row0) -> BHI (gl: 512, outp: 640)
__device__ __forceinline__ void load_w_128(int row0, int tid, char* sb)
{
#pragma unroll
    for (int q = 0; q < 8; q++) {
        int idx = tid + q*256;
        int row = idx >> 4, ch = idx & 15;
        *(uint4*)(sb + BHI + row*BRS + ch*16) = *(const uint4*)(g_Whi + (size_t)(row0 + row)*128 + ch*8);
    }
}

// M=128 x N=64 x K=128, single-pass (hi only); warp tile 32x32
__device__ __forceinline__ void mma_tile1(uint32_t sbase, const uint32_t aOff[2],
                                          const uint32_t bOff[2], float acc[2][4][4])
{
#pragma unroll
    for (int fm = 0; fm < 2; fm++)
#pragma unroll
        for (int fn = 0; fn < 4; fn++)
#pragma unroll
            for (int e = 0; e < 4; e++) acc[fm][fn][e] = 0.f;
#pragma unroll
    for (int kk = 0; kk < 8; kk++) {
        uint32_t ah[2][4], bh[2][4];
#pragma unroll
        for (int fm = 0; fm < 2; fm++)
            ldsm4(ah[fm], sbase + AHI + aOff[fm] + kk*32);
#pragma unroll
        for (int fp = 0; fp < 2; fp++)
            ldsm4(bh[fp], sbase + BHI + bOff[fp] + kk*32);
#pragma unroll
        for (int fm = 0; fm < 2; fm++)
#pragma unroll
            for (int fn = 0; fn < 4; fn++) {
                int fp = fn >> 1, s = (fn & 1)*2;
                mma16816(acc[fm][fn], ah[fm], bh[fp][s], bh[fp][s+1]);
            }
    }
}

// dual-N variant: both 64-col halves (bOff: B rows 0-63, bOffP: rows 64-127)
// sharing A fragments — one load of ah per kk for 16 mma.
__device__ __forceinline__ void mma_gp(uint32_t sbase, const uint32_t aOff[2],
                                       const uint32_t bOff[2], const uint32_t bOffP[2],
                                       float accG[2][4][4], float accP[2][4][4])
{
#pragma unroll
    for (int fm = 0; fm < 2; fm++)
#pragma unroll
        for (int fn = 0; fn < 4; fn++)
#pragma unroll
            for (int e = 0; e < 4; e++) { accG[fm][fn][e] = 0.f; accP[fm][fn][e] = 0.f; }
#pragma unroll
    for (int kk = 0; kk < 8; kk++) {
        uint32_t ah[2][4], bg[2][4], bp[2][4];
#pragma unroll
        for (int fm = 0; fm < 2; fm++)
            ldsm4(ah[fm], sbase + AHI + aOff[fm] + kk*32);
#pragma unroll
        for (int fp = 0; fp < 2; fp++) {
            ldsm4(bg[fp], sbase + BHI + bOff[fp]  + kk*32);
            ldsm4(bp[fp], sbase + BHI + bOffP[fp] + kk*32);
        }
#pragma unroll
        for (int fm = 0; fm < 2; fm++)
#pragma unroll
            for (int fn = 0; fn < 4; fn++) {
                int fp = fn >> 1, s = (fn & 1)*2;
                mma16816(accG[fm][fn], ah[fm], bg[fp][s], bg[fp][s+1]);
                mma16816(accP[fm][fn], ah[fm], bp[fp][s], bp[fp][s+1]);
            }
    }
}

// ---------------- K1: LN + gate/proj/gl, single-pass, writes L/R fp16 -------
__global__ __launch_bounds__(256, 2) void k1(const float* __restrict__ act,
                                             const float* __restrict__ mask,
                                             const float* __restrict__ lnw,
                                             const float* __restrict__ lnb,
                                             const float* __restrict__ pb,
                                             const float* __restrict__ gb,
                                             const float* __restrict__ glb)
{
    extern __shared__ char sb[];
    uint32_t sbase = smem_u32(sb);
    int tid = threadIdx.x, wid = tid >> 5, lane = tid & 31;
    int r0 = blockIdx.x * 128;
    int wm = wid & 3, wn = wid >> 2;
    int RM = wm*32, RNl = wn*32;
    int rr = lane >> 2, cp = (lane & 3)*2;

    uint32_t aOff[2], bOff[2], bOffP[2];
#pragma unroll
    for (int fm = 0; fm < 2; fm++)
        aOff[fm] = (uint32_t)((RM + fm*16 + (lane & 15))*ARS + (lane >> 4)*16);
#pragma unroll
    for (int fp = 0; fp < 2; fp++) {
        bOff[fp]  = (uint32_t)((RNl + fp*16 + ((lane >> 4) << 3) + (lane & 7))*BRS
                               + ((lane >> 3) & 1)*16);
        bOffP[fp] = bOff[fp] + 64*BRS;
    }

    ln_quant(act, lnw, lnb, r0, tid, sb);

    float accG[2][4][4], accP[2][4][4];

    // ---- 4 tiles of 64 cols: gate+proj in one dual-N mma pass ----
    for (int nt = 0; nt < 4; nt++) {
        load_w_gp(nt, tid, sb);                    // gate hi | proj hi
        __syncthreads();                           // B visible; prior staging reads done
        mma_gp(sbase, aOff, bOff, bOffP, accG, accP);
#pragma unroll
        for (int fm = 0; fm < 2; fm++) {
            int rowA = RM + fm*16 + rr;
            float mkA = mask[r0 + rowA];
            float mkB = mask[r0 + rowA + 8];
#pragma unroll
            for (int fn = 0; fn < 4; fn++) {
                int cl = RNl + fn*8 + cp;
                float2 gbv = *(const float2*)(gb + nt*64 + cl);
                float2 pbv = *(const float2*)(pb + nt*64 + cl);
                float sA0 = sigf(accG[fm][fn][0] + gbv.x);
                float sA1 = sigf(accG[fm][fn][1] + gbv.y);
                float sB0 = sigf(accG[fm][fn][2] + gbv.x);
                float sB1 = sigf(accG[fm][fn][3] + gbv.y);
                float vA0 = mkA*(accP[fm][fn][0] + pbv.x)*sA0;
                float vA1 = mkA*(accP[fm][fn][1] + pbv.y)*sA1;
                float vB0 = mkB*(accP[fm][fn][2] + pbv.x)*sB0;
                float vB1 = mkB*(accP[fm][fn][3] + pbv.y)*sB1;
                uint32_t oA = (uint32_t)(rowA*SSTR + cl*2);
                *(__half2*)(sb + STK1 + oA)          = __floats2half2_rn(vA0, vA1);
                *(__half2*)(sb + STK1 + oA + 8*SSTR) = __floats2half2_rn(vB0, vB1);
            }
        }
        __syncthreads();                           // staging visible
        {
            __half* dst = (nt < 2) ? g_LThi : g_RThi;
            int cl = tid >> 2, rs = (tid & 3)*32;
            uint32_t h[16];
#pragma unroll
            for (int r = 0; r < 16; r++) {
                uint32_t o0 = (uint32_t)((rs + 2*r)*SSTR + cl*2);
                h[r] = (uint32_t)*(const unsigned short*)(sb + STK1 + o0)
                     | ((uint32_t)*(const unsigned short*)(sb + STK1 + o0 + SSTR) << 16);
            }
            size_t go = (size_t)((nt & 1)*64 + cl)*NROW + r0 + rs;
#pragma unroll
            for (int s = 0; s < 4; s++)
                *(uint4*)(dst + go + s*8) = make_uint4(h[s*4], h[s*4+1], h[s*4+2], h[s*4+3]);
        }
    }

    __syncthreads();                               // staging reads finished

    // ---- gl gate: dual-N single pass ----
    load_w_128(512, tid, sb);
    __syncthreads();
    mma_gp(sbase, aOff, bOff, bOffP, accG, accP);
#pragma unroll
    for (int fm = 0; fm < 2; fm++) {
        int rowA = RM + fm*16 + rr;
#pragma unroll
        for (int fn = 0; fn < 4; fn++) {
            int cl = RNl + fn*8 + cp;
            float2 b0 = *(const float2*)(glb + cl);
            float2 b1 = *(const float2*)(glb + 64 + cl);
            *(__half2*)(g_glsig + (size_t)(r0 + rowA)*CZ + cl) =
                __floats2half2_rn(sigf(accG[fm][fn][0] + b0.x), sigf(accG[fm][fn][1] + b0.y));
            *(__half2*)(g_glsig + (size_t)(r0 + rowA + 8)*CZ + cl) =
                __floats2half2_rn(sigf(accG[fm][fn][2] + b0.x), sigf(accG[fm][fn][3] + b0.y));
            *(__half2*)(g_glsig + (size_t)(r0 + rowA)*CZ + 64 + cl) =
                __floats2half2_rn(sigf(accP[fm][fn][0] + b1.x), sigf(accP[fm][fn][1] + b1.y));
            *(__half2*)(g_glsig + (size_t)(r0 + rowA + 8)*CZ + 64 + cl) =
                __floats2half2_rn(sigf(accP[fm][fn][2] + b1.x), sigf(accP[fm][fn][3] + b1.y));
        }
    }
}

// ---------------- K2: fp16 single-pass GEMM, cp.async 3-stage ---------------
#define RSTRIDE 80
#define KCOMP   (128*RSTRIDE)       // 10240
#define ST_A    0
#define ST_BH   KCOMP
#define STAGE   (2*KCOMP)           // 20480
#define SMEM_K2 (3*STAGE)           // 61440 -> 2 blocks/SM

__device__ __forceinline__ void k2_compute(uint32_t sbk, const uint32_t aOff[2],
                                           const uint32_t bOff[4], float acc[2][8][4])
{
#pragma unroll
    for (int kk = 0; kk < 2; kk++) {
        uint32_t ah[2][4], bh[4][4];
#pragma unroll
        for (int fm = 0; fm < 2; fm++)
            ldsm4(ah[fm], sbk + ST_A + aOff[fm] + kk*32);
#pragma unroll
        for (int fp = 0; fp < 4; fp++)
            ldsm4(bh[fp], sbk + ST_BH + bOff[fp] + kk*32);
#pragma unroll
        for (int fm = 0; fm < 2; fm++)
#pragma unroll
            for (int fn = 0; fn < 8; fn++) {
                int fp = fn >> 1, s = (fn & 1)*2;
                mma16816(acc[fm][fn], ah[fm], bh[fp][s], bh[fp][s+1]);
            }
    }
}

__device__ __forceinline__ void k2_copy(uint32_t st, const __half* Ah,
                                        const __half* Bh, int k0, int lr, int lkg)
{
#pragma unroll
    for (int q = 0; q < 2; q++) {
        int r = lr + q*64;
        size_t go = (size_t)r*NN + k0 + lkg*8;
        uint32_t so = (uint32_t)(r*RSTRIDE + lkg*16);
        cp16(st + ST_A  + so, Ah + go);
        cp16(st + ST_BH + so, Bh + go);
    }
}

__global__ __launch_bounds__(256, 2) void k2()
{
    extern __shared__ char sb[];
    uint32_t sbase = smem_u32(sb);
    int tid = threadIdx.x, wid = tid >> 5, lane = tid & 31;
    int c  = blockIdx.y;
    int ti = blockIdx.x >> 2, tj = blockIdx.x & 3;

    const __half* Ah = g_LThi + (size_t)c*NROW + (size_t)ti*128*NN;
    const __half* Bh = g_RThi + (size_t)c*NROW + (size_t)tj*128*NN;
    __half* C = g_einH + (size_t)c*NROW + (size_t)(ti*128)*NN + tj*128;

    int wm = wid & 3, wn = wid >> 2;
    int RM = wm*32, RN = wn*64;

    uint32_t aOff[2], bOff[4];
#pragma unroll
    for (int fm = 0; fm < 2; fm++)
        aOff[fm] = (uint32_t)((RM + fm*16 + (lane & 15))*RSTRIDE + (lane >> 4)*16);
#pragma unroll
    for (int fp = 0; fp < 4; fp++)
        bOff[fp] = (uint32_t)((RN + fp*16 + ((lane >> 4) << 3) + (lane & 7))*RSTRIDE
                              + ((lane >> 3) & 1)*16);

    int lr  = tid >> 2;
    int lkg = tid & 3;

    float acc[2][8][4];
#pragma unroll
    for (int fm = 0; fm < 2; fm++)
#pragma unroll
        for (int fn = 0; fn < 8; fn++)
#pragma unroll
            for (int e = 0; e < 4; e++) acc[fm][fn][e] = 0.f;

    k2_copy(sbase + 0*STAGE, Ah, Bh, 0,  lr, lkg); CP_COMMIT();
    k2_copy(sbase + 1*STAGE, Ah, Bh, 32, lr, lkg); CP_COMMIT();

    for (int t = 0; t < 16; t++) {
        if (t < 15) asm volatile("cp.async.wait_group 1;" ::: "memory");
        else        asm volatile("cp.async.wait_group 0;" ::: "memory");
        __syncthreads();
        if (t + 2 < 16) {
            k2_copy(sbase + ((t+2)%3)*STAGE, Ah, Bh, (t+2)*32, lr, lkg);
            CP_COMMIT();
        }
        k2_compute(sbase + (t%3)*STAGE, aOff, bOff, acc);
    }

    int rr = lane >> 2, cp = (lane & 3)*2;
#pragma unroll
    for (int fm = 0; fm < 2; fm++)
#pragma unroll
        for (int fn = 0; fn < 8; fn++) {
            int row = RM + fm*16 + rr;
            int col = RN + fn*8 + cp;
            *(__half2*)(C + (size_t)row*NN + col) =
                __floats2half2_rn(acc[fm][fn][0], acc[fm][fn][1]);
            *(__half2*)(C + (size_t)(row+8)*NN + col) =
                __floats2half2_rn(acc[fm][fn][2], acc[fm][fn][3]);
        }
}

// ---------------- K3f: einH tile + transpose-LN + outp 1-pass + gl ----------
__global__ __launch_bounds__(256, 3) void k3f(float* __restrict__ out,
                                              const float* __restrict__ cnw,
                                              const float* __restrict__ cnb,
                                              const float* __restrict__ ob)
{
    extern __shared__ char sb[];
    uint32_t sbase = smem_u32(sb);
    __half* tileH = (__half*)(sb + BHI);   // 128 x 136 halves = 34816 B
    float* psum  = (float*)(sb + PSUM);
    float* psq   = (float*)(sb + PSQ);
    int tid = threadIdx.x, wid = tid >> 5, lane = tid & 31;
    int r0 = blockIdx.x * 128;             // = i*512 + jbase

    // ---- load 128(c) x 128(j) fp16 tile of g_einH, coalesced ----
#pragma unroll
    for (int q = 0; q < 8; q++) {
        int idx = tid + q*256;             // uint4 index, 2048 total
        int c = idx >> 4, col8 = idx & 15;
        uint4 v = *(const uint4*)(g_einH + (size_t)c*NROW + r0 + col8*8);
        *(uint4*)((char*)tileH + c*272 + col8*16) = v;
    }
    __syncthreads();

    // ---- LN over c for each j ----
    {
        int half = tid >> 7, j = tid & 127;
        float s = 0.f, sq = 0.f;
#pragma unroll 8
        for (int c2 = 0; c2 < 64; c2++) {
            float v = __half2float(tileH[(half*64 + c2)*TFSH + j]);
            s += v; sq += v*v;
        }
        psum[half*128 + j] = s;
        psq [half*128 + j] = sq;
        __syncthreads();
        float st  = psum[j] + psum[128 + j];
        float sqt = psq [j] + psq [128 + j];
        float m  = st * (1.f/CZ);
        float vv = sqt * (1.f/CZ) - m*m;
        float rs = rsqrtf(vv + 1e-5f);
#pragma unroll 8
        for (int c2 = 0; c2 < 32; c2++) {
            int c = half*64 + c2*2;
            float v0 = __half2float(tileH[c*TFSH + j]);
            float v1 = __half2float(tileH[(c+1)*TFSH + j]);
            float y0 = (v0 - m)*rs*__ldg(cnw + c)     + __ldg(cnb + c);
            float y1 = (v1 - m)*rs*__ldg(cnw + c + 1) + __ldg(cnb + c + 1);
            *(__half2*)(sb + AHI + j*ARS + c*2) = __floats2half2_rn(y0, y1);
        }
    }
    __syncthreads();                       // A complete; tileH dead

    load_w_128(640, tid, sb);              // outp hi (overwrites tileH region)
    __syncthreads();

    int wm = wid & 3, wn = wid >> 2;
    int RM = wm*32, RNl = wn*32;
    int rr = lane >> 2, cp = (lane & 3)*2;

    uint32_t aOff[2], bOff[2], bOffP[2];
#pragma unroll
    for (int fm = 0; fm < 2; fm++)
        aOff[fm] = (uint32_t)((RM + fm*16 + (lane & 15))*ARS + (lane >> 4)*16);
#pragma unroll
    for (int fp = 0; fp < 2; fp++) {
        bOff[fp]  = (uint32_t)((RNl + fp*16 + ((lane >> 4) << 3) + (lane & 7))*BRS
                               + ((lane >> 3) & 1)*16);
        bOffP[fp] = bOff[fp] + 64*BRS;
    }

    float acc[2][4][4];
    for (int nt = 0; nt < 2; nt++) {
        mma_tile1(sbase, aOff, nt ? bOffP : bOff, acc);
#pragma unroll
        for (int fm = 0; fm < 2; fm++) {
            int rowA = RM + fm*16 + rr;
#pragma unroll
            for (int fn = 0; fn < 4; fn++) {
                int c0 = nt*64 + RNl + fn*8 + cp;
                float2 obv = *(const float2*)(ob + c0);
                float2 glA = __half22float2(*(const __half2*)(g_glsig + (size_t)(r0 + rowA)*CZ + c0));
                float2 glB = __half22float2(*(const __half2*)(g_glsig + (size_t)(r0 + rowA + 8)*CZ + c0));
                float2 vA = { (acc[fm][fn][0] + obv.x)*glA.x,
                              (acc[fm][fn][1] + obv.y)*glA.y };
                float2 vB = { (acc[fm][fn][2] + obv.x)*glB.x,
                              (acc[fm][fn][3] + obv.y)*glB.y };
                *(float2*)(out + (size_t)(r0 + rowA)*CZ + c0)     = vA;
                *(float2*)(out + (size_t)(r0 + rowA + 8)*CZ + c0) = vB;
            }
        }
    }
}

// ---------------- launch ----------------------------------------------------
extern "C" void kernel_launch(void* const* d_in, const int* in_sizes, int n_in,
                              void* d_out, int out_size)
{
    const float* act = (const float*)d_in[0];
    const float* mask= (const float*)d_in[1];
    const float* lnw = (const float*)d_in[2];
    const float* lnb = (const float*)d_in[3];
    const float* pw  = (const float*)d_in[4];
    const float* pb  = (const float*)d_in[5];
    const float* gw  = (const float*)d_in[6];
    const float* gb  = (const float*)d_in[7];
    const float* cnw = (const float*)d_in[8];
    const float* cnb = (const float*)d_in[9];
    const float* ow  = (const float*)d_in[10];
    const float* ob  = (const float*)d_in[11];
    const float* glw = (const float*)d_in[12];
    const float* glb = (const float*)d_in[13];
    float* out = (float*)d_out;

    cudaFuncSetAttribute(k1,  cudaFuncAttributeMaxDynamicSharedMemorySize, SMEM13);
    cudaFuncSetAttribute(k3f, cudaFuncAttributeMaxDynamicSharedMemorySize, SMEM_K3);
    cudaFuncSetAttribute(k2,  cudaFuncAttributeMaxDynamicSharedMemorySize, SMEM_K2);

    wsplit<<<384, 256>>>(pw, gw, glw, ow);
    k1<<<NROW/128, 256, SMEM13>>>(act, mask, lnw, lnb, pb, gb, glb);
    k2<<<dim3(16, CZ), 256, SMEM_K2>>>();
    k3f<<<NROW/128, 256, SMEM_K3>>>(out, cnw, cnb, ob);
}

// round 11
// speedup vs baseline: 9.7178x; 1.1205x over previous
#include <cuda_runtime.h>
#include <cuda_fp16.h>
#include <math.h>
#include <stdint.h>

#define NN 512
#define CZ 128
#define NROW (NN*NN)          // 262144 rows

// ---------------- scratch (static device globals) ---------------------------
__device__ __half g_LThi[(size_t)CZ*NROW];  // [c][i*512+k] fp16
__device__ __half g_RThi[(size_t)CZ*NROW];  // [c][j*512+k] fp16
__device__ __half g_glsig[(size_t)NROW*CZ]; // fp16, row-major (r, c)
__device__ __half g_einH [(size_t)CZ*NROW]; // [c][i*512+j] fp16
// weights fp16 (hi only), [n][k]: rows 0-255 gate, 256-511 proj, 512-639 gl, 640-767 outp
__device__ __half g_Whi[768*128];

// ======================= PTX helpers (sm_103-safe) ==========================
__device__ __forceinline__ uint32_t smem_u32(const void* p) {
    uint32_t a;
    asm("{ .reg .u64 t; cvta.to.shared.u64 t, %1; cvt.u32.u64 %0, t; }" : "=r"(a) : "l"(p));
    return a;
}
__device__ __forceinline__ void ldsm4(uint32_t r[4], uint32_t addr) {
    asm volatile("ldmatrix.sync.aligned.m8n8.x4.shared.b16 {%0,%1,%2,%3}, [%4];"
        : "=r"(r[0]), "=r"(r[1]), "=r"(r[2]), "=r"(r[3]) : "r"(addr));
}
__device__ __forceinline__ void mma16816(float c[4], const uint32_t a[4],
                                         uint32_t b0, uint32_t b1) {
    asm volatile("mma.sync.aligned.m16n8k16.row.col.f32.f16.f16.f32 "
        "{%0,%1,%2,%3}, {%4,%5,%6,%7}, {%8,%9}, {%0,%1,%2,%3};"
        : "+f"(c[0]), "+f"(c[1]), "+f"(c[2]), "+f"(c[3])
        : "r"(a[0]), "r"(a[1]), "r"(a[2]), "r"(a[3]), "r"(b0), "r"(b1));
}
__device__ __forceinline__ void cp16(uint32_t dst, const void* src) {
    asm volatile("cp.async.cg.shared.global [%0], [%1], 16;" :: "r"(dst), "l"(src));
}
#define CP_COMMIT() asm volatile("cp.async.commit_group;" ::: "memory")
// fast sigmoid: MUFU.EX2 path + fast division; rel err ~1e-6 << 6.6e-4 budget
__device__ __forceinline__ float sigf(float x) {
    return __fdividef(1.f, 1.f + __expf(-x));
}

// ---------------- K0: weights -> fp16 ---------------------------------------
__global__ void wsplit(const float* __restrict__ pw, const float* __restrict__ gw,
                       const float* __restrict__ glw, const float* __restrict__ ow)
{
    int idx = blockIdx.x*256 + threadIdx.x;   // 384*256 = 98304 = 768*128
    int row = idx >> 7;
    float v;
    if      (row < 256) v = gw [idx];
    else if (row < 512) v = pw [idx - 256*128];
    else if (row < 640) v = glw[idx - 512*128];
    else                v = ow [idx - 640*128];
    g_Whi[idx] = __float2half_rn(v);
}

// =================== mma-based LN+GEMM machinery (k1/k3) ====================
#define ARS    272                 // A row stride  (128 fp16 = 256B + pad)
#define BRS    272
#define AHI    0                   // A: 128*272 = 34816
#define BHI    34816               // B hi: 128 rows -> 34816
#define STK1   69632               // k1 staging 128 x 64 fp16, stride 136
#define SSTR   136
#define SMEM13 87040               // k1: A + Bhi + staging; 2 blocks/SM
// k3f: A + tileH(=BHI region, also weights after) + partials
#define TFSH   136                 // half stride of einH tile (272 B rows)
#define PSUM   69632               // 256 floats
#define PSQ    70656
#define SMEM_K3 71680              // 3 blocks/SM

// LN 128 rows of src -> fp16 A tile in smem (row-major [row][k])
__device__ __forceinline__ void ln_quant(const float* __restrict__ src,
                                         const float* __restrict__ w,
                                         const float* __restrict__ b,
                                         int r0, int tid, char* sb)
{
    int wid = tid >> 5, lane = tid & 31;
    float4 wv = *(const float4*)(w + lane*4);
    float4 bv = *(const float4*)(b + lane*4);
#pragma unroll
    for (int q = 0; q < 16; q++) {
        int row = wid*16 + q;
        float4 x = *(const float4*)(src + (size_t)(r0+row)*CZ + lane*4);
        float s  = x.x+x.y+x.z+x.w;
        float sq = x.x*x.x + x.y*x.y + x.z*x.z + x.w*x.w;
#pragma unroll
        for (int o = 16; o > 0; o >>= 1) {
            s  += __shfl_xor_sync(0xffffffffu, s,  o);
            sq += __shfl_xor_sync(0xffffffffu, sq, o);
        }
        float m  = s * (1.f/CZ);
        float v  = sq * (1.f/CZ) - m*m;
        float rs = rsqrtf(v + 1e-5f);
        float y0 = (x.x-m)*rs*wv.x + bv.x;
        float y1 = (x.y-m)*rs*wv.y + bv.y;
        float y2 = (x.z-m)*rs*wv.z + bv.z;
        float y3 = (x.w-m)*rs*wv.w + bv.w;
        uint32_t off = (uint32_t)(row*ARS + lane*8);
        *(__half2*)(sb + AHI + off)     = __floats2half2_rn(y0, y1);
        *(__half2*)(sb + AHI + off + 4) = __floats2half2_rn(y2, y3);
    }
}

// gate rows 0-63 | proj rows 64-127 -> BHI
__device__ __forceinline__ void load_w_gp(int nt, int tid, char* sb)
{
#pragma unroll
    for (int q = 0; q < 8; q++) {
        int idx = tid + q*256;
        int row = idx >> 4, ch = idx & 15;
        int gr = (row < 64) ? (nt*64 + row) : (256 + nt*64 + row - 64);
        *(uint4*)(sb + BHI + row*BRS + ch*16) = *(const uint4*)(g_Whi + (size_t)gr*128 + ch*8);
    }
}

// 128 contiguous weight rows (base row0) -> BHI (gl: 512, outp: 640)
__device__ __forceinline__ void load_w_128(int row0, int tid, char* sb)
{
#pragma unroll
    for (int q = 0; q < 8; q++) {
        int idx = tid + q*256;
        int row = idx >> 4, ch = idx & 15;
        *(uint4*)(sb + BHI + row*BRS + ch*16) = *(const uint4*)(g_Whi + (size_t)(row0 + row)*128 + ch*8);
    }
}

// M=128 x N=64 x K=128, single-pass (hi only); warp tile 32x32
__device__ __forceinline__ void mma_tile1(uint32_t sbase, const uint32_t aOff[2],
                                          const uint32_t bOff[2], float acc[2][4][4])
{
#pragma unroll
    for (int fm = 0; fm < 2; fm++)
#pragma unroll
        for (int fn = 0; fn < 4; fn++)
#pragma unroll
            for (int e = 0; e < 4; e++) acc[fm][fn][e] = 0.f;
#pragma unroll
    for (int kk = 0; kk < 8; kk++) {
        uint32_t ah[2][4], bh[2][4];
#pragma unroll
        for (int fm = 0; fm < 2; fm++)
            ldsm4(ah[fm], sbase + AHI + aOff[fm] + kk*32);
#pragma unroll
        for (int fp = 0; fp < 2; fp++)
            ldsm4(bh[fp], sbase + BHI + bOff[fp] + kk*32);
#pragma unroll
        for (int fm = 0; fm < 2; fm++)
#pragma unroll
            for (int fn = 0; fn < 4; fn++) {
                int fp = fn >> 1, s = (fn & 1)*2;
                mma16816(acc[fm][fn], ah[fm], bh[fp][s], bh[fp][s+1]);
            }
    }
}

// dual-N variant: both 64-col halves sharing A fragments
__device__ __forceinline__ void mma_gp(uint32_t sbase, const uint32_t aOff[2],
                                       const uint32_t bOff[2], const uint32_t bOffP[2],
                                       float accG[2][4][4], float accP[2][4][4])
{
#pragma unroll
    for (int fm = 0; fm < 2; fm++)
#pragma unroll
        for (int fn = 0; fn < 4; fn++)
#pragma unroll
            for (int e = 0; e < 4; e++) { accG[fm][fn][e] = 0.f; accP[fm][fn][e] = 0.f; }
#pragma unroll
    for (int kk = 0; kk < 8; kk++) {
        uint32_t ah[2][4], bg[2][4], bp[2][4];
#pragma unroll
        for (int fm = 0; fm < 2; fm++)
            ldsm4(ah[fm], sbase + AHI + aOff[fm] + kk*32);
#pragma unroll
        for (int fp = 0; fp < 2; fp++) {
            ldsm4(bg[fp], sbase + BHI + bOff[fp]  + kk*32);
            ldsm4(bp[fp], sbase + BHI + bOffP[fp] + kk*32);
        }
#pragma unroll
        for (int fm = 0; fm < 2; fm++)
#pragma unroll
            for (int fn = 0; fn < 4; fn++) {
                int fp = fn >> 1, s = (fn & 1)*2;
                mma16816(accG[fm][fn], ah[fm], bg[fp][s], bg[fp][s+1]);
                mma16816(accP[fm][fn], ah[fm], bp[fp][s], bp[fp][s+1]);
            }
    }
}

// ---------------- K1: LN + gate/proj/gl, single-pass, writes L/R fp16 -------
__global__ __launch_bounds__(256, 2) void k1(const float* __restrict__ act,
                                             const float* __restrict__ mask,
                                             const float* __restrict__ lnw,
                                             const float* __restrict__ lnb,
                                             const float* __restrict__ pb,
                                             const float* __restrict__ gb,
                                             const float* __restrict__ glb)
{
    extern __shared__ char sb[];
    uint32_t sbase = smem_u32(sb);
    int tid = threadIdx.x, wid = tid >> 5, lane = tid & 31;
    int r0 = blockIdx.x * 128;
    int wm = wid & 3, wn = wid >> 2;
    int RM = wm*32, RNl = wn*32;
    int rr = lane >> 2, cp = (lane & 3)*2;

    uint32_t aOff[2], bOff[2], bOffP[2];
#pragma unroll
    for (int fm = 0; fm < 2; fm++)
        aOff[fm] = (uint32_t)((RM + fm*16 + (lane & 15))*ARS + (lane >> 4)*16);
#pragma unroll
    for (int fp = 0; fp < 2; fp++) {
        bOff[fp]  = (uint32_t)((RNl + fp*16 + ((lane >> 4) << 3) + (lane & 7))*BRS
                               + ((lane >> 3) & 1)*16);
        bOffP[fp] = bOff[fp] + 64*BRS;
    }

    ln_quant(act, lnw, lnb, r0, tid, sb);

    float accG[2][4][4], accP[2][4][4];

    // ---- 4 tiles of 64 cols: gate+proj in one dual-N mma pass ----
    for (int nt = 0; nt < 4; nt++) {
        load_w_gp(nt, tid, sb);                    // gate hi | proj hi
        __syncthreads();                           // B visible; prior staging reads done
        mma_gp(sbase, aOff, bOff, bOffP, accG, accP);
#pragma unroll
        for (int fm = 0; fm < 2; fm++) {
            int rowA = RM + fm*16 + rr;
            float mkA = mask[r0 + rowA];
            float mkB = mask[r0 + rowA + 8];
#pragma unroll
            for (int fn = 0; fn < 4; fn++) {
                int cl = RNl + fn*8 + cp;
                float2 gbv = *(const float2*)(gb + nt*64 + cl);
                float2 pbv = *(const float2*)(pb + nt*64 + cl);
                float sA0 = sigf(accG[fm][fn][0] + gbv.x);
                float sA1 = sigf(accG[fm][fn][1] + gbv.y);
                float sB0 = sigf(accG[fm][fn][2] + gbv.x);
                float sB1 = sigf(accG[fm][fn][3] + gbv.y);
                float vA0 = mkA*(accP[fm][fn][0] + pbv.x)*sA0;
                float vA1 = mkA*(accP[fm][fn][1] + pbv.y)*sA1;
                float vB0 = mkB*(accP[fm][fn][2] + pbv.x)*sB0;
                float vB1 = mkB*(accP[fm][fn][3] + pbv.y)*sB1;
                uint32_t oA = (uint32_t)(rowA*SSTR + cl*2);
                *(__half2*)(sb + STK1 + oA)          = __floats2half2_rn(vA0, vA1);
                *(__half2*)(sb + STK1 + oA + 8*SSTR) = __floats2half2_rn(vB0, vB1);
            }
        }
        __syncthreads();                           // staging visible
        {
            __half* dst = (nt < 2) ? g_LThi : g_RThi;
            int cl = tid >> 2, rs = (tid & 3)*32;
            uint32_t h[16];
#pragma unroll
            for (int r = 0; r < 16; r++) {
                uint32_t o0 = (uint32_t)((rs + 2*r)*SSTR + cl*2);
                h[r] = (uint32_t)*(const unsigned short*)(sb + STK1 + o0)
                     | ((uint32_t)*(const unsigned short*)(sb + STK1 + o0 + SSTR) << 16);
            }
            size_t go = (size_t)((nt & 1)*64 + cl)*NROW + r0 + rs;
#pragma unroll
            for (int s = 0; s < 4; s++)
                *(uint4*)(dst + go + s*8) = make_uint4(h[s*4], h[s*4+1], h[s*4+2], h[s*4+3]);
        }
    }

    __syncthreads();                               // staging reads finished

    // ---- gl gate: dual-N single pass ----
    load_w_128(512, tid, sb);
    __syncthreads();
    mma_gp(sbase, aOff, bOff, bOffP, accG, accP);
#pragma unroll
    for (int fm = 0; fm < 2; fm++) {
        int rowA = RM + fm*16 + rr;
#pragma unroll
        for (int fn = 0; fn < 4; fn++) {
            int cl = RNl + fn*8 + cp;
            float2 b0 = *(const float2*)(glb + cl);
            float2 b1 = *(const float2*)(glb + 64 + cl);
            *(__half2*)(g_glsig + (size_t)(r0 + rowA)*CZ + cl) =
                __floats2half2_rn(sigf(accG[fm][fn][0] + b0.x), sigf(accG[fm][fn][1] + b0.y));
            *(__half2*)(g_glsig + (size_t)(r0 + rowA + 8)*CZ + cl) =
                __floats2half2_rn(sigf(accG[fm][fn][2] + b0.x), sigf(accG[fm][fn][3] + b0.y));
            *(__half2*)(g_glsig + (size_t)(r0 + rowA)*CZ + 64 + cl) =
                __floats2half2_rn(sigf(accP[fm][fn][0] + b1.x), sigf(accP[fm][fn][1] + b1.y));
            *(__half2*)(g_glsig + (size_t)(r0 + rowA + 8)*CZ + 64 + cl) =
                __floats2half2_rn(sigf(accP[fm][fn][2] + b1.x), sigf(accP[fm][fn][3] + b1.y));
        }
    }
}

// ---------------- K2: fp16 single-pass GEMM, K-chunk 64, 3-stage ------------
#define RSTRIDE 144                 // 64 halves = 128B + 16B pad (9 chunks, gcd(9,32)=1)
#define KCOMP   (128*RSTRIDE)       // 18432
#define ST_A    0
#define ST_BH   KCOMP
#define STAGE   (2*KCOMP)           // 36864
#define SMEM_K2 (3*STAGE)           // 110592 <= 116224 -> 2 blocks/SM

__device__ __forceinline__ void k2_compute(uint32_t sbk, const uint32_t aOff[2],
                                           const uint32_t bOff[4], float acc[2][8][4])
{
#pragma unroll
    for (int kk = 0; kk < 4; kk++) {
        uint32_t ah[2][4], bh[4][4];
#pragma unroll
        for (int fm = 0; fm < 2; fm++)
            ldsm4(ah[fm], sbk + ST_A + aOff[fm] + kk*32);
#pragma unroll
        for (int fp = 0; fp < 4; fp++)
            ldsm4(bh[fp], sbk + ST_BH + bOff[fp] + kk*32);
#pragma unroll
        for (int fm = 0; fm < 2; fm++)
#pragma unroll
            for (int fn = 0; fn < 8; fn++) {
                int fp = fn >> 1, s = (fn & 1)*2;
                mma16816(acc[fm][fn], ah[fm], bh[fp][s], bh[fp][s+1]);
            }
    }
}

// copy one 128x64 tile pair (A,B) for k-chunk k0 -> stage st
__device__ __forceinline__ void k2_copy(uint32_t st, const __half* Ah,
                                        const __half* Bh, int k0, int tid)
{
#pragma unroll
    for (int q = 0; q < 4; q++) {
        int idx = tid + q*256;          // 0..1023
        int r = idx >> 3, kg = idx & 7;
        size_t go = (size_t)r*NN + k0 + kg*8;
        uint32_t so = (uint32_t)(r*RSTRIDE + kg*16);
        cp16(st + ST_A  + so, Ah + go);
        cp16(st + ST_BH + so, Bh + go);
    }
}

__global__ __launch_bounds__(256, 2) void k2()
{
    extern __shared__ char sb[];
    uint32_t sbase = smem_u32(sb);
    int tid = threadIdx.x, wid = tid >> 5, lane = tid & 31;
    int c  = blockIdx.y;
    int ti = blockIdx.x >> 2, tj = blockIdx.x & 3;

    const __half* Ah = g_LThi + (size_t)c*NROW + (size_t)ti*128*NN;
    const __half* Bh = g_RThi + (size_t)c*NROW + (size_t)tj*128*NN;
    __half* C = g_einH + (size_t)c*NROW + (size_t)(ti*128)*NN + tj*128;

    int wm = wid & 3, wn = wid >> 2;
    int RM = wm*32, RN = wn*64;

    uint32_t aOff[2], bOff[4];
#pragma unroll
    for (int fm = 0; fm < 2; fm++)
        aOff[fm] = (uint32_t)((RM + fm*16 + (lane & 15))*RSTRIDE + (lane >> 4)*16);
#pragma unroll
    for (int fp = 0; fp < 4; fp++)
        bOff[fp] = (uint32_t)((RN + fp*16 + ((lane >> 4) << 3) + (lane & 7))*RSTRIDE
                              + ((lane >> 3) & 1)*16);

    float acc[2][8][4];
#pragma unroll
    for (int fm = 0; fm < 2; fm++)
#pragma unroll
        for (int fn = 0; fn < 8; fn++)
#pragma unroll
            for (int e = 0; e < 4; e++) acc[fm][fn][e] = 0.f;

    k2_copy(sbase + 0*STAGE, Ah, Bh, 0,  tid); CP_COMMIT();
    k2_copy(sbase + 1*STAGE, Ah, Bh, 64, tid); CP_COMMIT();

    for (int t = 0; t < 8; t++) {
        if (t < 7) asm volatile("cp.async.wait_group 1;" ::: "memory");
        else       asm volatile("cp.async.wait_group 0;" ::: "memory");
        __syncthreads();
        if (t + 2 < 8) {
            k2_copy(sbase + ((t+2)%3)*STAGE, Ah, Bh, (t+2)*64, tid);
            CP_COMMIT();
        }
        k2_compute(sbase + (t%3)*STAGE, aOff, bOff, acc);
    }

    int rr = lane >> 2, cp = (lane & 3)*2;
#pragma unroll
    for (int fm = 0; fm < 2; fm++)
#pragma unroll
        for (int fn = 0; fn < 8; fn++) {
            int row = RM + fm*16 + rr;
            int col = RN + fn*8 + cp;
            *(__half2*)(C + (size_t)row*NN + col) =
                __floats2half2_rn(acc[fm][fn][0], acc[fm][fn][1]);
            *(__half2*)(C + (size_t)(row+8)*NN + col) =
                __floats2half2_rn(acc[fm][fn][2], acc[fm][fn][3]);
        }
}

// ---------------- K3f: einH tile + transpose-LN + outp 1-pass + gl ----------
__global__ __launch_bounds__(256, 3) void k3f(float* __restrict__ out,
                                              const float* __restrict__ cnw,
                                              const float* __restrict__ cnb,
                                              const float* __restrict__ ob)
{
    extern __shared__ char sb[];
    uint32_t sbase = smem_u32(sb);
    __half* tileH = (__half*)(sb + BHI);   // 128 x 136 halves = 34816 B
    float* psum  = (float*)(sb + PSUM);
    float* psq   = (float*)(sb + PSQ);
    int tid = threadIdx.x, wid = tid >> 5, lane = tid & 31;
    int r0 = blockIdx.x * 128;             // = i*512 + jbase

    // ---- load 128(c) x 128(j) fp16 tile of g_einH, coalesced ----
#pragma unroll
    for (int q = 0; q < 8; q++) {
        int idx = tid + q*256;             // uint4 index, 2048 total
        int c = idx >> 4, col8 = idx & 15;
        uint4 v = *(const uint4*)(g_einH + (size_t)c*NROW + r0 + col8*8);
        *(uint4*)((char*)tileH + c*272 + col8*16) = v;
    }
    __syncthreads();

    // ---- LN over c for each j ----
    {
        int half = tid >> 7, j = tid & 127;
        float s = 0.f, sq = 0.f;
#pragma unroll 8
        for (int c2 = 0; c2 < 64; c2++) {
            float v = __half2float(tileH[(half*64 + c2)*TFSH + j]);
            s += v; sq += v*v;
        }
        psum[half*128 + j] = s;
        psq [half*128 + j] = sq;
        __syncthreads();
        float st  = psum[j] + psum[128 + j];
        float sqt = psq [j] + psq [128 + j];
        float m  = st * (1.f/CZ);
        float vv = sqt * (1.f/CZ) - m*m;
        float rs = rsqrtf(vv + 1e-5f);
#pragma unroll 8
        for (int c2 = 0; c2 < 32; c2++) {
            int c = half*64 + c2*2;
            float v0 = __half2float(tileH[c*TFSH + j]);
            float v1 = __half2float(tileH[(c+1)*TFSH + j]);
            float y0 = (v0 - m)*rs*__ldg(cnw + c)     + __ldg(cnb + c);
            float y1 = (v1 - m)*rs*__ldg(cnw + c + 1) + __ldg(cnb + c + 1);
            *(__half2*)(sb + AHI + j*ARS + c*2) = __floats2half2_rn(y0, y1);
        }
    }
    __syncthreads();                       // A complete; tileH dead

    load_w_128(640, tid, sb);              // outp hi (overwrites tileH region)
    __syncthreads();

    int wm = wid & 3, wn = wid >> 2;
    int RM = wm*32, RNl = wn*32;
    int rr = lane >> 2, cp = (lane & 3)*2;

    uint32_t aOff[2], bOff[2], bOffP[2];
#pragma unroll
    for (int fm = 0; fm < 2; fm++)
        aOff[fm] = (uint32_t)((RM + fm*16 + (lane & 15))*ARS + (lane >> 4)*16);
#pragma unroll
    for (int fp = 0; fp < 2; fp++) {
        bOff[fp]  = (uint32_t)((RNl + fp*16 + ((lane >> 4) << 3) + (lane & 7))*BRS
                               + ((lane >> 3) & 1)*16);
        bOffP[fp] = bOff[fp] + 64*BRS;
    }

    float acc[2][4][4];
    for (int nt = 0; nt < 2; nt++) {
        mma_tile1(sbase, aOff, nt ? bOffP : bOff, acc);
#pragma unroll
        for (int fm = 0; fm < 2; fm++) {
            int rowA = RM + fm*16 + rr;
#pragma unroll
            for (int fn = 0; fn < 4; fn++) {
                int c0 = nt*64 + RNl + fn*8 + cp;
                float2 obv = *(const float2*)(ob + c0);
                float2 glA = __half22float2(*(const __half2*)(g_glsig + (size_t)(r0 + rowA)*CZ + c0));
                float2 glB = __half22float2(*(const __half2*)(g_glsig + (size_t)(r0 + rowA + 8)*CZ + c0));
                float2 vA = { (acc[fm][fn][0] + obv.x)*glA.x,
                              (acc[fm][fn][1] + obv.y)*glA.y };
                float2 vB = { (acc[fm][fn][2] + obv.x)*glB.x,
                              (acc[fm][fn][3] + obv.y)*glB.y };
                *(float2*)(out + (size_t)(r0 + rowA)*CZ + c0)     = vA;
                *(float2*)(out + (size_t)(r0 + rowA + 8)*CZ + c0) = vB;
            }
        }
    }
}

// ---------------- launch ----------------------------------------------------
extern "C" void kernel_launch(void* const* d_in, const int* in_sizes, int n_in,
                              void* d_out, int out_size)
{
    const float* act = (const float*)d_in[0];
    const float* mask= (const float*)d_in[1];
    const float* lnw = (const float*)d_in[2];
    const float* lnb = (const float*)d_in[3];
    const float* pw  = (const float*)d_in[4];
    const float* pb  = (const float*)d_in[5];
    const float* gw  = (const float*)d_in[6];
    const float* gb  = (const float*)d_in[7];
    const float* cnw = (const float*)d_in[8];
    const float* cnb = (const float*)d_in[9];
    const float* ow  = (const float*)d_in[10];
    const float* ob  = (const float*)d_in[11];
    const float* glw = (const float*)d_in[12];
    const float* glb = (const float*)d_in[13];
    float* out = (float*)d_out;

    cudaFuncSetAttribute(k1,  cudaFuncAttributeMaxDynamicSharedMemorySize, SMEM13);
    cudaFuncSetAttribute(k3f, cudaFuncAttributeMaxDynamicSharedMemorySize, SMEM_K3);
    cudaFuncSetAttribute(k2,  cudaFuncAttributeMaxDynamicSharedMemorySize, SMEM_K2);

    wsplit<<<384, 256>>>(pw, gw, glw, ow);
    k1<<<NROW/128, 256, SMEM13>>>(act, mask, lnw, lnb, pb, gb, glb);
    k2<<<dim3(16, CZ), 256, SMEM_K2>>>();
    k3f<<<NROW/128, 256, SMEM_K3>>>(out, cnw, cnb, ob);
}

// round 12
// speedup vs baseline: 10.1606x; 1.0456x over previous
#include <cuda_runtime.h>
#include <cuda_fp16.h>
#include <math.h>
#include <stdint.h>

#define NN 512
#define CZ 128
#define NROW (NN*NN)          // 262144 rows

// ---------------- scratch (static device globals) ---------------------------
__device__ __half g_LThi[(size_t)CZ*NROW];  // [c][i*512+k] fp16
__device__ __half g_RThi[(size_t)CZ*NROW];  // [c][j*512+k] fp16
__device__ __half g_glsig[(size_t)NROW*CZ]; // fp16, row-major (r, c)
__device__ __half g_einH [(size_t)CZ*NROW]; // [c][i*512+j] fp16
// weights fp16 (hi only), [n][k]: rows 0-255 gate, 256-511 proj, 512-639 gl, 640-767 outp
__device__ __half g_Whi[768*128];

// ======================= PTX helpers (sm_103-safe) ==========================
__device__ __forceinline__ uint32_t smem_u32(const void* p) {
    uint32_t a;
    asm("{ .reg .u64 t; cvta.to.shared.u64 t, %1; cvt.u32.u64 %0, t; }" : "=r"(a) : "l"(p));
    return a;
}
__device__ __forceinline__ void ldsm4(uint32_t r[4], uint32_t addr) {
    asm volatile("ldmatrix.sync.aligned.m8n8.x4.shared.b16 {%0,%1,%2,%3}, [%4];"
        : "=r"(r[0]), "=r"(r[1]), "=r"(r[2]), "=r"(r[3]) : "r"(addr));
}
__device__ __forceinline__ void mma16816(float c[4], const uint32_t a[4],
                                         uint32_t b0, uint32_t b1) {
    asm volatile("mma.sync.aligned.m16n8k16.row.col.f32.f16.f16.f32 "
        "{%0,%1,%2,%3}, {%4,%5,%6,%7}, {%8,%9}, {%0,%1,%2,%3};"
        : "+f"(c[0]), "+f"(c[1]), "+f"(c[2]), "+f"(c[3])
        : "r"(a[0]), "r"(a[1]), "r"(a[2]), "r"(a[3]), "r"(b0), "r"(b1));
}
__device__ __forceinline__ void cp16(uint32_t dst, const void* src) {
    asm volatile("cp.async.cg.shared.global [%0], [%1], 16;" :: "r"(dst), "l"(src));
}
#define CP_COMMIT() asm volatile("cp.async.commit_group;" ::: "memory")
// fast sigmoid: MUFU.EX2 path + fast division; rel err ~1e-6 << 6.6e-4 budget
__device__ __forceinline__ float sigf(float x) {
    return __fdividef(1.f, 1.f + __expf(-x));
}

// ---------------- K0: weights -> fp16 ---------------------------------------
__global__ void wsplit(const float* __restrict__ pw, const float* __restrict__ gw,
                       const float* __restrict__ glw, const float* __restrict__ ow)
{
    int idx = blockIdx.x*256 + threadIdx.x;   // 384*256 = 98304 = 768*128
    int row = idx >> 7;
    float v;
    if      (row < 256) v = gw [idx];
    else if (row < 512) v = pw [idx - 256*128];
    else if (row < 640) v = glw[idx - 512*128];
    else                v = ow [idx - 640*128];
    g_Whi[idx] = __float2half_rn(v);
}

// =================== mma-based LN+GEMM machinery (k1/k3) ====================
#define ARS    272                 // A row stride  (128 fp16 = 256B + pad)
#define BRS    272
#define AHI    0                   // A: 128*272 = 34816
#define BHI    34816               // B hi: 128 rows -> 34816
#define STK1   69632               // k1 staging, COLUMN-major: [col][row], 64 cols x 272B
#define SCS    272                 // staging col stride (128 rows x 2B + 16 pad)
#define SMEM13 87040               // k1: A + Bhi + staging; 2 blocks/SM
// k3f: A + tileH(=BHI region, also weights after) + partials
#define TFSH   136                 // half stride of einH tile (272 B rows)
#define PSUM   69632               // 4 x 128 floats = 2048 B
#define PSQ    71680               // 4 x 128 floats
#define SMEM_K3 73728              // 3 blocks/SM

// LN 128 rows of src -> fp16 A tile in smem (row-major [row][k])
__device__ __forceinline__ void ln_quant(const float* __restrict__ src,
                                         const float* __restrict__ w,
                                         const float* __restrict__ b,
                                         int r0, int tid, char* sb)
{
    int wid = tid >> 5, lane = tid & 31;
    float4 wv = *(const float4*)(w + lane*4);
    float4 bv = *(const float4*)(b + lane*4);
#pragma unroll
    for (int q = 0; q < 16; q++) {
        int row = wid*16 + q;
        float4 x = *(const float4*)(src + (size_t)(r0+row)*CZ + lane*4);
        float s  = x.x+x.y+x.z+x.w;
        float sq = x.x*x.x + x.y*x.y + x.z*x.z + x.w*x.w;
#pragma unroll
        for (int o = 16; o > 0; o >>= 1) {
            s  += __shfl_xor_sync(0xffffffffu, s,  o);
            sq += __shfl_xor_sync(0xffffffffu, sq, o);
        }
        float m  = s * (1.f/CZ);
        float v  = sq * (1.f/CZ) - m*m;
        float rs = rsqrtf(v + 1e-5f);
        float y0 = (x.x-m)*rs*wv.x + bv.x;
        float y1 = (x.y-m)*rs*wv.y + bv.y;
        float y2 = (x.z-m)*rs*wv.z + bv.z;
        float y3 = (x.w-m)*rs*wv.w + bv.w;
        uint32_t off = (uint32_t)(row*ARS + lane*8);
        *(__half2*)(sb + AHI + off)     = __floats2half2_rn(y0, y1);
        *(__half2*)(sb + AHI + off + 4) = __floats2half2_rn(y2, y3);
    }
}

// gate rows 0-63 | proj rows 64-127 -> BHI
__device__ __forceinline__ void load_w_gp(int nt, int tid, char* sb)
{
#pragma unroll
    for (int q = 0; q < 8; q++) {
        int idx = tid + q*256;
        int row = idx >> 4, ch = idx & 15;
        int gr = (row < 64) ? (nt*64 + row) : (256 + nt*64 + row - 64);
        *(uint4*)(sb + BHI + row*BRS + ch*16) = *(const uint4*)(g_Whi + (size_t)gr*128 + ch*8);
    }
}

// 128 contiguous weight rows (base row0) -> BHI (gl: 512, outp: 640)
__device__ __forceinline__ void load_w_128(int row0, int tid, char* sb)
{
#pragma unroll
    for (int q = 0; q < 8; q++) {
        int idx = tid + q*256;
        int row = idx >> 4, ch = idx & 15;
        *(uint4*)(sb + BHI + row*BRS + ch*16) = *(const uint4*)(g_Whi + (size_t)(row0 + row)*128 + ch*8);
    }
}

// M=128 x N=64 x K=128, single-pass (hi only); warp tile 32x32
__device__ __forceinline__ void mma_tile1(uint32_t sbase, const uint32_t aOff[2],
                                          const uint32_t bOff[2], float acc[2][4][4])
{
#pragma unroll
    for (int fm = 0; fm < 2; fm++)
#pragma unroll
        for (int fn = 0; fn < 4; fn++)
#pragma unroll
            for (int e = 0; e < 4; e++) acc[fm][fn][e] = 0.f;
#pragma unroll
    for (int kk = 0; kk < 8; kk++) {
        uint32_t ah[2][4], bh[2][4];
#pragma unroll
        for (int fm = 0; fm < 2; fm++)
            ldsm4(ah[fm], sbase + AHI + aOff[fm] + kk*32);
#pragma unroll
        for (int fp = 0; fp < 2; fp++)
            ldsm4(bh[fp], sbase + BHI + bOff[fp] + kk*32);
#pragma unroll
        for (int fm = 0; fm < 2; fm++)
#pragma unroll
            for (int fn = 0; fn < 4; fn++) {
                int fp = fn >> 1, s = (fn & 1)*2;
                mma16816(acc[fm][fn], ah[fm], bh[fp][s], bh[fp][s+1]);
            }
    }
}

// dual-N variant: both 64-col halves sharing A fragments
__device__ __forceinline__ void mma_gp(uint32_t sbase, const uint32_t aOff[2],
                                       const uint32_t bOff[2], const uint32_t bOffP[2],
                                       float accG[2][4][4], float accP[2][4][4])
{
#pragma unroll
    for (int fm = 0; fm < 2; fm++)
#pragma unroll
        for (int fn = 0; fn < 4; fn++)
#pragma unroll
            for (int e = 0; e < 4; e++) { accG[fm][fn][e] = 0.f; accP[fm][fn][e] = 0.f; }
#pragma unroll
    for (int kk = 0; kk < 8; kk++) {
        uint32_t ah[2][4], bg[2][4], bp[2][4];
#pragma unroll
        for (int fm = 0; fm < 2; fm++)
            ldsm4(ah[fm], sbase + AHI + aOff[fm] + kk*32);
#pragma unroll
        for (int fp = 0; fp < 2; fp++) {
            ldsm4(bg[fp], sbase + BHI + bOff[fp]  + kk*32);
            ldsm4(bp[fp], sbase + BHI + bOffP[fp] + kk*32);
        }
#pragma unroll
        for (int fm = 0; fm < 2; fm++)
#pragma unroll
            for (int fn = 0; fn < 4; fn++) {
                int fp = fn >> 1, s = (fn & 1)*2;
                mma16816(accG[fm][fn], ah[fm], bg[fp][s], bg[fp][s+1]);
                mma16816(accP[fm][fn], ah[fm], bp[fp][s], bp[fp][s+1]);
            }
    }
}

// ---------------- K1: LN + gate/proj/gl, single-pass, writes L/R fp16 -------
__global__ __launch_bounds__(256, 2) void k1(const float* __restrict__ act,
                                             const float* __restrict__ mask,
                                             const float* __restrict__ lnw,
                                             const float* __restrict__ lnb,
                                             const float* __restrict__ pb,
                                             const float* __restrict__ gb,
                                             const float* __restrict__ glb)
{
    extern __shared__ char sb[];
    uint32_t sbase = smem_u32(sb);
    int tid = threadIdx.x, wid = tid >> 5, lane = tid & 31;
    int r0 = blockIdx.x * 128;
    int wm = wid & 3, wn = wid >> 2;
    int RM = wm*32, RNl = wn*32;
    int rr = lane >> 2, cp = (lane & 3)*2;

    uint32_t aOff[2], bOff[2], bOffP[2];
#pragma unroll
    for (int fm = 0; fm < 2; fm++)
        aOff[fm] = (uint32_t)((RM + fm*16 + (lane & 15))*ARS + (lane >> 4)*16);
#pragma unroll
    for (int fp = 0; fp < 2; fp++) {
        bOff[fp]  = (uint32_t)((RNl + fp*16 + ((lane >> 4) << 3) + (lane & 7))*BRS
                               + ((lane >> 3) & 1)*16);
        bOffP[fp] = bOff[fp] + 64*BRS;
    }

    ln_quant(act, lnw, lnb, r0, tid, sb);

    float accG[2][4][4], accP[2][4][4];

    // ---- 4 tiles of 64 cols: gate+proj in one dual-N mma pass ----
    for (int nt = 0; nt < 4; nt++) {
        load_w_gp(nt, tid, sb);                    // gate hi | proj hi
        __syncthreads();                           // B visible; prior staging reads done
        mma_gp(sbase, aOff, bOff, bOffP, accG, accP);
#pragma unroll
        for (int fm = 0; fm < 2; fm++) {
            int rowA = RM + fm*16 + rr;
            float mkA = mask[r0 + rowA];
            float mkB = mask[r0 + rowA + 8];
#pragma unroll
            for (int fn = 0; fn < 4; fn++) {
                int cl = RNl + fn*8 + cp;
                float2 gbv = *(const float2*)(gb + nt*64 + cl);
                float2 pbv = *(const float2*)(pb + nt*64 + cl);
                float sA0 = sigf(accG[fm][fn][0] + gbv.x);
                float sA1 = sigf(accG[fm][fn][1] + gbv.y);
                float sB0 = sigf(accG[fm][fn][2] + gbv.x);
                float sB1 = sigf(accG[fm][fn][3] + gbv.y);
                float vA0 = mkA*(accP[fm][fn][0] + pbv.x)*sA0;
                float vA1 = mkA*(accP[fm][fn][1] + pbv.y)*sA1;
                float vB0 = mkB*(accP[fm][fn][2] + pbv.x)*sB0;
                float vB1 = mkB*(accP[fm][fn][3] + pbv.y)*sB1;
                // column-major staging: [col][row], scalar stores
                uint32_t o = (uint32_t)(STK1 + cl*SCS + rowA*2);
                *(__half*)(sb + o)             = __float2half_rn(vA0);   // (rowA,   cl)
                *(__half*)(sb + o + SCS)       = __float2half_rn(vA1);   // (rowA,   cl+1)
                *(__half*)(sb + o + 16)        = __float2half_rn(vB0);   // (rowA+8, cl)
                *(__half*)(sb + o + SCS + 16)  = __float2half_rn(vB1);   // (rowA+8, cl+1)
            }
        }
        __syncthreads();                           // staging visible
        {
            // read column cl rows rs..rs+31 as 4x uint4 (already in global order)
            __half* dst = (nt < 2) ? g_LThi : g_RThi;
            int cl = tid >> 2, rs = (tid & 3)*32;
            size_t go = (size_t)((nt & 1)*64 + cl)*NROW + r0 + rs;
            uint32_t so = (uint32_t)(STK1 + cl*SCS + rs*2);
#pragma unroll
            for (int s = 0; s < 4; s++)
                *(uint4*)(dst + go + s*8) = *(const uint4*)(sb + so + s*16);
        }
    }

    __syncthreads();                               // staging reads finished

    // ---- gl gate: dual-N single pass ----
    load_w_128(512, tid, sb);
    __syncthreads();
    mma_gp(sbase, aOff, bOff, bOffP, accG, accP);
#pragma unroll
    for (int fm = 0; fm < 2; fm++) {
        int rowA = RM + fm*16 + rr;
#pragma unroll
        for (int fn = 0; fn < 4; fn++) {
            int cl = RNl + fn*8 + cp;
            float2 b0 = *(const float2*)(glb + cl);
            float2 b1 = *(const float2*)(glb + 64 + cl);
            *(__half2*)(g_glsig + (size_t)(r0 + rowA)*CZ + cl) =
                __floats2half2_rn(sigf(accG[fm][fn][0] + b0.x), sigf(accG[fm][fn][1] + b0.y));
            *(__half2*)(g_glsig + (size_t)(r0 + rowA + 8)*CZ + cl) =
                __floats2half2_rn(sigf(accG[fm][fn][2] + b0.x), sigf(accG[fm][fn][3] + b0.y));
            *(__half2*)(g_glsig + (size_t)(r0 + rowA)*CZ + 64 + cl) =
                __floats2half2_rn(sigf(accP[fm][fn][0] + b1.x), sigf(accP[fm][fn][1] + b1.y));
            *(__half2*)(g_glsig + (size_t)(r0 + rowA + 8)*CZ + 64 + cl) =
                __floats2half2_rn(sigf(accP[fm][fn][2] + b1.x), sigf(accP[fm][fn][3] + b1.y));
        }
    }
}

// ---------------- K2: fp16 single-pass GEMM, K-chunk 64, 3-stage ------------
#define RSTRIDE 144
#define KCOMP   (128*RSTRIDE)       // 18432
#define ST_A    0
#define ST_BH   KCOMP
#define STAGE   (2*KCOMP)           // 36864
#define SMEM_K2 (3*STAGE)           // 110592 -> 2 blocks/SM

__device__ __forceinline__ void k2_compute(uint32_t sbk, const uint32_t aOff[2],
                                           const uint32_t bOff[4], float acc[2][8][4])
{
#pragma unroll
    for (int kk = 0; kk < 4; kk++) {
        uint32_t ah[2][4], bh[4][4];
#pragma unroll
        for (int fm = 0; fm < 2; fm++)
            ldsm4(ah[fm], sbk + ST_A + aOff[fm] + kk*32);
#pragma unroll
        for (int fp = 0; fp < 4; fp++)
            ldsm4(bh[fp], sbk + ST_BH + bOff[fp] + kk*32);
#pragma unroll
        for (int fm = 0; fm < 2; fm++)
#pragma unroll
            for (int fn = 0; fn < 8; fn++) {
                int fp = fn >> 1, s = (fn & 1)*2;
                mma16816(acc[fm][fn], ah[fm], bh[fp][s], bh[fp][s+1]);
            }
    }
}

__device__ __forceinline__ void k2_copy(uint32_t st, const __half* Ah,
                                        const __half* Bh, int k0, int tid)
{
#pragma unroll
    for (int q = 0; q < 4; q++) {
        int idx = tid + q*256;          // 0..1023
        int r = idx >> 3, kg = idx & 7;
        size_t go = (size_t)r*NN + k0 + kg*8;
        uint32_t so = (uint32_t)(r*RSTRIDE + kg*16);
        cp16(st + ST_A  + so, Ah + go);
        cp16(st + ST_BH + so, Bh + go);
    }
}

__global__ __launch_bounds__(256, 2) void k2()
{
    extern __shared__ char sb[];
    uint32_t sbase = smem_u32(sb);
    int tid = threadIdx.x, wid = tid >> 5, lane = tid & 31;
    int c  = blockIdx.y;
    int ti = blockIdx.x >> 2, tj = blockIdx.x & 3;

    const __half* Ah = g_LThi + (size_t)c*NROW + (size_t)ti*128*NN;
    const __half* Bh = g_RThi + (size_t)c*NROW + (size_t)tj*128*NN;
    __half* C = g_einH + (size_t)c*NROW + (size_t)(ti*128)*NN + tj*128;

    int wm = wid & 3, wn = wid >> 2;
    int RM = wm*32, RN = wn*64;

    uint32_t aOff[2], bOff[4];
#pragma unroll
    for (int fm = 0; fm < 2; fm++)
        aOff[fm] = (uint32_t)((RM + fm*16 + (lane & 15))*RSTRIDE + (lane >> 4)*16);
#pragma unroll
    for (int fp = 0; fp < 4; fp++)
        bOff[fp] = (uint32_t)((RN + fp*16 + ((lane >> 4) << 3) + (lane & 7))*RSTRIDE
                              + ((lane >> 3) & 1)*16);

    float acc[2][8][4];
#pragma unroll
    for (int fm = 0; fm < 2; fm++)
#pragma unroll
        for (int fn = 0; fn < 8; fn++)
#pragma unroll
            for (int e = 0; e < 4; e++) acc[fm][fn][e] = 0.f;

    k2_copy(sbase + 0*STAGE, Ah, Bh, 0,  tid); CP_COMMIT();
    k2_copy(sbase + 1*STAGE, Ah, Bh, 64, tid); CP_COMMIT();

    for (int t = 0; t < 8; t++) {
        if (t < 7) asm volatile("cp.async.wait_group 1;" ::: "memory");
        else       asm volatile("cp.async.wait_group 0;" ::: "memory");
        __syncthreads();
        if (t + 2 < 8) {
            k2_copy(sbase + ((t+2)%3)*STAGE, Ah, Bh, (t+2)*64, tid);
            CP_COMMIT();
        }
        k2_compute(sbase + (t%3)*STAGE, aOff, bOff, acc);
    }

    int rr = lane >> 2, cp = (lane & 3)*2;
#pragma unroll
    for (int fm = 0; fm < 2; fm++)
#pragma unroll
        for (int fn = 0; fn < 8; fn++) {
            int row = RM + fm*16 + rr;
            int col = RN + fn*8 + cp;
            *(__half2*)(C + (size_t)row*NN + col) =
                __floats2half2_rn(acc[fm][fn][0], acc[fm][fn][1]);
            *(__half2*)(C + (size_t)(row+8)*NN + col) =
                __floats2half2_rn(acc[fm][fn][2], acc[fm][fn][3]);
        }
}

// ---------------- K3f: einH tile + vectorized transpose-LN + outp + gl ------
__global__ __launch_bounds__(256, 3) void k3f(float* __restrict__ out,
                                              const float* __restrict__ cnw,
                                              const float* __restrict__ cnb,
                                              const float* __restrict__ ob)
{
    extern __shared__ char sb[];
    uint32_t sbase = smem_u32(sb);
    __half* tileH = (__half*)(sb + BHI);   // 128 x 136 halves = 34816 B
    float* psum  = (float*)(sb + PSUM);    // [4][128]
    float* psq   = (float*)(sb + PSQ);     // [4][128]
    int tid = threadIdx.x, wid = tid >> 5, lane = tid & 31;
    int r0 = blockIdx.x * 128;             // = i*512 + jbase

    // ---- load 128(c) x 128(j) fp16 tile of g_einH, coalesced ----
#pragma unroll
    for (int q = 0; q < 8; q++) {
        int idx = tid + q*256;             // uint4 index, 2048 total
        int c = idx >> 4, col8 = idx & 15;
        uint4 v = *(const uint4*)(g_einH + (size_t)c*NROW + r0 + col8*8);
        *(uint4*)((char*)tileH + c*272 + col8*16) = v;
    }
    __syncthreads();

    // ---- LN over c, vectorized: thread = (j-pair jp, c-quarter cq) ----
    {
        int jp = tid & 63, cq = tid >> 6;  // jp: 0..63, cq: 0..3
        int j0 = jp*2;
        float2 s = {0.f, 0.f}, q2 = {0.f, 0.f};
#pragma unroll 8
        for (int c2 = 0; c2 < 32; c2++) {
            int c = cq*32 + c2;
            float2 v = __half22float2(*(const __half2*)(tileH + c*TFSH + j0));
            s.x += v.x; s.y += v.y;
            q2.x += v.x*v.x; q2.y += v.y*v.y;
        }
        *(float2*)(psum + cq*128 + j0) = s;
        *(float2*)(psq  + cq*128 + j0) = q2;
        __syncthreads();
        float2 st = {0.f, 0.f}, sqt = {0.f, 0.f};
#pragma unroll
        for (int c4 = 0; c4 < 4; c4++) {
            float2 a = *(const float2*)(psum + c4*128 + j0);
            float2 b = *(const float2*)(psq  + c4*128 + j0);
            st.x += a.x; st.y += a.y; sqt.x += b.x; sqt.y += b.y;
        }
        float m0 = st.x * (1.f/CZ), m1 = st.y * (1.f/CZ);
        float rs0 = rsqrtf(sqt.x*(1.f/CZ) - m0*m0 + 1e-5f);
        float rs1 = rsqrtf(sqt.y*(1.f/CZ) - m1*m1 + 1e-5f);
        // normalize this thread's c-quarter for both j's; c staggered by jp
        // so the scalar A stores hit distinct banks (9*jp mod 32 distinct).
#pragma unroll 8
        for (int c2 = 0; c2 < 32; c2++) {
            int c = cq*32 + ((c2 + jp) & 31);
            float2 v = __half22float2(*(const __half2*)(tileH + c*TFSH + j0));
            float wc = __ldg(cnw + c), bc = __ldg(cnb + c);
            float y0 = (v.x - m0)*rs0*wc + bc;
            float y1 = (v.y - m1)*rs1*wc + bc;
            *(__half*)(sb + AHI + j0*ARS + c*2)       = __float2half_rn(y0);
            *(__half*)(sb + AHI + (j0+1)*ARS + c*2)   = __float2half_rn(y1);
        }
    }
    __syncthreads();                       // A complete; tileH dead

    load_w_128(640, tid, sb);              // outp hi (overwrites tileH region)
    __syncthreads();

    int wm = wid & 3, wn = wid >> 2;
    int RM = wm*32, RNl = wn*32;
    int rr = lane >> 2, cp = (lane & 3)*2;

    uint32_t aOff[2], bOff[2], bOffP[2];
#pragma unroll
    for (int fm = 0; fm < 2; fm++)
        aOff[fm] = (uint32_t)((RM + fm*16 + (lane & 15))*ARS + (lane >> 4)*16);
#pragma unroll
    for (int fp = 0; fp < 2; fp++) {
        bOff[fp]  = (uint32_t)((RNl + fp*16 + ((lane >> 4) << 3) + (lane & 7))*BRS
                               + ((lane >> 3) & 1)*16);
        bOffP[fp] = bOff[fp] + 64*BRS;
    }

    float acc[2][4][4];
    for (int nt = 0; nt < 2; nt++) {
        mma_tile1(sbase, aOff, nt ? bOffP : bOff, acc);
#pragma unroll
        for (int fm = 0; fm < 2; fm++) {
            int rowA = RM + fm*16 + rr;
#pragma unroll
            for (int fn = 0; fn < 4; fn++) {
                int c0 = nt*64 + RNl + fn*8 + cp;
                float2 obv = *(const float2*)(ob + c0);
                float2 glA = __half22float2(*(const __half2*)(g_glsig + (size_t)(r0 + rowA)*CZ + c0));
                float2 glB = __half22float2(*(const __half2*)(g_glsig + (size_t)(r0 + rowA + 8)*CZ + c0));
                float2 vA = { (acc[fm][fn][0] + obv.x)*glA.x,
                              (acc[fm][fn][1] + obv.y)*glA.y };
                float2 vB = { (acc[fm][fn][2] + obv.x)*glB.x,
                              (acc[fm][fn][3] + obv.y)*glB.y };
                *(float2*)(out + (size_t)(r0 + rowA)*CZ + c0)     = vA;
                *(float2*)(out + (size_t)(r0 + rowA + 8)*CZ + c0) = vB;
            }
        }
    }
}

// ---------------- launch ----------------------------------------------------
extern "C" void kernel_launch(void* const* d_in, const int* in_sizes, int n_in,
                              void* d_out, int out_size)
{
    const float* act = (const float*)d_in[0];
    const float* mask= (const float*)d_in[1];
    const float* lnw = (const float*)d_in[2];
    const float* lnb = (const float*)d_in[3];
    const float* pw  = (const float*)d_in[4];
    const float* pb  = (const float*)d_in[5];
    const float* gw  = (const float*)d_in[6];
    const float* gb  = (const float*)d_in[7];
    const float* cnw = (const float*)d_in[8];
    const float* cnb = (const float*)d_in[9];
    const float* ow  = (const float*)d_in[10];
    const float* ob  = (const float*)d_in[11];
    const float* glw = (const float*)d_in[12];
    const float* glb = (const float*)d_in[13];
    float* out = (float*)d_out;

    cudaFuncSetAttribute(k1,  cudaFuncAttributeMaxDynamicSharedMemorySize, SMEM13);
    cudaFuncSetAttribute(k3f, cudaFuncAttributeMaxDynamicSharedMemorySize, SMEM_K3);
    cudaFuncSetAttribute(k2,  cudaFuncAttributeMaxDynamicSharedMemorySize, SMEM_K2);

    wsplit<<<384, 256>>>(pw, gw, glw, ow);
    k1<<<NROW/128, 256, SMEM13>>>(act, mask, lnw, lnb, pb, gb, glb);
    k2<<<dim3(16, CZ), 256, SMEM_K2>>>();
    k3f<<<NROW/128, 256, SMEM_K3>>>(out, cnw, cnb, ob);
}